// round 1
// baseline (speedup 1.0000x reference)
#include <cuda_runtime.h>
#include <math.h>

// Problem constants
#define B_    2
#define T_    2048
#define C_    2048
#define H_    16
#define HD_   128
#define LORA_ 512
#define RD_   64
#define ND_   64
#define BT_   (B_ * T_)   // 4096

// ---------------------------------------------------------------------------
// Scratch (static __device__ globals — allocation-free per harness rules)
// ---------------------------------------------------------------------------
__device__ float g_q[(size_t)BT_ * (H_ * HD_)];      // [4096, 2048] q (rope applied in place)
__device__ float g_ckv[(size_t)BT_ * (LORA_ + RD_)]; // [4096, 576]
__device__ float g_kv[(size_t)BT_ * (H_ * ND_)];     // [4096, 1024]  layout [bt][h*64+d]
__device__ float g_krope[(size_t)BT_ * RD_];         // [4096, 64]   roped, shared across heads
__device__ float g_y[(size_t)BT_ * (H_ * ND_)];      // [4096, 1024] attention out (nope half only)

// ---------------------------------------------------------------------------
// SGEMM: C[M,N] = A[M,K] @ B[K,N]  (row-major, fp32)
// BM=BN=128, BK=8, 256 threads, 8x8 register tile per thread.
// MAPB: gather B rows via k -> (k/64)*128 + k%64   (skips the zero rope rows of y @ Wo)
// NCHK: bounds-check N (only needed for N=576)
// Requires: M % 128 == 0, K % 8 == 0, lda/ldb/ldc % 4 == 0.
// ---------------------------------------------------------------------------
template <bool MAPB, bool NCHK>
__global__ __launch_bounds__(256)
void gemm_kernel(const float* __restrict__ A, const float* __restrict__ Bm,
                 float* __restrict__ Cm, int M, int N, int K,
                 int lda, int ldb, int ldc)
{
    __shared__ float AsT[8][128];
    __shared__ float Bs[8][128];

    const int tid = threadIdx.x;
    const int tx = tid & 15, ty = tid >> 4;
    const int m0 = blockIdx.y * 128;
    const int n0 = blockIdx.x * 128;

    const int ar = tid >> 1;          // 0..127
    const int ac = (tid & 1) * 4;     // 0 or 4
    const int br = tid >> 5;          // 0..7
    const int bc = (tid & 31) * 4;    // 0..124

    float acc[8][8];
    #pragma unroll
    for (int i = 0; i < 8; i++)
        #pragma unroll
        for (int j = 0; j < 8; j++) acc[i][j] = 0.f;

    for (int k0 = 0; k0 < K; k0 += 8) {
        // --- load A tile (128x8) transposed into smem ---
        float4 av = *(const float4*)&A[(size_t)(m0 + ar) * lda + k0 + ac];
        AsT[ac + 0][ar] = av.x;
        AsT[ac + 1][ar] = av.y;
        AsT[ac + 2][ar] = av.z;
        AsT[ac + 3][ar] = av.w;

        // --- load B tile (8x128) ---
        const int kr = k0 + br;
        const int brow = MAPB ? (((kr >> 6) << 7) + (kr & 63)) : kr;
        float4 bv;
        if (!NCHK || (n0 + bc + 3) < N) {
            bv = *(const float4*)&Bm[(size_t)brow * ldb + n0 + bc];
        } else {
            bv.x = (n0 + bc + 0 < N) ? Bm[(size_t)brow * ldb + n0 + bc + 0] : 0.f;
            bv.y = (n0 + bc + 1 < N) ? Bm[(size_t)brow * ldb + n0 + bc + 1] : 0.f;
            bv.z = (n0 + bc + 2 < N) ? Bm[(size_t)brow * ldb + n0 + bc + 2] : 0.f;
            bv.w = 0.f;
        }
        *(float4*)&Bs[br][bc] = bv;

        __syncthreads();

        #pragma unroll
        for (int kk = 0; kk < 8; kk++) {
            float a[8], b[8];
            *(float4*)&a[0] = *(const float4*)&AsT[kk][ty * 8];
            *(float4*)&a[4] = *(const float4*)&AsT[kk][ty * 8 + 4];
            *(float4*)&b[0] = *(const float4*)&Bs[kk][tx * 8];
            *(float4*)&b[4] = *(const float4*)&Bs[kk][tx * 8 + 4];
            #pragma unroll
            for (int i = 0; i < 8; i++)
                #pragma unroll
                for (int j = 0; j < 8; j++)
                    acc[i][j] += a[i] * b[j];
        }
        __syncthreads();
    }

    // --- store ---
    #pragma unroll
    for (int i = 0; i < 8; i++) {
        const size_t row = (size_t)(m0 + ty * 8 + i);
        if (!NCHK) {
            float4 v0 = make_float4(acc[i][0], acc[i][1], acc[i][2], acc[i][3]);
            float4 v1 = make_float4(acc[i][4], acc[i][5], acc[i][6], acc[i][7]);
            *(float4*)&Cm[row * ldc + n0 + tx * 8]     = v0;
            *(float4*)&Cm[row * ldc + n0 + tx * 8 + 4] = v1;
        } else {
            #pragma unroll
            for (int j = 0; j < 8; j++) {
                const int col = n0 + tx * 8 + j;
                if (col < N) Cm[row * ldc + col] = acc[i][j];
            }
        }
    }
}

// ---------------------------------------------------------------------------
// RoPE: in-place on q rope half (per head), and ckv rope cols -> g_krope
// freq_i = theta^(-i/32), ang = t * freq (fp32 multiply, matching reference)
// ---------------------------------------------------------------------------
__global__ void rope_kernel(float* __restrict__ q, const float* __restrict__ ckv,
                            float* __restrict__ krope)
{
    const int idx = blockIdx.x * blockDim.x + threadIdx.x;
    const int QP = BT_ * H_ * (RD_ / 2);       // 2,097,152
    const int TOT = QP + BT_ * (RD_ / 2);      // + 131,072
    if (idx >= TOT) return;

    if (idx < QP) {
        const int i  = idx & 31;
        const int h  = (idx >> 5) & 15;
        const int bt = idx >> 9;
        const int t  = bt & (T_ - 1);
        const float freq = (float)pow(100000.0, -(double)i / 32.0);
        const float ang = (float)t * freq;
        float s, c;
        sincosf(ang, &s, &c);
        float* p = q + (size_t)bt * 2048 + h * 128 + 64 + 2 * i;
        const float x0 = p[0], x1 = p[1];
        p[0] = x0 * c - x1 * s;
        p[1] = x0 * s + x1 * c;
    } else {
        const int k  = idx - QP;
        const int i  = k & 31;
        const int bt = k >> 5;
        const int t  = bt & (T_ - 1);
        const float freq = (float)pow(100000.0, -(double)i / 32.0);
        const float ang = (float)t * freq;
        float s, c;
        sincosf(ang, &s, &c);
        const float* p = ckv + (size_t)bt * 576 + 512 + 2 * i;
        const float x0 = p[0], x1 = p[1];
        krope[(size_t)bt * 64 + 2 * i]     = x0 * c - x1 * s;
        krope[(size_t)bt * 64 + 2 * i + 1] = x0 * s + x1 * c;
    }
}

// ---------------------------------------------------------------------------
// Flash attention (causal), 64x64 tiles, D=128 for QK^T, D=64 for P@V
// (V rope half is identically zero -> only compute the kv half of the output).
// smem operands stored transposed so inner loops are 2x LDS.128 + 16 FFMA.
// grid: (T/64, H, B), 256 threads.
// ---------------------------------------------------------------------------
#define PAD 68
#define ATTN_SMEM ((2 * 128 * PAD + 2 * 64 * PAD) * 4)   // 104448 B

__global__ __launch_bounds__(256)
void attn_kernel(const float* __restrict__ q, const float* __restrict__ kv,
                 const float* __restrict__ krope, float* __restrict__ y)
{
    extern __shared__ float sm[];
    float* QsT = sm;                         // [128 d][64 r] (pad 68)
    float* KsT = sm + 128 * PAD;             // [128 d][64 s]
    float* Vs  = sm + 2 * 128 * PAD;         // [64 s][64 c]
    float* PsT = sm + 2 * 128 * PAD + 64 * PAD; // [64 s][64 r]

    const int tid = threadIdx.x;
    const int tx = tid & 15, ty = tid >> 4;
    const int qt = blockIdx.x, h = blockIdx.y, b = blockIdx.z;
    const int m0 = qt * 64;
    const int bq0 = b * T_ + m0;
    const float scale = 0.08838834764831845f;  // 1/sqrt(128)

    // load Q tile (scaled), transposed
    for (int idx = tid; idx < 64 * 128; idx += 256) {
        const int r = idx >> 7, d = idx & 127;
        QsT[d * PAD + r] = q[(size_t)(bq0 + r) * 2048 + h * 128 + d] * scale;
    }

    const int r0 = ty * 4, c0 = tx * 4;
    float m_i[4] = {-1e30f, -1e30f, -1e30f, -1e30f};
    float l_i[4] = {0.f, 0.f, 0.f, 0.f};
    float o[4][4];
    #pragma unroll
    for (int i = 0; i < 4; i++)
        #pragma unroll
        for (int j = 0; j < 4; j++) o[i][j] = 0.f;

    for (int kt = 0; kt <= qt; kt++) {
        const int ks0 = b * T_ + kt * 64;
        __syncthreads();   // prior-iteration consumers of KsT/Vs/PsT done
        for (int idx = tid; idx < 64 * 128; idx += 256) {
            const int s = idx >> 7, d = idx & 127;
            const float v = (d < 64)
                ? kv[(size_t)(ks0 + s) * 1024 + h * 64 + d]
                : krope[(size_t)(ks0 + s) * 64 + (d - 64)];
            KsT[d * PAD + s] = v;
        }
        for (int idx = tid; idx < 64 * 64; idx += 256) {
            const int s = idx >> 6, c = idx & 63;
            Vs[s * PAD + c] = kv[(size_t)(ks0 + s) * 1024 + h * 64 + c];
        }
        __syncthreads();

        // S = Q K^T (scaled)
        float acc[4][4];
        #pragma unroll
        for (int i = 0; i < 4; i++)
            #pragma unroll
            for (int j = 0; j < 4; j++) acc[i][j] = 0.f;

        #pragma unroll 8
        for (int d = 0; d < 128; d++) {
            const float4 av = *(const float4*)&QsT[d * PAD + r0];
            const float4 bv = *(const float4*)&KsT[d * PAD + c0];
            const float a[4] = {av.x, av.y, av.z, av.w};
            const float bb[4] = {bv.x, bv.y, bv.z, bv.w};
            #pragma unroll
            for (int i = 0; i < 4; i++)
                #pragma unroll
                for (int j = 0; j < 4; j++)
                    acc[i][j] += a[i] * bb[j];
        }

        if (kt == qt) {
            #pragma unroll
            for (int i = 0; i < 4; i++)
                #pragma unroll
                for (int j = 0; j < 4; j++)
                    if (c0 + j > r0 + i) acc[i][j] = -1e30f;
        }

        // online softmax (row groups = 16 lanes of a half-warp)
        #pragma unroll
        for (int i = 0; i < 4; i++) {
            float tmax = fmaxf(fmaxf(acc[i][0], acc[i][1]), fmaxf(acc[i][2], acc[i][3]));
            #pragma unroll
            for (int mm = 1; mm < 16; mm <<= 1)
                tmax = fmaxf(tmax, __shfl_xor_sync(0xffffffffu, tmax, mm));
            const float newm = fmaxf(m_i[i], tmax);
            const float factor = __expf(m_i[i] - newm);
            float tsum = 0.f;
            #pragma unroll
            for (int j = 0; j < 4; j++) {
                const float p = __expf(acc[i][j] - newm);
                acc[i][j] = p;
                tsum += p;
            }
            #pragma unroll
            for (int mm = 1; mm < 16; mm <<= 1)
                tsum += __shfl_xor_sync(0xffffffffu, tsum, mm);
            l_i[i] = l_i[i] * factor + tsum;
            m_i[i] = newm;
            #pragma unroll
            for (int j = 0; j < 4; j++) o[i][j] *= factor;
        }

        // publish P (transposed)
        #pragma unroll
        for (int i = 0; i < 4; i++)
            #pragma unroll
            for (int j = 0; j < 4; j++)
                PsT[(c0 + j) * PAD + r0 + i] = acc[i][j];
        __syncthreads();

        // O += P @ V  (64-wide)
        #pragma unroll 8
        for (int s = 0; s < 64; s++) {
            const float4 av = *(const float4*)&PsT[s * PAD + r0];
            const float4 bv = *(const float4*)&Vs[s * PAD + c0];
            const float a[4] = {av.x, av.y, av.z, av.w};
            const float bb[4] = {bv.x, bv.y, bv.z, bv.w};
            #pragma unroll
            for (int i = 0; i < 4; i++)
                #pragma unroll
                for (int j = 0; j < 4; j++)
                    o[i][j] += a[i] * bb[j];
        }
    }

    #pragma unroll
    for (int i = 0; i < 4; i++) {
        const float inv = 1.f / l_i[i];
        #pragma unroll
        for (int j = 0; j < 4; j++)
            y[(size_t)(bq0 + r0 + i) * 1024 + h * 64 + c0 + j] = o[i][j] * inv;
    }
}

// ---------------------------------------------------------------------------
// Launch
// ---------------------------------------------------------------------------
extern "C" void kernel_launch(void* const* d_in, const int* in_sizes, int n_in,
                              void* d_out, int out_size)
{
    const float* x    = (const float*)d_in[0];
    const float* Wq   = (const float*)d_in[1];
    const float* Wkva = (const float*)d_in[2];
    const float* Wkvb = (const float*)d_in[3];
    const float* Wo   = (const float*)d_in[4];
    float* out = (float*)d_out;

    float *q, *ckv, *kvb, *kr, *y;
    cudaGetSymbolAddress((void**)&q,   g_q);
    cudaGetSymbolAddress((void**)&ckv, g_ckv);
    cudaGetSymbolAddress((void**)&kvb, g_kv);
    cudaGetSymbolAddress((void**)&kr,  g_krope);
    cudaGetSymbolAddress((void**)&y,   g_y);

    cudaFuncSetAttribute(attn_kernel,
                         cudaFuncAttributeMaxDynamicSharedMemorySize, ATTN_SMEM);

    // q = x @ Wq                      [4096,2048] x [2048,2048]
    gemm_kernel<false, false><<<dim3(16, 32), 256>>>(x, Wq, q,
        4096, 2048, 2048, 2048, 2048, 2048);
    // ckv = x @ Wkva                  [4096,2048] x [2048,576]
    gemm_kernel<false, true><<<dim3(5, 32), 256>>>(x, Wkva, ckv,
        4096, 576, 2048, 2048, 576, 576);
    // rope (q in place; ckv rope -> krope)
    rope_kernel<<<8704, 256>>>(q, ckv, kr);
    // kv = ckv[:, :512] @ Wkvb        [4096,512] x [512,1024]
    gemm_kernel<false, false><<<dim3(8, 32), 256>>>(ckv, Wkvb, kvb,
        4096, 1024, 512, 576, 1024, 1024);
    // flash attention
    attn_kernel<<<dim3(32, 16, 2), 256, ATTN_SMEM>>>(q, kvb, kr, y);
    // out = y @ Wo[nope rows]         [4096,1024] x gather(Wo)[1024,2048]
    gemm_kernel<true, false><<<dim3(16, 32), 256>>>(y, Wo, out,
        4096, 2048, 1024, 1024, 2048, 2048);
}

// round 3
// speedup vs baseline: 1.5899x; 1.5899x over previous
#include <cuda_runtime.h>
#include <cuda_bf16.h>
#include <math.h>
#include <stdint.h>

// Problem constants
#define B_    2
#define T_    2048
#define C_    2048
#define H_    16
#define HD_   128
#define LORA_ 512
#define RD_   64
#define ND_   64
#define BT_   (B_ * T_)   // 4096

// ---------------------------------------------------------------------------
// Scratch (static __device__ globals — allocation-free per harness rules)
// ---------------------------------------------------------------------------
__device__ float g_q[(size_t)BT_ * 2048];
__device__ float g_ckv[(size_t)BT_ * 576];
__device__ float g_kv[(size_t)BT_ * 1024];
__device__ float g_krope[(size_t)BT_ * 64];
__device__ float g_y[(size_t)BT_ * 1024];

// bf16 split-precision copies (x ≈ hi + lo, ~16 effective mantissa bits)
__device__ __nv_bfloat16 g_xhi[(size_t)BT_ * 2048],  g_xlo[(size_t)BT_ * 2048];
__device__ __nv_bfloat16 g_ckvhi[(size_t)BT_ * 512], g_ckvlo[(size_t)BT_ * 512];
__device__ __nv_bfloat16 g_yhi[(size_t)BT_ * 1024],  g_ylo[(size_t)BT_ * 1024];
// weights transposed to [N, K] (K contiguous) for the B operand
__device__ __nv_bfloat16 g_wqt_hi[(size_t)2048 * 2048], g_wqt_lo[(size_t)2048 * 2048];
__device__ __nv_bfloat16 g_wkvat_hi[(size_t)640 * 2048], g_wkvat_lo[(size_t)640 * 2048];
__device__ __nv_bfloat16 g_wkvbt_hi[(size_t)1024 * 512], g_wkvbt_lo[(size_t)1024 * 512];
__device__ __nv_bfloat16 g_wot_hi[(size_t)2048 * 1024], g_wot_lo[(size_t)2048 * 1024];

// ---------------------------------------------------------------------------
// fp32 -> bf16 hi/lo split (no transpose)
// ---------------------------------------------------------------------------
__global__ void split_kernel(const float* __restrict__ in, int ld_in,
                             __nv_bfloat16* __restrict__ hi,
                             __nv_bfloat16* __restrict__ lo,
                             int rows, int width)
{
    const int idx = blockIdx.x * blockDim.x + threadIdx.x;
    const int w4 = width >> 2;
    if (idx >= rows * w4) return;
    const int r = idx / w4, c4 = idx - r * w4;
    const float4 v = *(const float4*)&in[(size_t)r * ld_in + c4 * 4];
    float f[4] = {v.x, v.y, v.z, v.w};
    ushort4 hv, lv;
    unsigned short* hp = &hv.x;
    unsigned short* lp = &lv.x;
    #pragma unroll
    for (int i = 0; i < 4; i++) {
        __nv_bfloat16 h = __float2bfloat16(f[i]);
        __nv_bfloat16 l = __float2bfloat16(f[i] - __bfloat162float(h));
        hp[i] = __bfloat16_as_ushort(h);
        lp[i] = __bfloat16_as_ushort(l);
    }
    *(ushort4*)&hi[(size_t)r * width + c4 * 4] = hv;
    *(ushort4*)&lo[(size_t)r * width + c4 * 4] = lv;
}

// ---------------------------------------------------------------------------
// fp32 W[k][n] -> bf16 hi/lo out[n][k] (transpose + optional gather + pad)
// ---------------------------------------------------------------------------
template <bool GATHER>
__global__ void splitT_kernel(const float* __restrict__ W, int ldw, int nIn,
                              __nv_bfloat16* __restrict__ hi,
                              __nv_bfloat16* __restrict__ lo, int kDim)
{
    __shared__ float tile[32][33];
    const int k0 = blockIdx.x * 32, n0 = blockIdx.y * 32;
    #pragma unroll
    for (int i = threadIdx.y; i < 32; i += 8) {
        const int k = k0 + i;
        const int row = GATHER ? (((k >> 6) << 7) + (k & 63)) : k;
        const int n = n0 + threadIdx.x;
        tile[i][threadIdx.x] = (n < nIn) ? W[(size_t)row * ldw + n] : 0.f;
    }
    __syncthreads();
    #pragma unroll
    for (int i = threadIdx.y; i < 32; i += 8) {
        const int n = n0 + i, k = k0 + threadIdx.x;
        const float v = tile[threadIdx.x][i];
        const __nv_bfloat16 h = __float2bfloat16(v);
        hi[(size_t)n * kDim + k] = h;
        lo[(size_t)n * kDim + k] = __float2bfloat16(v - __bfloat162float(h));
    }
}

// ---------------------------------------------------------------------------
// HMMA (mma.sync) bf16 split-precision GEMM:
//   C[M,N] = (Ahi+Alo)[M,K] @ (Bhi+Blo)[N,K]^T   (drop lo*lo)
// CTA tile 128x128, 8 warps of 64x32, BK=32, register-staged double buffer.
// Smem rows padded to 40 bf16 (80B) -> conflict-free ldmatrix.
// ---------------------------------------------------------------------------
#define ROWB   80                       // bytes per smem row
#define TILEB  (128 * ROWB)             // 10240 B per tile
#define BUFB   (4 * TILEB)              // Ahi,Alo,Bhi,Blo
#define GEMM_SMEM (2 * BUFB)            // 81920 B

__device__ __forceinline__ uint32_t smem_u32(const void* p) {
    uint32_t a;
    asm("{ .reg .u64 t; cvta.to.shared.u64 t, %1; cvt.u32.u64 %0, t; }"
        : "=r"(a) : "l"(p));
    return a;
}
__device__ __forceinline__ void ldsm4(uint32_t r[4], uint32_t addr) {
    asm volatile("ldmatrix.sync.aligned.m8n8.x4.shared.b16 {%0,%1,%2,%3}, [%4];"
                 : "=r"(r[0]), "=r"(r[1]), "=r"(r[2]), "=r"(r[3]) : "r"(addr));
}
__device__ __forceinline__ void mma_bf16(float c[4], const uint32_t a[4],
                                         const uint32_t b[2]) {
    asm volatile(
        "mma.sync.aligned.m16n8k16.row.col.f32.bf16.bf16.f32 "
        "{%0,%1,%2,%3}, {%4,%5,%6,%7}, {%8,%9}, {%0,%1,%2,%3};"
        : "+f"(c[0]), "+f"(c[1]), "+f"(c[2]), "+f"(c[3])
        : "r"(a[0]), "r"(a[1]), "r"(a[2]), "r"(a[3]), "r"(b[0]), "r"(b[1]));
}

template <bool NCHK>
__global__ __launch_bounds__(256)
void hmma_gemm(const __nv_bfloat16* __restrict__ Ahi, const __nv_bfloat16* __restrict__ Alo,
               const __nv_bfloat16* __restrict__ Bhi, const __nv_bfloat16* __restrict__ Blo,
               float* __restrict__ C, int N, int K, int lda, int ldb, int ldc)
{
    extern __shared__ char smc[];
    const uint32_t sb = smem_u32(smc);
    const int tid = threadIdx.x;
    const int lane = tid & 31, warp = tid >> 5;
    const int wm = warp >> 2, wn = warp & 3;      // warp tile: 64 x 32
    const int m0 = blockIdx.y * 128, n0 = blockIdx.x * 128;

    // staged global->reg loads: 2 float4 per tile per thread
    const int r_ld = tid >> 2;              // 0..63 (+64 on second)
    const int s_ld = (tid & 3) * 8;         // k element offset within chunk
    const size_t aoff0 = (size_t)(m0 + r_ld) * lda + s_ld;
    const size_t aoff1 = (size_t)(m0 + r_ld + 64) * lda + s_ld;
    const size_t boff0 = (size_t)(n0 + r_ld) * ldb + s_ld;
    const size_t boff1 = (size_t)(n0 + r_ld + 64) * ldb + s_ld;
    const uint32_t st0 = r_ld * ROWB + (tid & 3) * 16;
    const uint32_t st1 = (r_ld + 64) * ROWB + (tid & 3) * 16;

    float4 vAh[2], vAl[2], vBh[2], vBl[2];
    #define LOADREGS(k0_)                                                     \
        vAh[0] = *(const float4*)(Ahi + aoff0 + (k0_));                       \
        vAh[1] = *(const float4*)(Ahi + aoff1 + (k0_));                       \
        vAl[0] = *(const float4*)(Alo + aoff0 + (k0_));                       \
        vAl[1] = *(const float4*)(Alo + aoff1 + (k0_));                       \
        vBh[0] = *(const float4*)(Bhi + boff0 + (k0_));                       \
        vBh[1] = *(const float4*)(Bhi + boff1 + (k0_));                       \
        vBl[0] = *(const float4*)(Blo + boff0 + (k0_));                       \
        vBl[1] = *(const float4*)(Blo + boff1 + (k0_));

    float c[4][4][4];
    #pragma unroll
    for (int i = 0; i < 4; i++)
        #pragma unroll
        for (int j = 0; j < 4; j++)
            #pragma unroll
            for (int l = 0; l < 4; l++) c[i][j][l] = 0.f;

    // ldmatrix source addresses (byte offsets within a buffer)
    const uint32_t a_row = wm * 64 + (lane & 15);
    const uint32_t a_koff = (lane >> 4) * 16;                 // bytes
    const uint32_t b_row = wn * 32 + ((lane >> 4) << 3) + (lane & 7);
    const uint32_t b_koff = ((lane >> 3) & 1) * 16;           // bytes

    const int niter = K >> 5;
    LOADREGS(0);

    for (int it = 0; it < niter; it++) {
        const uint32_t buf = sb + (uint32_t)(it & 1) * BUFB;
        // store staged regs to smem
        *(float4*)(smc + (buf - sb) + 0 * TILEB + st0) = vAh[0];
        *(float4*)(smc + (buf - sb) + 0 * TILEB + st1) = vAh[1];
        *(float4*)(smc + (buf - sb) + 1 * TILEB + st0) = vAl[0];
        *(float4*)(smc + (buf - sb) + 1 * TILEB + st1) = vAl[1];
        *(float4*)(smc + (buf - sb) + 2 * TILEB + st0) = vBh[0];
        *(float4*)(smc + (buf - sb) + 2 * TILEB + st1) = vBh[1];
        *(float4*)(smc + (buf - sb) + 3 * TILEB + st0) = vBl[0];
        *(float4*)(smc + (buf - sb) + 3 * TILEB + st1) = vBl[1];
        __syncthreads();

        if (it + 1 < niter) { LOADREGS((it + 1) << 5); }

        #pragma unroll
        for (int ks = 0; ks < 2; ks++) {
            const uint32_t kb = ks * 32;   // bytes (16 bf16)
            uint32_t afh[4][4], afl[4][4], bfh[4][2], bfl[4][2];
            #pragma unroll
            for (int mt = 0; mt < 4; mt++) {
                const uint32_t ad = buf + (a_row + mt * 16) * ROWB + kb + a_koff;
                ldsm4(afh[mt], ad + 0 * TILEB);
                ldsm4(afl[mt], ad + 1 * TILEB);
            }
            #pragma unroll
            for (int np = 0; np < 2; np++) {
                const uint32_t bd = buf + (b_row + np * 16) * ROWB + kb + b_koff;
                uint32_t t[4];
                ldsm4(t, bd + 2 * TILEB);
                bfh[np * 2][0] = t[0]; bfh[np * 2][1] = t[1];
                bfh[np * 2 + 1][0] = t[2]; bfh[np * 2 + 1][1] = t[3];
                ldsm4(t, bd + 3 * TILEB);
                bfl[np * 2][0] = t[0]; bfl[np * 2][1] = t[1];
                bfl[np * 2 + 1][0] = t[2]; bfl[np * 2 + 1][1] = t[3];
            }
            #pragma unroll
            for (int mt = 0; mt < 4; mt++)
                #pragma unroll
                for (int nt = 0; nt < 4; nt++) {
                    mma_bf16(c[mt][nt], afh[mt], bfh[nt]);
                    mma_bf16(c[mt][nt], afh[mt], bfl[nt]);
                    mma_bf16(c[mt][nt], afl[mt], bfh[nt]);
                }
        }
        __syncthreads();
    }
    #undef LOADREGS

    // epilogue
    #pragma unroll
    for (int mt = 0; mt < 4; mt++) {
        const int row = m0 + wm * 64 + mt * 16 + (lane >> 2);
        #pragma unroll
        for (int nt = 0; nt < 4; nt++) {
            const int col = n0 + wn * 32 + nt * 8 + (lane & 3) * 2;
            if (!NCHK || col < N) {
                *(float2*)&C[(size_t)row * ldc + col] =
                    make_float2(c[mt][nt][0], c[mt][nt][1]);
                *(float2*)&C[(size_t)(row + 8) * ldc + col] =
                    make_float2(c[mt][nt][2], c[mt][nt][3]);
            }
        }
    }
}

// ---------------------------------------------------------------------------
// RoPE
// ---------------------------------------------------------------------------
__global__ void rope_kernel(float* __restrict__ q, const float* __restrict__ ckv,
                            float* __restrict__ krope)
{
    const int idx = blockIdx.x * blockDim.x + threadIdx.x;
    const int QP = BT_ * H_ * (RD_ / 2);
    const int TOT = QP + BT_ * (RD_ / 2);
    if (idx >= TOT) return;

    if (idx < QP) {
        const int i  = idx & 31;
        const int h  = (idx >> 5) & 15;
        const int bt = idx >> 9;
        const int t  = bt & (T_ - 1);
        const float freq = (float)pow(100000.0, -(double)i / 32.0);
        float s, c;
        sincosf((float)t * freq, &s, &c);
        float* p = q + (size_t)bt * 2048 + h * 128 + 64 + 2 * i;
        const float x0 = p[0], x1 = p[1];
        p[0] = x0 * c - x1 * s;
        p[1] = x0 * s + x1 * c;
    } else {
        const int k  = idx - QP;
        const int i  = k & 31;
        const int bt = k >> 5;
        const int t  = bt & (T_ - 1);
        const float freq = (float)pow(100000.0, -(double)i / 32.0);
        float s, c;
        sincosf((float)t * freq, &s, &c);
        const float* p = ckv + (size_t)bt * 576 + 512 + 2 * i;
        const float x0 = p[0], x1 = p[1];
        krope[(size_t)bt * 64 + 2 * i]     = x0 * c - x1 * s;
        krope[(size_t)bt * 64 + 2 * i + 1] = x0 * s + x1 * c;
    }
}

// ---------------------------------------------------------------------------
// Flash attention (causal), fp32 SIMT (unchanged from R1)
// ---------------------------------------------------------------------------
#define PAD 68
#define ATTN_SMEM ((2 * 128 * PAD + 2 * 64 * PAD) * 4)

__global__ __launch_bounds__(256)
void attn_kernel(const float* __restrict__ q, const float* __restrict__ kv,
                 const float* __restrict__ krope, float* __restrict__ y)
{
    extern __shared__ float smf[];
    float* QsT = smf;
    float* KsT = smf + 128 * PAD;
    float* Vs  = smf + 2 * 128 * PAD;
    float* PsT = smf + 2 * 128 * PAD + 64 * PAD;

    const int tid = threadIdx.x;
    const int tx = tid & 15, ty = tid >> 4;
    const int qt = blockIdx.x, h = blockIdx.y, b = blockIdx.z;
    const int bq0 = b * T_ + qt * 64;
    const float scale = 0.08838834764831845f;

    for (int idx = tid; idx < 64 * 128; idx += 256) {
        const int r = idx >> 7, d = idx & 127;
        QsT[d * PAD + r] = q[(size_t)(bq0 + r) * 2048 + h * 128 + d] * scale;
    }

    const int r0 = ty * 4, c0 = tx * 4;
    float m_i[4] = {-1e30f, -1e30f, -1e30f, -1e30f};
    float l_i[4] = {0.f, 0.f, 0.f, 0.f};
    float o[4][4];
    #pragma unroll
    for (int i = 0; i < 4; i++)
        #pragma unroll
        for (int j = 0; j < 4; j++) o[i][j] = 0.f;

    for (int kt = 0; kt <= qt; kt++) {
        const int ks0 = b * T_ + kt * 64;
        __syncthreads();
        for (int idx = tid; idx < 64 * 128; idx += 256) {
            const int s = idx >> 7, d = idx & 127;
            const float v = (d < 64)
                ? kv[(size_t)(ks0 + s) * 1024 + h * 64 + d]
                : krope[(size_t)(ks0 + s) * 64 + (d - 64)];
            KsT[d * PAD + s] = v;
        }
        for (int idx = tid; idx < 64 * 64; idx += 256) {
            const int s = idx >> 6, c = idx & 63;
            Vs[s * PAD + c] = kv[(size_t)(ks0 + s) * 1024 + h * 64 + c];
        }
        __syncthreads();

        float acc[4][4];
        #pragma unroll
        for (int i = 0; i < 4; i++)
            #pragma unroll
            for (int j = 0; j < 4; j++) acc[i][j] = 0.f;

        #pragma unroll 8
        for (int d = 0; d < 128; d++) {
            const float4 av = *(const float4*)&QsT[d * PAD + r0];
            const float4 bv = *(const float4*)&KsT[d * PAD + c0];
            const float a[4] = {av.x, av.y, av.z, av.w};
            const float bb[4] = {bv.x, bv.y, bv.z, bv.w};
            #pragma unroll
            for (int i = 0; i < 4; i++)
                #pragma unroll
                for (int j = 0; j < 4; j++)
                    acc[i][j] += a[i] * bb[j];
        }

        if (kt == qt) {
            #pragma unroll
            for (int i = 0; i < 4; i++)
                #pragma unroll
                for (int j = 0; j < 4; j++)
                    if (c0 + j > r0 + i) acc[i][j] = -1e30f;
        }

        #pragma unroll
        for (int i = 0; i < 4; i++) {
            float tmax = fmaxf(fmaxf(acc[i][0], acc[i][1]), fmaxf(acc[i][2], acc[i][3]));
            #pragma unroll
            for (int mm = 1; mm < 16; mm <<= 1)
                tmax = fmaxf(tmax, __shfl_xor_sync(0xffffffffu, tmax, mm));
            const float newm = fmaxf(m_i[i], tmax);
            const float factor = __expf(m_i[i] - newm);
            float tsum = 0.f;
            #pragma unroll
            for (int j = 0; j < 4; j++) {
                const float p = __expf(acc[i][j] - newm);
                acc[i][j] = p;
                tsum += p;
            }
            #pragma unroll
            for (int mm = 1; mm < 16; mm <<= 1)
                tsum += __shfl_xor_sync(0xffffffffu, tsum, mm);
            l_i[i] = l_i[i] * factor + tsum;
            m_i[i] = newm;
            #pragma unroll
            for (int j = 0; j < 4; j++) o[i][j] *= factor;
        }

        #pragma unroll
        for (int i = 0; i < 4; i++)
            #pragma unroll
            for (int j = 0; j < 4; j++)
                PsT[(c0 + j) * PAD + r0 + i] = acc[i][j];
        __syncthreads();

        #pragma unroll 8
        for (int s = 0; s < 64; s++) {
            const float4 av = *(const float4*)&PsT[s * PAD + r0];
            const float4 bv = *(const float4*)&Vs[s * PAD + c0];
            const float a[4] = {av.x, av.y, av.z, av.w};
            const float bb[4] = {bv.x, bv.y, bv.z, bv.w};
            #pragma unroll
            for (int i = 0; i < 4; i++)
                #pragma unroll
                for (int j = 0; j < 4; j++)
                    o[i][j] += a[i] * bb[j];
        }
    }

    #pragma unroll
    for (int i = 0; i < 4; i++) {
        const float inv = 1.f / l_i[i];
        #pragma unroll
        for (int j = 0; j < 4; j++)
            y[(size_t)(bq0 + r0 + i) * 1024 + h * 64 + c0 + j] = o[i][j] * inv;
    }
}

// ---------------------------------------------------------------------------
// Launch
// ---------------------------------------------------------------------------
extern "C" void kernel_launch(void* const* d_in, const int* in_sizes, int n_in,
                              void* d_out, int out_size)
{
    const float* x    = (const float*)d_in[0];
    const float* Wq   = (const float*)d_in[1];
    const float* Wkva = (const float*)d_in[2];
    const float* Wkvb = (const float*)d_in[3];
    const float* Wo   = (const float*)d_in[4];
    float* out = (float*)d_out;

    float *q, *ckv, *kvb, *kr, *y;
    cudaGetSymbolAddress((void**)&q,   g_q);
    cudaGetSymbolAddress((void**)&ckv, g_ckv);
    cudaGetSymbolAddress((void**)&kvb, g_kv);
    cudaGetSymbolAddress((void**)&kr,  g_krope);
    cudaGetSymbolAddress((void**)&y,   g_y);
    __nv_bfloat16 *xhi, *xlo, *ckvhi, *ckvlo, *yhi, *ylo;
    __nv_bfloat16 *wqh, *wql, *wah, *wal, *wbh, *wbl, *woh, *wol;
    cudaGetSymbolAddress((void**)&xhi, g_xhi);     cudaGetSymbolAddress((void**)&xlo, g_xlo);
    cudaGetSymbolAddress((void**)&ckvhi, g_ckvhi); cudaGetSymbolAddress((void**)&ckvlo, g_ckvlo);
    cudaGetSymbolAddress((void**)&yhi, g_yhi);     cudaGetSymbolAddress((void**)&ylo, g_ylo);
    cudaGetSymbolAddress((void**)&wqh, g_wqt_hi);  cudaGetSymbolAddress((void**)&wql, g_wqt_lo);
    cudaGetSymbolAddress((void**)&wah, g_wkvat_hi); cudaGetSymbolAddress((void**)&wal, g_wkvat_lo);
    cudaGetSymbolAddress((void**)&wbh, g_wkvbt_hi); cudaGetSymbolAddress((void**)&wbl, g_wkvbt_lo);
    cudaGetSymbolAddress((void**)&woh, g_wot_hi);  cudaGetSymbolAddress((void**)&wol, g_wot_lo);

    cudaFuncSetAttribute(attn_kernel,
                         cudaFuncAttributeMaxDynamicSharedMemorySize, ATTN_SMEM);
    cudaFuncSetAttribute(hmma_gemm<false>,
                         cudaFuncAttributeMaxDynamicSharedMemorySize, GEMM_SMEM);
    cudaFuncSetAttribute(hmma_gemm<true>,
                         cudaFuncAttributeMaxDynamicSharedMemorySize, GEMM_SMEM);

    const dim3 tb(32, 8);
    // weight conversions
    splitT_kernel<false><<<dim3(64, 64), tb>>>(Wq,   2048, 2048, wqh, wql, 2048);
    splitT_kernel<false><<<dim3(64, 20), tb>>>(Wkva,  576,  576, wah, wal, 2048);
    splitT_kernel<false><<<dim3(16, 32), tb>>>(Wkvb, 1024, 1024, wbh, wbl,  512);
    splitT_kernel<true ><<<dim3(32, 64), tb>>>(Wo,   2048, 2048, woh, wol, 1024);
    // x split
    split_kernel<<<8192, 256>>>(x, 2048, xhi, xlo, 4096, 2048);

    // q = x @ Wq
    hmma_gemm<false><<<dim3(16, 32), 256, GEMM_SMEM>>>(xhi, xlo, wqh, wql, q,
        2048, 2048, 2048, 2048, 2048);
    // ckv = x @ Wkva  (N=576, B padded to 640)
    hmma_gemm<true><<<dim3(5, 32), 256, GEMM_SMEM>>>(xhi, xlo, wah, wal, ckv,
        576, 2048, 2048, 2048, 576);
    // rope
    rope_kernel<<<8704, 256>>>(q, ckv, kr);
    // latent split + kv = latent @ Wkvb
    split_kernel<<<2048, 256>>>(ckv, 576, ckvhi, ckvlo, 4096, 512);
    hmma_gemm<false><<<dim3(8, 32), 256, GEMM_SMEM>>>(ckvhi, ckvlo, wbh, wbl, kvb,
        1024, 512, 512, 512, 1024);
    // attention
    attn_kernel<<<dim3(32, 16, 2), 256, ATTN_SMEM>>>(q, kvb, kr, y);
    // y split + out = y @ gather(Wo)
    split_kernel<<<4096, 256>>>(y, 1024, yhi, ylo, 4096, 1024);
    hmma_gemm<false><<<dim3(16, 32), 256, GEMM_SMEM>>>(yhi, ylo, woh, wol, out,
        2048, 1024, 1024, 1024, 2048);
}

// round 4
// speedup vs baseline: 2.3924x; 1.5048x over previous
#include <cuda_runtime.h>
#include <cuda_bf16.h>
#include <math.h>
#include <stdint.h>

// Problem constants
#define B_    2
#define T_    2048
#define C_    2048
#define H_    16
#define HD_   128
#define LORA_ 512
#define RD_   64
#define ND_   64
#define BT_   (B_ * T_)   // 4096

// ---------------------------------------------------------------------------
// Scratch
// ---------------------------------------------------------------------------
__device__ float g_q[(size_t)BT_ * 2048];
__device__ float g_ckv[(size_t)BT_ * 576];
__device__ float g_kv[(size_t)BT_ * 1024];
__device__ float g_krope[(size_t)BT_ * 64];

__device__ __nv_bfloat16 g_xhi[(size_t)BT_ * 2048],  g_xlo[(size_t)BT_ * 2048];
__device__ __nv_bfloat16 g_ckvhi[(size_t)BT_ * 512], g_ckvlo[(size_t)BT_ * 512];
__device__ __nv_bfloat16 g_yhi[(size_t)BT_ * 1024],  g_ylo[(size_t)BT_ * 1024];
__device__ __nv_bfloat16 g_qhi[(size_t)BT_ * 2048],  g_qlo[(size_t)BT_ * 2048];
__device__ __nv_bfloat16 g_kvhi[(size_t)BT_ * 1024], g_kvlo[(size_t)BT_ * 1024];
__device__ __nv_bfloat16 g_krhi[(size_t)BT_ * 64],   g_krlo[(size_t)BT_ * 64];
__device__ __nv_bfloat16 g_wqt_hi[(size_t)2048 * 2048], g_wqt_lo[(size_t)2048 * 2048];
__device__ __nv_bfloat16 g_wkvat_hi[(size_t)640 * 2048], g_wkvat_lo[(size_t)640 * 2048];
__device__ __nv_bfloat16 g_wkvbt_hi[(size_t)1024 * 512], g_wkvbt_lo[(size_t)1024 * 512];
__device__ __nv_bfloat16 g_wot_hi[(size_t)2048 * 1024], g_wot_lo[(size_t)2048 * 1024];

// ---------------------------------------------------------------------------
// fp32 -> bf16 hi/lo split
// ---------------------------------------------------------------------------
__global__ void split_kernel(const float* __restrict__ in, int ld_in,
                             __nv_bfloat16* __restrict__ hi,
                             __nv_bfloat16* __restrict__ lo,
                             int rows, int width)
{
    const int idx = blockIdx.x * blockDim.x + threadIdx.x;
    const int w4 = width >> 2;
    if (idx >= rows * w4) return;
    const int r = idx / w4, c4 = idx - r * w4;
    const float4 v = *(const float4*)&in[(size_t)r * ld_in + c4 * 4];
    float f[4] = {v.x, v.y, v.z, v.w};
    ushort4 hv, lv;
    unsigned short* hp = &hv.x;
    unsigned short* lp = &lv.x;
    #pragma unroll
    for (int i = 0; i < 4; i++) {
        __nv_bfloat16 h = __float2bfloat16(f[i]);
        __nv_bfloat16 l = __float2bfloat16(f[i] - __bfloat162float(h));
        hp[i] = __bfloat16_as_ushort(h);
        lp[i] = __bfloat16_as_ushort(l);
    }
    *(ushort4*)&hi[(size_t)r * width + c4 * 4] = hv;
    *(ushort4*)&lo[(size_t)r * width + c4 * 4] = lv;
}

// ---------------------------------------------------------------------------
// fp32 W[k][n] -> bf16 hi/lo out[n][k] (transpose + optional gather + pad)
// ---------------------------------------------------------------------------
template <bool GATHER>
__global__ void splitT_kernel(const float* __restrict__ W, int ldw, int nIn,
                              __nv_bfloat16* __restrict__ hi,
                              __nv_bfloat16* __restrict__ lo, int kDim)
{
    __shared__ float tile[32][33];
    const int k0 = blockIdx.x * 32, n0 = blockIdx.y * 32;
    #pragma unroll
    for (int i = threadIdx.y; i < 32; i += 8) {
        const int k = k0 + i;
        const int row = GATHER ? (((k >> 6) << 7) + (k & 63)) : k;
        const int n = n0 + threadIdx.x;
        tile[i][threadIdx.x] = (n < nIn) ? W[(size_t)row * ldw + n] : 0.f;
    }
    __syncthreads();
    #pragma unroll
    for (int i = threadIdx.y; i < 32; i += 8) {
        const int n = n0 + i, k = k0 + threadIdx.x;
        const float v = tile[threadIdx.x][i];
        const __nv_bfloat16 h = __float2bfloat16(v);
        hi[(size_t)n * kDim + k] = h;
        lo[(size_t)n * kDim + k] = __float2bfloat16(v - __bfloat162float(h));
    }
}

// ---------------------------------------------------------------------------
// Shared HMMA helpers
// ---------------------------------------------------------------------------
__device__ __forceinline__ uint32_t smem_u32(const void* p) {
    uint32_t a;
    asm("{ .reg .u64 t; cvta.to.shared.u64 t, %1; cvt.u32.u64 %0, t; }"
        : "=r"(a) : "l"(p));
    return a;
}
__device__ __forceinline__ void ldsm4(uint32_t r[4], uint32_t addr) {
    asm volatile("ldmatrix.sync.aligned.m8n8.x4.shared.b16 {%0,%1,%2,%3}, [%4];"
                 : "=r"(r[0]), "=r"(r[1]), "=r"(r[2]), "=r"(r[3]) : "r"(addr));
}
__device__ __forceinline__ void ldsm4t(uint32_t r[4], uint32_t addr) {
    asm volatile("ldmatrix.sync.aligned.m8n8.x4.trans.shared.b16 {%0,%1,%2,%3}, [%4];"
                 : "=r"(r[0]), "=r"(r[1]), "=r"(r[2]), "=r"(r[3]) : "r"(addr));
}
__device__ __forceinline__ void mma_bf16(float c[4], const uint32_t a[4],
                                         const uint32_t b[2]) {
    asm volatile(
        "mma.sync.aligned.m16n8k16.row.col.f32.bf16.bf16.f32 "
        "{%0,%1,%2,%3}, {%4,%5,%6,%7}, {%8,%9}, {%0,%1,%2,%3};"
        : "+f"(c[0]), "+f"(c[1]), "+f"(c[2]), "+f"(c[3])
        : "r"(a[0]), "r"(a[1]), "r"(a[2]), "r"(a[3]), "r"(b[0]), "r"(b[1]));
}
__device__ __forceinline__ void mma_bf16s(float c[4], const uint32_t a[4],
                                          uint32_t b0, uint32_t b1) {
    asm volatile(
        "mma.sync.aligned.m16n8k16.row.col.f32.bf16.bf16.f32 "
        "{%0,%1,%2,%3}, {%4,%5,%6,%7}, {%8,%9}, {%0,%1,%2,%3};"
        : "+f"(c[0]), "+f"(c[1]), "+f"(c[2]), "+f"(c[3])
        : "r"(a[0]), "r"(a[1]), "r"(a[2]), "r"(a[3]), "r"(b0), "r"(b1));
}
// split c0,c1 into packed bf16x2 hi ({lo16=c0}) and lo residual
__device__ __forceinline__ void packsplit(float c0, float c1,
                                          uint32_t& hi, uint32_t& lo) {
    __nv_bfloat16 h0 = __float2bfloat16(c0);
    __nv_bfloat16 h1 = __float2bfloat16(c1);
    __nv_bfloat16 l0 = __float2bfloat16(c0 - __bfloat162float(h0));
    __nv_bfloat16 l1 = __float2bfloat16(c1 - __bfloat162float(h1));
    hi = ((uint32_t)__bfloat16_as_ushort(h1) << 16) | __bfloat16_as_ushort(h0);
    lo = ((uint32_t)__bfloat16_as_ushort(l1) << 16) | __bfloat16_as_ushort(l0);
}

// ---------------------------------------------------------------------------
// HMMA split-precision GEMM (unchanged from R3)
// ---------------------------------------------------------------------------
#define ROWB   80
#define TILEB  (128 * ROWB)
#define BUFB   (4 * TILEB)
#define GEMM_SMEM (2 * BUFB)

template <bool NCHK>
__global__ __launch_bounds__(256)
void hmma_gemm(const __nv_bfloat16* __restrict__ Ahi, const __nv_bfloat16* __restrict__ Alo,
               const __nv_bfloat16* __restrict__ Bhi, const __nv_bfloat16* __restrict__ Blo,
               float* __restrict__ C, int N, int K, int lda, int ldb, int ldc)
{
    extern __shared__ char smc[];
    const uint32_t sb = smem_u32(smc);
    const int tid = threadIdx.x;
    const int lane = tid & 31, warp = tid >> 5;
    const int wm = warp >> 2, wn = warp & 3;
    const int m0 = blockIdx.y * 128, n0 = blockIdx.x * 128;

    const int r_ld = tid >> 2;
    const int s_ld = (tid & 3) * 8;
    const size_t aoff0 = (size_t)(m0 + r_ld) * lda + s_ld;
    const size_t aoff1 = (size_t)(m0 + r_ld + 64) * lda + s_ld;
    const size_t boff0 = (size_t)(n0 + r_ld) * ldb + s_ld;
    const size_t boff1 = (size_t)(n0 + r_ld + 64) * ldb + s_ld;
    const uint32_t st0 = r_ld * ROWB + (tid & 3) * 16;
    const uint32_t st1 = (r_ld + 64) * ROWB + (tid & 3) * 16;

    float4 vAh[2], vAl[2], vBh[2], vBl[2];
    #define LOADREGS(k0_)                                                     \
        vAh[0] = *(const float4*)(Ahi + aoff0 + (k0_));                       \
        vAh[1] = *(const float4*)(Ahi + aoff1 + (k0_));                       \
        vAl[0] = *(const float4*)(Alo + aoff0 + (k0_));                       \
        vAl[1] = *(const float4*)(Alo + aoff1 + (k0_));                       \
        vBh[0] = *(const float4*)(Bhi + boff0 + (k0_));                       \
        vBh[1] = *(const float4*)(Bhi + boff1 + (k0_));                       \
        vBl[0] = *(const float4*)(Blo + boff0 + (k0_));                       \
        vBl[1] = *(const float4*)(Blo + boff1 + (k0_));

    float c[4][4][4];
    #pragma unroll
    for (int i = 0; i < 4; i++)
        #pragma unroll
        for (int j = 0; j < 4; j++)
            #pragma unroll
            for (int l = 0; l < 4; l++) c[i][j][l] = 0.f;

    const uint32_t a_row = wm * 64 + (lane & 15);
    const uint32_t a_koff = (lane >> 4) * 16;
    const uint32_t b_row = wn * 32 + ((lane >> 4) << 3) + (lane & 7);
    const uint32_t b_koff = ((lane >> 3) & 1) * 16;

    const int niter = K >> 5;
    LOADREGS(0);

    for (int it = 0; it < niter; it++) {
        const uint32_t buf = sb + (uint32_t)(it & 1) * BUFB;
        *(float4*)(smc + (buf - sb) + 0 * TILEB + st0) = vAh[0];
        *(float4*)(smc + (buf - sb) + 0 * TILEB + st1) = vAh[1];
        *(float4*)(smc + (buf - sb) + 1 * TILEB + st0) = vAl[0];
        *(float4*)(smc + (buf - sb) + 1 * TILEB + st1) = vAl[1];
        *(float4*)(smc + (buf - sb) + 2 * TILEB + st0) = vBh[0];
        *(float4*)(smc + (buf - sb) + 2 * TILEB + st1) = vBh[1];
        *(float4*)(smc + (buf - sb) + 3 * TILEB + st0) = vBl[0];
        *(float4*)(smc + (buf - sb) + 3 * TILEB + st1) = vBl[1];
        __syncthreads();

        if (it + 1 < niter) { LOADREGS((it + 1) << 5); }

        #pragma unroll
        for (int ks = 0; ks < 2; ks++) {
            const uint32_t kb = ks * 32;
            uint32_t afh[4][4], afl[4][4], bfh[4][2], bfl[4][2];
            #pragma unroll
            for (int mt = 0; mt < 4; mt++) {
                const uint32_t ad = buf + (a_row + mt * 16) * ROWB + kb + a_koff;
                ldsm4(afh[mt], ad + 0 * TILEB);
                ldsm4(afl[mt], ad + 1 * TILEB);
            }
            #pragma unroll
            for (int np = 0; np < 2; np++) {
                const uint32_t bd = buf + (b_row + np * 16) * ROWB + kb + b_koff;
                uint32_t t[4];
                ldsm4(t, bd + 2 * TILEB);
                bfh[np * 2][0] = t[0]; bfh[np * 2][1] = t[1];
                bfh[np * 2 + 1][0] = t[2]; bfh[np * 2 + 1][1] = t[3];
                ldsm4(t, bd + 3 * TILEB);
                bfl[np * 2][0] = t[0]; bfl[np * 2][1] = t[1];
                bfl[np * 2 + 1][0] = t[2]; bfl[np * 2 + 1][1] = t[3];
            }
            #pragma unroll
            for (int mt = 0; mt < 4; mt++)
                #pragma unroll
                for (int nt = 0; nt < 4; nt++) {
                    mma_bf16(c[mt][nt], afh[mt], bfh[nt]);
                    mma_bf16(c[mt][nt], afh[mt], bfl[nt]);
                    mma_bf16(c[mt][nt], afl[mt], bfh[nt]);
                }
        }
        __syncthreads();
    }
    #undef LOADREGS

    #pragma unroll
    for (int mt = 0; mt < 4; mt++) {
        const int row = m0 + wm * 64 + mt * 16 + (lane >> 2);
        #pragma unroll
        for (int nt = 0; nt < 4; nt++) {
            const int col = n0 + wn * 32 + nt * 8 + (lane & 3) * 2;
            if (!NCHK || col < N) {
                *(float2*)&C[(size_t)row * ldc + col] =
                    make_float2(c[mt][nt][0], c[mt][nt][1]);
                *(float2*)&C[(size_t)(row + 8) * ldc + col] =
                    make_float2(c[mt][nt][2], c[mt][nt][3]);
            }
        }
    }
}

// ---------------------------------------------------------------------------
// RoPE
// ---------------------------------------------------------------------------
__global__ void rope_kernel(float* __restrict__ q, const float* __restrict__ ckv,
                            float* __restrict__ krope)
{
    const int idx = blockIdx.x * blockDim.x + threadIdx.x;
    const int QP = BT_ * H_ * (RD_ / 2);
    const int TOT = QP + BT_ * (RD_ / 2);
    if (idx >= TOT) return;

    if (idx < QP) {
        const int i  = idx & 31;
        const int h  = (idx >> 5) & 15;
        const int bt = idx >> 9;
        const int t  = bt & (T_ - 1);
        const float freq = (float)pow(100000.0, -(double)i / 32.0);
        float s, c;
        sincosf((float)t * freq, &s, &c);
        float* p = q + (size_t)bt * 2048 + h * 128 + 64 + 2 * i;
        const float x0 = p[0], x1 = p[1];
        p[0] = x0 * c - x1 * s;
        p[1] = x0 * s + x1 * c;
    } else {
        const int k  = idx - QP;
        const int i  = k & 31;
        const int bt = k >> 5;
        const int t  = bt & (T_ - 1);
        const float freq = (float)pow(100000.0, -(double)i / 32.0);
        float s, c;
        sincosf((float)t * freq, &s, &c);
        const float* p = ckv + (size_t)bt * 576 + 512 + 2 * i;
        const float x0 = p[0], x1 = p[1];
        krope[(size_t)bt * 64 + 2 * i]     = x0 * c - x1 * s;
        krope[(size_t)bt * 64 + 2 * i + 1] = x0 * s + x1 * c;
    }
}

// ---------------------------------------------------------------------------
// HMMA flash attention (causal), split precision.
// CTA: 128 q rows, 8 warps (m16 each). K-tiles of 64 keys.
// Q frags held in registers; K smem tile doubles as V (ldmatrix.trans).
// Writes yhi/ylo bf16 directly.
// ---------------------------------------------------------------------------
#define APITCH 272
#define KTILEB (64 * APITCH)             // 17408
#define ATTN_SMEM (2 * 128 * APITCH)     // 69632 (Q staging hi+lo; reused for K)

__global__ __launch_bounds__(256)
void attn_hmma(const __nv_bfloat16* __restrict__ qhi, const __nv_bfloat16* __restrict__ qlo,
               const __nv_bfloat16* __restrict__ kvhi, const __nv_bfloat16* __restrict__ kvlo,
               const __nv_bfloat16* __restrict__ krhi, const __nv_bfloat16* __restrict__ krlo,
               __nv_bfloat16* __restrict__ yhi, __nv_bfloat16* __restrict__ ylo)
{
    extern __shared__ char sma[];
    const uint32_t sb = smem_u32(sma);
    const int tid = threadIdx.x;
    const int lane = tid & 31, warp = tid >> 5;
    const int qt = blockIdx.x, h = blockIdx.y, b = blockIdx.z;
    const int q0 = qt * 128;
    const int bq0 = b * T_ + q0;
    const float scale = 0.08838834764831845f;   // 1/sqrt(128)

    // ---- stage Q (hi, lo) and pull fragments into registers ----
    #pragma unroll
    for (int t = 0; t < 2; t++) {
        const __nv_bfloat16* src = t ? qlo : qhi;
        #pragma unroll
        for (int i = 0; i < 8; i++) {
            const int idx = i * 256 + tid;         // 0..2047
            const int r = idx >> 4, gc = idx & 15;
            *(float4*)(sma + t * (128 * APITCH) + r * APITCH + gc * 16) =
                *(const float4*)(src + (size_t)(bq0 + r) * 2048 + h * 128 + gc * 8);
        }
    }
    __syncthreads();

    uint32_t qh[8][4], ql[8][4];
    {
        const uint32_t a_base = sb + (warp * 16 + (lane & 15)) * APITCH + (lane >> 4) * 16;
        #pragma unroll
        for (int kt = 0; kt < 8; kt++) {
            ldsm4(qh[kt], a_base + kt * 32);
            ldsm4(ql[kt], a_base + kt * 32 + 128 * APITCH);
        }
    }
    __syncthreads();    // smem now free for K tiles

    float m_i[2] = {-1e30f, -1e30f};
    float l_i[2] = {0.f, 0.f};
    float o[8][4];
    #pragma unroll
    for (int j = 0; j < 8; j++)
        #pragma unroll
        for (int e = 0; e < 4; e++) o[j][e] = 0.f;

    const int g = lane >> 2, cq = lane & 3;
    const int rbase = q0 + warp * 16 + g;

    const int nk = 2 * qt + 2;
    for (int c = 0; c < nk; c++) {
        const int bk0 = b * T_ + c * 64;
        __syncthreads();
        // ---- load K tile: rows s(64) x cols d(128); cols 0-63 kv, 64-127 krope
        #pragma unroll
        for (int t = 0; t < 2; t++) {
            const __nv_bfloat16* vsrc = t ? kvlo : kvhi;
            const __nv_bfloat16* rsrc = t ? krlo : krhi;
            #pragma unroll
            for (int i = 0; i < 4; i++) {
                const int idx = i * 256 + tid;       // 0..1023
                const int s = idx >> 4, gc = idx & 15;
                float4 v;
                if (gc < 8)
                    v = *(const float4*)(vsrc + (size_t)(bk0 + s) * 1024 + h * 64 + gc * 8);
                else
                    v = *(const float4*)(rsrc + (size_t)(bk0 + s) * 64 + (gc - 8) * 8);
                *(float4*)(sma + t * KTILEB + s * APITCH + gc * 16) = v;
            }
        }
        __syncthreads();

        // ---- S = Q K^T ----
        float cS[8][4];
        #pragma unroll
        for (int j = 0; j < 8; j++)
            #pragma unroll
            for (int e = 0; e < 4; e++) cS[j][e] = 0.f;

        const uint32_t b_base = sb + (((lane >> 4) << 3) + (lane & 7)) * APITCH
                              + ((lane >> 3) & 1) * 16;
        #pragma unroll
        for (int kt = 0; kt < 8; kt++) {
            #pragma unroll
            for (int np = 0; np < 4; np++) {
                uint32_t th[4], tl[4];
                const uint32_t bd = b_base + np * 16 * APITCH + kt * 32;
                ldsm4(th, bd);
                ldsm4(tl, bd + KTILEB);
                const int j0 = 2 * np;
                mma_bf16s(cS[j0],     qh[kt], th[0], th[1]);
                mma_bf16s(cS[j0],     qh[kt], tl[0], tl[1]);
                mma_bf16s(cS[j0],     ql[kt], th[0], th[1]);
                mma_bf16s(cS[j0 + 1], qh[kt], th[2], th[3]);
                mma_bf16s(cS[j0 + 1], qh[kt], tl[2], tl[3]);
                mma_bf16s(cS[j0 + 1], ql[kt], th[2], th[3]);
            }
        }

        // ---- scale + causal mask ----
        const int cbase = c * 64 + cq * 2;
        #pragma unroll
        for (int j = 0; j < 8; j++) {
            const int col = cbase + j * 8;
            cS[j][0] = (col     <= rbase)     ? cS[j][0] * scale : -3e30f;
            cS[j][1] = (col + 1 <= rbase)     ? cS[j][1] * scale : -3e30f;
            cS[j][2] = (col     <= rbase + 8) ? cS[j][2] * scale : -3e30f;
            cS[j][3] = (col + 1 <= rbase + 8) ? cS[j][3] * scale : -3e30f;
        }

        // ---- online softmax ----
        float mx0 = -3e30f, mx1 = -3e30f;
        #pragma unroll
        for (int j = 0; j < 8; j++) {
            mx0 = fmaxf(mx0, fmaxf(cS[j][0], cS[j][1]));
            mx1 = fmaxf(mx1, fmaxf(cS[j][2], cS[j][3]));
        }
        mx0 = fmaxf(mx0, __shfl_xor_sync(0xffffffffu, mx0, 1));
        mx0 = fmaxf(mx0, __shfl_xor_sync(0xffffffffu, mx0, 2));
        mx1 = fmaxf(mx1, __shfl_xor_sync(0xffffffffu, mx1, 1));
        mx1 = fmaxf(mx1, __shfl_xor_sync(0xffffffffu, mx1, 2));
        const float nm0 = fmaxf(m_i[0], mx0);
        const float nm1 = fmaxf(m_i[1], mx1);
        const float f0 = __expf(m_i[0] - nm0);
        const float f1 = __expf(m_i[1] - nm1);
        float s0 = 0.f, s1 = 0.f;
        #pragma unroll
        for (int j = 0; j < 8; j++) {
            cS[j][0] = __expf(cS[j][0] - nm0);
            cS[j][1] = __expf(cS[j][1] - nm0);
            cS[j][2] = __expf(cS[j][2] - nm1);
            cS[j][3] = __expf(cS[j][3] - nm1);
            s0 += cS[j][0] + cS[j][1];
            s1 += cS[j][2] + cS[j][3];
        }
        s0 += __shfl_xor_sync(0xffffffffu, s0, 1);
        s0 += __shfl_xor_sync(0xffffffffu, s0, 2);
        s1 += __shfl_xor_sync(0xffffffffu, s1, 1);
        s1 += __shfl_xor_sync(0xffffffffu, s1, 2);
        l_i[0] = l_i[0] * f0 + s0;  m_i[0] = nm0;
        l_i[1] = l_i[1] * f1 + s1;  m_i[1] = nm1;
        #pragma unroll
        for (int j = 0; j < 8; j++) {
            o[j][0] *= f0; o[j][1] *= f0;
            o[j][2] *= f1; o[j][3] *= f1;
        }

        // ---- O += P @ V  (V = kv half of K smem, via ldmatrix.trans) ----
        const uint32_t v_row = ((lane & 7) + 8 * ((lane >> 3) & 1)) * APITCH
                             + (lane >> 4) * 16;   // row*pitch + col*2 (8 cols)
        #pragma unroll
        for (int ks = 0; ks < 4; ks++) {
            uint32_t ah[4], al[4];
            packsplit(cS[2 * ks][0],     cS[2 * ks][1],     ah[0], al[0]);
            packsplit(cS[2 * ks][2],     cS[2 * ks][3],     ah[1], al[1]);
            packsplit(cS[2 * ks + 1][0], cS[2 * ks + 1][1], ah[2], al[2]);
            packsplit(cS[2 * ks + 1][2], cS[2 * ks + 1][3], ah[3], al[3]);
            #pragma unroll
            for (int np = 0; np < 4; np++) {
                uint32_t th[4], tl[4];
                const uint32_t vd = sb + v_row + ks * 16 * APITCH + np * 32;
                ldsm4t(th, vd);
                ldsm4t(tl, vd + KTILEB);
                const int jd = 2 * np;
                mma_bf16s(o[jd],     ah, th[0], th[1]);
                mma_bf16s(o[jd],     ah, tl[0], tl[1]);
                mma_bf16s(o[jd],     al, th[0], th[1]);
                mma_bf16s(o[jd + 1], ah, th[2], th[3]);
                mma_bf16s(o[jd + 1], ah, tl[2], tl[3]);
                mma_bf16s(o[jd + 1], al, th[2], th[3]);
            }
        }
    }

    // ---- epilogue: y = o / l, write bf16 hi/lo ----
    const float inv0 = 1.f / l_i[0];
    const float inv1 = 1.f / l_i[1];
    const size_t row0 = (size_t)(bq0 + warp * 16 + g);
    const size_t row1 = row0 + 8;
    #pragma unroll
    for (int j = 0; j < 8; j++) {
        const int col = h * 64 + j * 8 + cq * 2;
        uint32_t hi, lo;
        packsplit(o[j][0] * inv0, o[j][1] * inv0, hi, lo);
        *(uint32_t*)&yhi[row0 * 1024 + col] = hi;
        *(uint32_t*)&ylo[row0 * 1024 + col] = lo;
        packsplit(o[j][2] * inv1, o[j][3] * inv1, hi, lo);
        *(uint32_t*)&yhi[row1 * 1024 + col] = hi;
        *(uint32_t*)&ylo[row1 * 1024 + col] = lo;
    }
}

// ---------------------------------------------------------------------------
// Launch
// ---------------------------------------------------------------------------
extern "C" void kernel_launch(void* const* d_in, const int* in_sizes, int n_in,
                              void* d_out, int out_size)
{
    const float* x    = (const float*)d_in[0];
    const float* Wq   = (const float*)d_in[1];
    const float* Wkva = (const float*)d_in[2];
    const float* Wkvb = (const float*)d_in[3];
    const float* Wo   = (const float*)d_in[4];
    float* out = (float*)d_out;

    float *q, *ckv, *kvb, *kr;
    cudaGetSymbolAddress((void**)&q,   g_q);
    cudaGetSymbolAddress((void**)&ckv, g_ckv);
    cudaGetSymbolAddress((void**)&kvb, g_kv);
    cudaGetSymbolAddress((void**)&kr,  g_krope);
    __nv_bfloat16 *xhi, *xlo, *ckvhi, *ckvlo, *yhi, *ylo;
    __nv_bfloat16 *qhi, *qlo, *kvhi, *kvlo, *krhi, *krlo;
    __nv_bfloat16 *wqh, *wql, *wah, *wal, *wbh, *wbl, *woh, *wol;
    cudaGetSymbolAddress((void**)&xhi, g_xhi);     cudaGetSymbolAddress((void**)&xlo, g_xlo);
    cudaGetSymbolAddress((void**)&ckvhi, g_ckvhi); cudaGetSymbolAddress((void**)&ckvlo, g_ckvlo);
    cudaGetSymbolAddress((void**)&yhi, g_yhi);     cudaGetSymbolAddress((void**)&ylo, g_ylo);
    cudaGetSymbolAddress((void**)&qhi, g_qhi);     cudaGetSymbolAddress((void**)&qlo, g_qlo);
    cudaGetSymbolAddress((void**)&kvhi, g_kvhi);   cudaGetSymbolAddress((void**)&kvlo, g_kvlo);
    cudaGetSymbolAddress((void**)&krhi, g_krhi);   cudaGetSymbolAddress((void**)&krlo, g_krlo);
    cudaGetSymbolAddress((void**)&wqh, g_wqt_hi);  cudaGetSymbolAddress((void**)&wql, g_wqt_lo);
    cudaGetSymbolAddress((void**)&wah, g_wkvat_hi); cudaGetSymbolAddress((void**)&wal, g_wkvat_lo);
    cudaGetSymbolAddress((void**)&wbh, g_wkvbt_hi); cudaGetSymbolAddress((void**)&wbl, g_wkvbt_lo);
    cudaGetSymbolAddress((void**)&woh, g_wot_hi);  cudaGetSymbolAddress((void**)&wol, g_wot_lo);

    cudaFuncSetAttribute(hmma_gemm<false>,
                         cudaFuncAttributeMaxDynamicSharedMemorySize, GEMM_SMEM);
    cudaFuncSetAttribute(hmma_gemm<true>,
                         cudaFuncAttributeMaxDynamicSharedMemorySize, GEMM_SMEM);
    cudaFuncSetAttribute(attn_hmma,
                         cudaFuncAttributeMaxDynamicSharedMemorySize, ATTN_SMEM);

    const dim3 tb(32, 8);
    splitT_kernel<false><<<dim3(64, 64), tb>>>(Wq,   2048, 2048, wqh, wql, 2048);
    splitT_kernel<false><<<dim3(64, 20), tb>>>(Wkva,  576,  576, wah, wal, 2048);
    splitT_kernel<false><<<dim3(16, 32), tb>>>(Wkvb, 1024, 1024, wbh, wbl,  512);
    splitT_kernel<true ><<<dim3(32, 64), tb>>>(Wo,   2048, 2048, woh, wol, 1024);
    split_kernel<<<8192, 256>>>(x, 2048, xhi, xlo, 4096, 2048);

    // q = x @ Wq
    hmma_gemm<false><<<dim3(16, 32), 256, GEMM_SMEM>>>(xhi, xlo, wqh, wql, q,
        2048, 2048, 2048, 2048, 2048);
    // ckv = x @ Wkva
    hmma_gemm<true><<<dim3(5, 32), 256, GEMM_SMEM>>>(xhi, xlo, wah, wal, ckv,
        576, 2048, 2048, 2048, 576);
    // rope
    rope_kernel<<<8704, 256>>>(q, ckv, kr);
    // splits for attention operands
    split_kernel<<<8192, 256>>>(q, 2048, qhi, qlo, 4096, 2048);
    split_kernel<<<2048, 256>>>(ckv, 576, ckvhi, ckvlo, 4096, 512);
    split_kernel<<<256, 256>>>(kr, 64, krhi, krlo, 4096, 64);
    // kv = latent @ Wkvb
    hmma_gemm<false><<<dim3(8, 32), 256, GEMM_SMEM>>>(ckvhi, ckvlo, wbh, wbl, kvb,
        1024, 512, 512, 512, 1024);
    split_kernel<<<4096, 256>>>(kvb, 1024, kvhi, kvlo, 4096, 1024);
    // attention (writes yhi/ylo directly)
    attn_hmma<<<dim3(16, 16, 2), 256, ATTN_SMEM>>>(qhi, qlo, kvhi, kvlo,
                                                   krhi, krlo, yhi, ylo);
    // out = y @ gather(Wo)
    hmma_gemm<false><<<dim3(16, 32), 256, GEMM_SMEM>>>(yhi, ylo, woh, wol, out,
        2048, 1024, 1024, 1024, 2048);
}

// round 7
// speedup vs baseline: 2.9416x; 1.2296x over previous
#include <cuda_runtime.h>
#include <cuda_bf16.h>
#include <math.h>
#include <stdint.h>

// Problem constants
#define B_    2
#define T_    2048
#define C_    2048
#define H_    16
#define HD_   128
#define LORA_ 512
#define RD_   64
#define ND_   64
#define BT_   (B_ * T_)   // 4096

// ---------------------------------------------------------------------------
// Scratch (static __device__ globals — allocation-free per harness rules)
// ---------------------------------------------------------------------------
__device__ float g_freq[32];

__device__ __align__(16) __nv_bfloat16 g_xhi[(size_t)BT_ * 2048],  g_xlo[(size_t)BT_ * 2048];
__device__ __align__(16) __nv_bfloat16 g_qhi[(size_t)BT_ * 2048],  g_qlo[(size_t)BT_ * 2048];
__device__ __align__(16) __nv_bfloat16 g_ckvhi[(size_t)BT_ * 512], g_ckvlo[(size_t)BT_ * 512];
__device__ __align__(16) __nv_bfloat16 g_kvhi[(size_t)BT_ * 1024], g_kvlo[(size_t)BT_ * 1024];
__device__ __align__(16) __nv_bfloat16 g_krhi[(size_t)BT_ * 64],   g_krlo[(size_t)BT_ * 64];
__device__ __align__(16) __nv_bfloat16 g_yhi[(size_t)BT_ * 1024],  g_ylo[(size_t)BT_ * 1024];
__device__ __align__(16) __nv_bfloat16 g_wqt_hi[(size_t)2048 * 2048], g_wqt_lo[(size_t)2048 * 2048];
__device__ __align__(16) __nv_bfloat16 g_wkvat_hi[(size_t)640 * 2048], g_wkvat_lo[(size_t)640 * 2048];
__device__ __align__(16) __nv_bfloat16 g_wkvbt_hi[(size_t)1024 * 512], g_wkvbt_lo[(size_t)1024 * 512];
__device__ __align__(16) __nv_bfloat16 g_wot_hi[(size_t)2048 * 1024], g_wot_lo[(size_t)2048 * 1024];

// ---------------------------------------------------------------------------
// RoPE frequency table (exact formula as reference; computed once per launch)
// ---------------------------------------------------------------------------
__global__ void freq_init_kernel() {
    const int i = threadIdx.x;
    if (i < 32) g_freq[i] = (float)pow(100000.0, -(double)i / 32.0);
}

// ---------------------------------------------------------------------------
// fp32 -> bf16 hi/lo split (for x)
// ---------------------------------------------------------------------------
__global__ void split_kernel(const float* __restrict__ in, int ld_in,
                             __nv_bfloat16* __restrict__ hi,
                             __nv_bfloat16* __restrict__ lo,
                             int rows, int width)
{
    const int idx = blockIdx.x * blockDim.x + threadIdx.x;
    const int w4 = width >> 2;
    if (idx >= rows * w4) return;
    const int r = idx / w4, c4 = idx - r * w4;
    const float4 v = *(const float4*)&in[(size_t)r * ld_in + c4 * 4];
    float f[4] = {v.x, v.y, v.z, v.w};
    ushort4 hv, lv;
    unsigned short* hp = &hv.x;
    unsigned short* lp = &lv.x;
    #pragma unroll
    for (int i = 0; i < 4; i++) {
        __nv_bfloat16 h = __float2bfloat16(f[i]);
        __nv_bfloat16 l = __float2bfloat16(f[i] - __bfloat162float(h));
        hp[i] = __bfloat16_as_ushort(h);
        lp[i] = __bfloat16_as_ushort(l);
    }
    *(ushort4*)&hi[(size_t)r * width + c4 * 4] = hv;
    *(ushort4*)&lo[(size_t)r * width + c4 * 4] = lv;
}

// ---------------------------------------------------------------------------
// fp32 W[k][n] -> bf16 hi/lo out[n][k] (transpose + optional gather + pad)
// ---------------------------------------------------------------------------
template <bool GATHER>
__global__ void splitT_kernel(const float* __restrict__ W, int ldw, int nIn,
                              __nv_bfloat16* __restrict__ hi,
                              __nv_bfloat16* __restrict__ lo, int kDim)
{
    __shared__ float tile[32][33];
    const int k0 = blockIdx.x * 32, n0 = blockIdx.y * 32;
    #pragma unroll
    for (int i = threadIdx.y; i < 32; i += 8) {
        const int k = k0 + i;
        const int row = GATHER ? (((k >> 6) << 7) + (k & 63)) : k;
        const int n = n0 + threadIdx.x;
        tile[i][threadIdx.x] = (n < nIn) ? W[(size_t)row * ldw + n] : 0.f;
    }
    __syncthreads();
    #pragma unroll
    for (int i = threadIdx.y; i < 32; i += 8) {
        const int n = n0 + i, k = k0 + threadIdx.x;
        const float v = tile[threadIdx.x][i];
        const __nv_bfloat16 h = __float2bfloat16(v);
        hi[(size_t)n * kDim + k] = h;
        lo[(size_t)n * kDim + k] = __float2bfloat16(v - __bfloat162float(h));
    }
}

// ---------------------------------------------------------------------------
// Shared HMMA helpers
// ---------------------------------------------------------------------------
__device__ __forceinline__ uint32_t smem_u32(const void* p) {
    uint32_t a;
    asm("{ .reg .u64 t; cvta.to.shared.u64 t, %1; cvt.u32.u64 %0, t; }"
        : "=r"(a) : "l"(p));
    return a;
}
__device__ __forceinline__ void cp16(uint32_t dst, const void* src) {
    asm volatile("cp.async.cg.shared.global [%0], [%1], 16;"
                 :: "r"(dst), "l"(src) : "memory");
}
__device__ __forceinline__ void ldsm4(uint32_t r[4], uint32_t addr) {
    asm volatile("ldmatrix.sync.aligned.m8n8.x4.shared.b16 {%0,%1,%2,%3}, [%4];"
                 : "=r"(r[0]), "=r"(r[1]), "=r"(r[2]), "=r"(r[3]) : "r"(addr));
}
__device__ __forceinline__ void ldsm4t(uint32_t r[4], uint32_t addr) {
    asm volatile("ldmatrix.sync.aligned.m8n8.x4.trans.shared.b16 {%0,%1,%2,%3}, [%4];"
                 : "=r"(r[0]), "=r"(r[1]), "=r"(r[2]), "=r"(r[3]) : "r"(addr));
}
__device__ __forceinline__ void mma_bf16(float c[4], const uint32_t a[4],
                                         const uint32_t b[2]) {
    asm volatile(
        "mma.sync.aligned.m16n8k16.row.col.f32.bf16.bf16.f32 "
        "{%0,%1,%2,%3}, {%4,%5,%6,%7}, {%8,%9}, {%0,%1,%2,%3};"
        : "+f"(c[0]), "+f"(c[1]), "+f"(c[2]), "+f"(c[3])
        : "r"(a[0]), "r"(a[1]), "r"(a[2]), "r"(a[3]), "r"(b[0]), "r"(b[1]));
}
__device__ __forceinline__ void mma_bf16s(float c[4], const uint32_t a[4],
                                          uint32_t b0, uint32_t b1) {
    asm volatile(
        "mma.sync.aligned.m16n8k16.row.col.f32.bf16.bf16.f32 "
        "{%0,%1,%2,%3}, {%4,%5,%6,%7}, {%8,%9}, {%0,%1,%2,%3};"
        : "+f"(c[0]), "+f"(c[1]), "+f"(c[2]), "+f"(c[3])
        : "r"(a[0]), "r"(a[1]), "r"(a[2]), "r"(a[3]), "r"(b0), "r"(b1));
}
__device__ __forceinline__ void packsplit(float c0, float c1,
                                          uint32_t& hi, uint32_t& lo) {
    __nv_bfloat16 h0 = __float2bfloat16(c0);
    __nv_bfloat16 h1 = __float2bfloat16(c1);
    __nv_bfloat16 l0 = __float2bfloat16(c0 - __bfloat162float(h0));
    __nv_bfloat16 l1 = __float2bfloat16(c1 - __bfloat162float(h1));
    hi = ((uint32_t)__bfloat16_as_ushort(h1) << 16) | __bfloat16_as_ushort(h0);
    lo = ((uint32_t)__bfloat16_as_ushort(l1) << 16) | __bfloat16_as_ushort(l0);
}

// ---------------------------------------------------------------------------
// Epilogue modes
// ---------------------------------------------------------------------------
#define EPI_F32   0
#define EPI_SPLIT 1
#define EPI_Q     2
#define EPI_CKV   3

template <int EPI>
__device__ __forceinline__ void epi_store(int row, int col, float v0, float v1,
    float* __restrict__ Cf,
    __nv_bfloat16* __restrict__ O1, __nv_bfloat16* __restrict__ O2,
    __nv_bfloat16* __restrict__ O3, __nv_bfloat16* __restrict__ O4, int ldc)
{
    if (EPI == EPI_F32) {
        *(float2*)&Cf[(size_t)row * ldc + col] = make_float2(v0, v1);
    } else if (EPI == EPI_SPLIT) {
        uint32_t h, l;
        packsplit(v0, v1, h, l);
        *(uint32_t*)&O1[(size_t)row * ldc + col] = h;
        *(uint32_t*)&O2[(size_t)row * ldc + col] = l;
    } else if (EPI == EPI_Q) {
        const int d = col & 127;
        if (d >= 64) {
            const float freq = g_freq[(d - 64) >> 1];
            float s, c;
            sincosf((float)(row & (T_ - 1)) * freq, &s, &c);
            const float t0 = v0 * c - v1 * s;
            const float t1 = v0 * s + v1 * c;
            v0 = t0; v1 = t1;
        }
        uint32_t h, l;
        packsplit(v0, v1, h, l);
        *(uint32_t*)&O1[(size_t)row * 2048 + col] = h;
        *(uint32_t*)&O2[(size_t)row * 2048 + col] = l;
    } else {  // EPI_CKV
        if (col < 512) {
            uint32_t h, l;
            packsplit(v0, v1, h, l);
            *(uint32_t*)&O1[(size_t)row * 512 + col] = h;
            *(uint32_t*)&O2[(size_t)row * 512 + col] = l;
        } else if (col < 576) {
            const float freq = g_freq[(col - 512) >> 1];
            float s, c;
            sincosf((float)(row & (T_ - 1)) * freq, &s, &c);
            uint32_t h, l;
            packsplit(v0 * c - v1 * s, v0 * s + v1 * c, h, l);
            *(uint32_t*)&O3[(size_t)row * 64 + (col - 512)] = h;
            *(uint32_t*)&O4[(size_t)row * 64 + (col - 512)] = l;
        }
    }
}

// ---------------------------------------------------------------------------
// HMMA split-precision GEMM, cp.async double-buffered:
//   C[M,N] = (Ahi+Alo)[M,K] @ (Bhi+Blo)[N,K]^T   (drop lo*lo)
// CTA 128x128, 8 warps of 64x32, BK=32, 1 barrier per K-iter.
// ---------------------------------------------------------------------------
#define ROWB   80
#define TILEB  (128 * ROWB)     // 10240
#define STAGEB (4 * TILEB)      // 40960
#define GEMM_SMEM (2 * STAGEB)  // 81920

template <int EPI>
__global__ __launch_bounds__(256)
void hmma_gemm(const __nv_bfloat16* __restrict__ Ahi, const __nv_bfloat16* __restrict__ Alo,
               const __nv_bfloat16* __restrict__ Bhi, const __nv_bfloat16* __restrict__ Blo,
               float* __restrict__ Cf,
               __nv_bfloat16* __restrict__ O1, __nv_bfloat16* __restrict__ O2,
               __nv_bfloat16* __restrict__ O3, __nv_bfloat16* __restrict__ O4,
               int K, int lda, int ldb, int ldc)
{
    extern __shared__ char smc[];
    const uint32_t sb = smem_u32(smc);
    const int tid = threadIdx.x;
    const int lane = tid & 31, warp = tid >> 5;
    const int wm = warp >> 2, wn = warp & 3;
    const int m0 = blockIdx.y * 128, n0 = blockIdx.x * 128;

    // cp.async mapping: thread -> rows r_ld, r_ld+64, 16B chunk cc per tile
    const int r_ld = tid >> 2;
    const int cc = tid & 3;
    const __nv_bfloat16* pAh0 = Ahi + (size_t)(m0 + r_ld) * lda + cc * 8;
    const __nv_bfloat16* pAh1 = Ahi + (size_t)(m0 + r_ld + 64) * lda + cc * 8;
    const __nv_bfloat16* pAl0 = Alo + (size_t)(m0 + r_ld) * lda + cc * 8;
    const __nv_bfloat16* pAl1 = Alo + (size_t)(m0 + r_ld + 64) * lda + cc * 8;
    const __nv_bfloat16* pBh0 = Bhi + (size_t)(n0 + r_ld) * ldb + cc * 8;
    const __nv_bfloat16* pBh1 = Bhi + (size_t)(n0 + r_ld + 64) * ldb + cc * 8;
    const __nv_bfloat16* pBl0 = Blo + (size_t)(n0 + r_ld) * ldb + cc * 8;
    const __nv_bfloat16* pBl1 = Blo + (size_t)(n0 + r_ld + 64) * ldb + cc * 8;
    const uint32_t d0 = r_ld * ROWB + cc * 16;
    const uint32_t d1 = (r_ld + 64) * ROWB + cc * 16;

    #define ISSUE(st, k0_) do {                                               \
        const uint32_t bb = sb + (uint32_t)(st) * STAGEB;                     \
        cp16(bb + 0 * TILEB + d0, pAh0 + (k0_));                              \
        cp16(bb + 0 * TILEB + d1, pAh1 + (k0_));                              \
        cp16(bb + 1 * TILEB + d0, pAl0 + (k0_));                              \
        cp16(bb + 1 * TILEB + d1, pAl1 + (k0_));                              \
        cp16(bb + 2 * TILEB + d0, pBh0 + (k0_));                              \
        cp16(bb + 2 * TILEB + d1, pBh1 + (k0_));                              \
        cp16(bb + 3 * TILEB + d0, pBl0 + (k0_));                              \
        cp16(bb + 3 * TILEB + d1, pBl1 + (k0_));                              \
        asm volatile("cp.async.commit_group;" ::: "memory");                  \
    } while (0)

    float c[4][4][4];
    #pragma unroll
    for (int i = 0; i < 4; i++)
        #pragma unroll
        for (int j = 0; j < 4; j++)
            #pragma unroll
            for (int l = 0; l < 4; l++) c[i][j][l] = 0.f;

    const uint32_t a_row = wm * 64 + (lane & 15);
    const uint32_t a_koff = (lane >> 4) * 16;
    const uint32_t b_row = wn * 32 + ((lane >> 4) << 3) + (lane & 7);
    const uint32_t b_koff = ((lane >> 3) & 1) * 16;

    const int niter = K >> 5;
    ISSUE(0, 0);

    for (int it = 0; it < niter; it++) {
        asm volatile("cp.async.wait_group 0;" ::: "memory");
        __syncthreads();
        if (it + 1 < niter) ISSUE((it + 1) & 1, (it + 1) << 5);

        const uint32_t buf = sb + (uint32_t)(it & 1) * STAGEB;
        #pragma unroll
        for (int ks = 0; ks < 2; ks++) {
            const uint32_t kb = ks * 32;
            uint32_t afh[4][4], afl[4][4], bfh[4][2], bfl[4][2];
            #pragma unroll
            for (int mt = 0; mt < 4; mt++) {
                const uint32_t ad = buf + (a_row + mt * 16) * ROWB + kb + a_koff;
                ldsm4(afh[mt], ad + 0 * TILEB);
                ldsm4(afl[mt], ad + 1 * TILEB);
            }
            #pragma unroll
            for (int np = 0; np < 2; np++) {
                const uint32_t bd = buf + (b_row + np * 16) * ROWB + kb + b_koff;
                uint32_t t[4];
                ldsm4(t, bd + 2 * TILEB);
                bfh[np * 2][0] = t[0]; bfh[np * 2][1] = t[1];
                bfh[np * 2 + 1][0] = t[2]; bfh[np * 2 + 1][1] = t[3];
                ldsm4(t, bd + 3 * TILEB);
                bfl[np * 2][0] = t[0]; bfl[np * 2][1] = t[1];
                bfl[np * 2 + 1][0] = t[2]; bfl[np * 2 + 1][1] = t[3];
            }
            #pragma unroll
            for (int mt = 0; mt < 4; mt++)
                #pragma unroll
                for (int nt = 0; nt < 4; nt++) {
                    mma_bf16(c[mt][nt], afh[mt], bfh[nt]);
                    mma_bf16(c[mt][nt], afh[mt], bfl[nt]);
                    mma_bf16(c[mt][nt], afl[mt], bfh[nt]);
                }
        }
        __syncthreads();
    }
    #undef ISSUE

    #pragma unroll
    for (int mt = 0; mt < 4; mt++) {
        const int row = m0 + wm * 64 + mt * 16 + (lane >> 2);
        #pragma unroll
        for (int nt = 0; nt < 4; nt++) {
            const int col = n0 + wn * 32 + nt * 8 + (lane & 3) * 2;
            epi_store<EPI>(row,     col, c[mt][nt][0], c[mt][nt][1],
                           Cf, O1, O2, O3, O4, ldc);
            epi_store<EPI>(row + 8, col, c[mt][nt][2], c[mt][nt][3],
                           Cf, O1, O2, O3, O4, ldc);
        }
    }
}

// ---------------------------------------------------------------------------
// HMMA flash attention (causal), split precision (unchanged from R4)
// ---------------------------------------------------------------------------
#define APITCH 272
#define KTILEB (64 * APITCH)
#define ATTN_SMEM (2 * 128 * APITCH)

__global__ __launch_bounds__(256)
void attn_hmma(const __nv_bfloat16* __restrict__ qhi, const __nv_bfloat16* __restrict__ qlo,
               const __nv_bfloat16* __restrict__ kvhi, const __nv_bfloat16* __restrict__ kvlo,
               const __nv_bfloat16* __restrict__ krhi, const __nv_bfloat16* __restrict__ krlo,
               __nv_bfloat16* __restrict__ yhi, __nv_bfloat16* __restrict__ ylo)
{
    extern __shared__ char sma[];
    const uint32_t sb = smem_u32(sma);
    const int tid = threadIdx.x;
    const int lane = tid & 31, warp = tid >> 5;
    const int qt = blockIdx.x, h = blockIdx.y, b = blockIdx.z;
    const int q0 = qt * 128;
    const int bq0 = b * T_ + q0;
    const float scale = 0.08838834764831845f;

    #pragma unroll
    for (int t = 0; t < 2; t++) {
        const __nv_bfloat16* src = t ? qlo : qhi;
        #pragma unroll
        for (int i = 0; i < 8; i++) {
            const int idx = i * 256 + tid;
            const int r = idx >> 4, gc = idx & 15;
            *(float4*)(sma + t * (128 * APITCH) + r * APITCH + gc * 16) =
                *(const float4*)(src + (size_t)(bq0 + r) * 2048 + h * 128 + gc * 8);
        }
    }
    __syncthreads();

    uint32_t qh[8][4], ql[8][4];
    {
        const uint32_t a_base = sb + (warp * 16 + (lane & 15)) * APITCH + (lane >> 4) * 16;
        #pragma unroll
        for (int kt = 0; kt < 8; kt++) {
            ldsm4(qh[kt], a_base + kt * 32);
            ldsm4(ql[kt], a_base + kt * 32 + 128 * APITCH);
        }
    }
    __syncthreads();

    float m_i[2] = {-1e30f, -1e30f};
    float l_i[2] = {0.f, 0.f};
    float o[8][4];
    #pragma unroll
    for (int j = 0; j < 8; j++)
        #pragma unroll
        for (int e = 0; e < 4; e++) o[j][e] = 0.f;

    const int g = lane >> 2, cq = lane & 3;
    const int rbase = q0 + warp * 16 + g;

    const int nk = 2 * qt + 2;
    for (int c = 0; c < nk; c++) {
        const int bk0 = b * T_ + c * 64;
        __syncthreads();
        #pragma unroll
        for (int t = 0; t < 2; t++) {
            const __nv_bfloat16* vsrc = t ? kvlo : kvhi;
            const __nv_bfloat16* rsrc = t ? krlo : krhi;
            #pragma unroll
            for (int i = 0; i < 4; i++) {
                const int idx = i * 256 + tid;
                const int s = idx >> 4, gc = idx & 15;
                float4 v;
                if (gc < 8)
                    v = *(const float4*)(vsrc + (size_t)(bk0 + s) * 1024 + h * 64 + gc * 8);
                else
                    v = *(const float4*)(rsrc + (size_t)(bk0 + s) * 64 + (gc - 8) * 8);
                *(float4*)(sma + t * KTILEB + s * APITCH + gc * 16) = v;
            }
        }
        __syncthreads();

        float cS[8][4];
        #pragma unroll
        for (int j = 0; j < 8; j++)
            #pragma unroll
            for (int e = 0; e < 4; e++) cS[j][e] = 0.f;

        const uint32_t b_base = sb + (((lane >> 4) << 3) + (lane & 7)) * APITCH
                              + ((lane >> 3) & 1) * 16;
        #pragma unroll
        for (int kt = 0; kt < 8; kt++) {
            #pragma unroll
            for (int np = 0; np < 4; np++) {
                uint32_t th[4], tl[4];
                const uint32_t bd = b_base + np * 16 * APITCH + kt * 32;
                ldsm4(th, bd);
                ldsm4(tl, bd + KTILEB);
                const int j0 = 2 * np;
                mma_bf16s(cS[j0],     qh[kt], th[0], th[1]);
                mma_bf16s(cS[j0],     qh[kt], tl[0], tl[1]);
                mma_bf16s(cS[j0],     ql[kt], th[0], th[1]);
                mma_bf16s(cS[j0 + 1], qh[kt], th[2], th[3]);
                mma_bf16s(cS[j0 + 1], qh[kt], tl[2], tl[3]);
                mma_bf16s(cS[j0 + 1], ql[kt], th[2], th[3]);
            }
        }

        const int cbase = c * 64 + cq * 2;
        #pragma unroll
        for (int j = 0; j < 8; j++) {
            const int col = cbase + j * 8;
            cS[j][0] = (col     <= rbase)     ? cS[j][0] * scale : -3e30f;
            cS[j][1] = (col + 1 <= rbase)     ? cS[j][1] * scale : -3e30f;
            cS[j][2] = (col     <= rbase + 8) ? cS[j][2] * scale : -3e30f;
            cS[j][3] = (col + 1 <= rbase + 8) ? cS[j][3] * scale : -3e30f;
        }

        float mx0 = -3e30f, mx1 = -3e30f;
        #pragma unroll
        for (int j = 0; j < 8; j++) {
            mx0 = fmaxf(mx0, fmaxf(cS[j][0], cS[j][1]));
            mx1 = fmaxf(mx1, fmaxf(cS[j][2], cS[j][3]));
        }
        mx0 = fmaxf(mx0, __shfl_xor_sync(0xffffffffu, mx0, 1));
        mx0 = fmaxf(mx0, __shfl_xor_sync(0xffffffffu, mx0, 2));
        mx1 = fmaxf(mx1, __shfl_xor_sync(0xffffffffu, mx1, 1));
        mx1 = fmaxf(mx1, __shfl_xor_sync(0xffffffffu, mx1, 2));
        const float nm0 = fmaxf(m_i[0], mx0);
        const float nm1 = fmaxf(m_i[1], mx1);
        const float f0 = __expf(m_i[0] - nm0);
        const float f1 = __expf(m_i[1] - nm1);
        float s0 = 0.f, s1 = 0.f;
        #pragma unroll
        for (int j = 0; j < 8; j++) {
            cS[j][0] = __expf(cS[j][0] - nm0);
            cS[j][1] = __expf(cS[j][1] - nm0);
            cS[j][2] = __expf(cS[j][2] - nm1);
            cS[j][3] = __expf(cS[j][3] - nm1);
            s0 += cS[j][0] + cS[j][1];
            s1 += cS[j][2] + cS[j][3];
        }
        s0 += __shfl_xor_sync(0xffffffffu, s0, 1);
        s0 += __shfl_xor_sync(0xffffffffu, s0, 2);
        s1 += __shfl_xor_sync(0xffffffffu, s1, 1);
        s1 += __shfl_xor_sync(0xffffffffu, s1, 2);
        l_i[0] = l_i[0] * f0 + s0;  m_i[0] = nm0;
        l_i[1] = l_i[1] * f1 + s1;  m_i[1] = nm1;
        #pragma unroll
        for (int j = 0; j < 8; j++) {
            o[j][0] *= f0; o[j][1] *= f0;
            o[j][2] *= f1; o[j][3] *= f1;
        }

        const uint32_t v_row = ((lane & 7) + 8 * ((lane >> 3) & 1)) * APITCH
                             + (lane >> 4) * 16;
        #pragma unroll
        for (int ks = 0; ks < 4; ks++) {
            uint32_t ah[4], al[4];
            packsplit(cS[2 * ks][0],     cS[2 * ks][1],     ah[0], al[0]);
            packsplit(cS[2 * ks][2],     cS[2 * ks][3],     ah[1], al[1]);
            packsplit(cS[2 * ks + 1][0], cS[2 * ks + 1][1], ah[2], al[2]);
            packsplit(cS[2 * ks + 1][2], cS[2 * ks + 1][3], ah[3], al[3]);
            #pragma unroll
            for (int np = 0; np < 4; np++) {
                uint32_t th[4], tl[4];
                const uint32_t vd = sb + v_row + ks * 16 * APITCH + np * 32;
                ldsm4t(th, vd);
                ldsm4t(tl, vd + KTILEB);
                const int jd = 2 * np;
                mma_bf16s(o[jd],     ah, th[0], th[1]);
                mma_bf16s(o[jd],     ah, tl[0], tl[1]);
                mma_bf16s(o[jd],     al, th[0], th[1]);
                mma_bf16s(o[jd + 1], ah, th[2], th[3]);
                mma_bf16s(o[jd + 1], ah, tl[2], tl[3]);
                mma_bf16s(o[jd + 1], al, th[2], th[3]);
            }
        }
    }

    const float inv0 = 1.f / l_i[0];
    const float inv1 = 1.f / l_i[1];
    const size_t row0 = (size_t)(bq0 + warp * 16 + g);
    const size_t row1 = row0 + 8;
    #pragma unroll
    for (int j = 0; j < 8; j++) {
        const int col = h * 64 + j * 8 + cq * 2;
        uint32_t hi, lo;
        packsplit(o[j][0] * inv0, o[j][1] * inv0, hi, lo);
        *(uint32_t*)&yhi[row0 * 1024 + col] = hi;
        *(uint32_t*)&ylo[row0 * 1024 + col] = lo;
        packsplit(o[j][2] * inv1, o[j][3] * inv1, hi, lo);
        *(uint32_t*)&yhi[row1 * 1024 + col] = hi;
        *(uint32_t*)&ylo[row1 * 1024 + col] = lo;
    }
}

// ---------------------------------------------------------------------------
// Launch
// ---------------------------------------------------------------------------
extern "C" void kernel_launch(void* const* d_in, const int* in_sizes, int n_in,
                              void* d_out, int out_size)
{
    const float* x    = (const float*)d_in[0];
    const float* Wq   = (const float*)d_in[1];
    const float* Wkva = (const float*)d_in[2];
    const float* Wkvb = (const float*)d_in[3];
    const float* Wo   = (const float*)d_in[4];
    float* out = (float*)d_out;

    __nv_bfloat16 *xhi, *xlo, *qhi, *qlo, *ckvhi, *ckvlo;
    __nv_bfloat16 *kvhi, *kvlo, *krhi, *krlo, *yhi, *ylo;
    __nv_bfloat16 *wqh, *wql, *wah, *wal, *wbh, *wbl, *woh, *wol;
    cudaGetSymbolAddress((void**)&xhi, g_xhi);     cudaGetSymbolAddress((void**)&xlo, g_xlo);
    cudaGetSymbolAddress((void**)&qhi, g_qhi);     cudaGetSymbolAddress((void**)&qlo, g_qlo);
    cudaGetSymbolAddress((void**)&ckvhi, g_ckvhi); cudaGetSymbolAddress((void**)&ckvlo, g_ckvlo);
    cudaGetSymbolAddress((void**)&kvhi, g_kvhi);   cudaGetSymbolAddress((void**)&kvlo, g_kvlo);
    cudaGetSymbolAddress((void**)&krhi, g_krhi);   cudaGetSymbolAddress((void**)&krlo, g_krlo);
    cudaGetSymbolAddress((void**)&yhi, g_yhi);     cudaGetSymbolAddress((void**)&ylo, g_ylo);
    cudaGetSymbolAddress((void**)&wqh, g_wqt_hi);  cudaGetSymbolAddress((void**)&wql, g_wqt_lo);
    cudaGetSymbolAddress((void**)&wah, g_wkvat_hi); cudaGetSymbolAddress((void**)&wal, g_wkvat_lo);
    cudaGetSymbolAddress((void**)&wbh, g_wkvbt_hi); cudaGetSymbolAddress((void**)&wbl, g_wkvbt_lo);
    cudaGetSymbolAddress((void**)&woh, g_wot_hi);  cudaGetSymbolAddress((void**)&wol, g_wot_lo);

    cudaFuncSetAttribute(hmma_gemm<EPI_F32>,
                         cudaFuncAttributeMaxDynamicSharedMemorySize, GEMM_SMEM);
    cudaFuncSetAttribute(hmma_gemm<EPI_SPLIT>,
                         cudaFuncAttributeMaxDynamicSharedMemorySize, GEMM_SMEM);
    cudaFuncSetAttribute(hmma_gemm<EPI_Q>,
                         cudaFuncAttributeMaxDynamicSharedMemorySize, GEMM_SMEM);
    cudaFuncSetAttribute(hmma_gemm<EPI_CKV>,
                         cudaFuncAttributeMaxDynamicSharedMemorySize, GEMM_SMEM);
    cudaFuncSetAttribute(attn_hmma,
                         cudaFuncAttributeMaxDynamicSharedMemorySize, ATTN_SMEM);

    freq_init_kernel<<<1, 32>>>();

    const dim3 tb(32, 8);
    splitT_kernel<false><<<dim3(64, 64), tb>>>(Wq,   2048, 2048, wqh, wql, 2048);
    splitT_kernel<false><<<dim3(64, 20), tb>>>(Wkva,  576,  576, wah, wal, 2048);
    splitT_kernel<false><<<dim3(16, 32), tb>>>(Wkvb, 1024, 1024, wbh, wbl,  512);
    splitT_kernel<true ><<<dim3(32, 64), tb>>>(Wo,   2048, 2048, woh, wol, 1024);
    split_kernel<<<8192, 256>>>(x, 2048, xhi, xlo, 4096, 2048);

    // q = rope(x @ Wq) -> qhi/qlo  (fused epilogue)
    hmma_gemm<EPI_Q><<<dim3(16, 32), 256, GEMM_SMEM>>>(
        xhi, xlo, wqh, wql, nullptr, qhi, qlo, nullptr, nullptr,
        2048, 2048, 2048, 0);
    // ckv = x @ Wkva -> ckvhi/ckvlo (cols<512) + roped krhi/krlo (rope cols)
    hmma_gemm<EPI_CKV><<<dim3(5, 32), 256, GEMM_SMEM>>>(
        xhi, xlo, wah, wal, nullptr, ckvhi, ckvlo, krhi, krlo,
        2048, 2048, 2048, 0);
    // kv = latent @ Wkvb -> kvhi/kvlo
    hmma_gemm<EPI_SPLIT><<<dim3(8, 32), 256, GEMM_SMEM>>>(
        ckvhi, ckvlo, wbh, wbl, nullptr, kvhi, kvlo, nullptr, nullptr,
        512, 512, 512, 1024);
    // attention -> yhi/ylo
    attn_hmma<<<dim3(16, 16, 2), 256, ATTN_SMEM>>>(qhi, qlo, kvhi, kvlo,
                                                   krhi, krlo, yhi, ylo);
    // out = y @ gather(Wo)
    hmma_gemm<EPI_F32><<<dim3(16, 32), 256, GEMM_SMEM>>>(
        yhi, ylo, woh, wol, out, nullptr, nullptr, nullptr, nullptr,
        1024, 1024, 1024, 2048);
}

// round 8
// speedup vs baseline: 2.9999x; 1.0198x over previous
#include <cuda_runtime.h>
#include <cuda_bf16.h>
#include <math.h>
#include <stdint.h>

// Problem constants
#define B_    2
#define T_    2048
#define C_    2048
#define H_    16
#define HD_   128
#define LORA_ 512
#define RD_   64
#define ND_   64
#define BT_   (B_ * T_)   // 4096

// ---------------------------------------------------------------------------
// Scratch (static __device__ globals — allocation-free per harness rules)
// ---------------------------------------------------------------------------
__device__ float g_freq[32];

__device__ __align__(16) __nv_bfloat16 g_xhi[(size_t)BT_ * 2048],  g_xlo[(size_t)BT_ * 2048];
__device__ __align__(16) __nv_bfloat16 g_qhi[(size_t)BT_ * 2048],  g_qlo[(size_t)BT_ * 2048];
__device__ __align__(16) __nv_bfloat16 g_ckvhi[(size_t)BT_ * 512], g_ckvlo[(size_t)BT_ * 512];
__device__ __align__(16) __nv_bfloat16 g_kvhi[(size_t)BT_ * 1024], g_kvlo[(size_t)BT_ * 1024];
__device__ __align__(16) __nv_bfloat16 g_krhi[(size_t)BT_ * 64],   g_krlo[(size_t)BT_ * 64];
__device__ __align__(16) __nv_bfloat16 g_yhi[(size_t)BT_ * 1024],  g_ylo[(size_t)BT_ * 1024];
__device__ __align__(16) __nv_bfloat16 g_wqt_hi[(size_t)2048 * 2048], g_wqt_lo[(size_t)2048 * 2048];
__device__ __align__(16) __nv_bfloat16 g_wkvat_hi[(size_t)640 * 2048], g_wkvat_lo[(size_t)640 * 2048];
__device__ __align__(16) __nv_bfloat16 g_wkvbt_hi[(size_t)1024 * 512], g_wkvbt_lo[(size_t)1024 * 512];
__device__ __align__(16) __nv_bfloat16 g_wot_hi[(size_t)2048 * 1024], g_wot_lo[(size_t)2048 * 1024];

// ---------------------------------------------------------------------------
// RoPE frequency table (exact formula as reference; computed once per launch)
// ---------------------------------------------------------------------------
__global__ void freq_init_kernel() {
    const int i = threadIdx.x;
    if (i < 32) g_freq[i] = (float)pow(100000.0, -(double)i / 32.0);
}

// ---------------------------------------------------------------------------
// fp32 -> bf16 hi/lo split (for x)
// ---------------------------------------------------------------------------
__global__ void split_kernel(const float* __restrict__ in, int ld_in,
                             __nv_bfloat16* __restrict__ hi,
                             __nv_bfloat16* __restrict__ lo,
                             int rows, int width)
{
    const int idx = blockIdx.x * blockDim.x + threadIdx.x;
    const int w4 = width >> 2;
    if (idx >= rows * w4) return;
    const int r = idx / w4, c4 = idx - r * w4;
    const float4 v = *(const float4*)&in[(size_t)r * ld_in + c4 * 4];
    float f[4] = {v.x, v.y, v.z, v.w};
    ushort4 hv, lv;
    unsigned short* hp = &hv.x;
    unsigned short* lp = &lv.x;
    #pragma unroll
    for (int i = 0; i < 4; i++) {
        __nv_bfloat16 h = __float2bfloat16(f[i]);
        __nv_bfloat16 l = __float2bfloat16(f[i] - __bfloat162float(h));
        hp[i] = __bfloat16_as_ushort(h);
        lp[i] = __bfloat16_as_ushort(l);
    }
    *(ushort4*)&hi[(size_t)r * width + c4 * 4] = hv;
    *(ushort4*)&lo[(size_t)r * width + c4 * 4] = lv;
}

// ---------------------------------------------------------------------------
// fp32 W[k][n] -> bf16 hi/lo out[n][k] (transpose + optional gather + pad)
// ---------------------------------------------------------------------------
template <bool GATHER>
__global__ void splitT_kernel(const float* __restrict__ W, int ldw, int nIn,
                              __nv_bfloat16* __restrict__ hi,
                              __nv_bfloat16* __restrict__ lo, int kDim)
{
    __shared__ float tile[32][33];
    const int k0 = blockIdx.x * 32, n0 = blockIdx.y * 32;
    #pragma unroll
    for (int i = threadIdx.y; i < 32; i += 8) {
        const int k = k0 + i;
        const int row = GATHER ? (((k >> 6) << 7) + (k & 63)) : k;
        const int n = n0 + threadIdx.x;
        tile[i][threadIdx.x] = (n < nIn) ? W[(size_t)row * ldw + n] : 0.f;
    }
    __syncthreads();
    #pragma unroll
    for (int i = threadIdx.y; i < 32; i += 8) {
        const int n = n0 + i, k = k0 + threadIdx.x;
        const float v = tile[threadIdx.x][i];
        const __nv_bfloat16 h = __float2bfloat16(v);
        hi[(size_t)n * kDim + k] = h;
        lo[(size_t)n * kDim + k] = __float2bfloat16(v - __bfloat162float(h));
    }
}

// ---------------------------------------------------------------------------
// Shared HMMA helpers
// ---------------------------------------------------------------------------
__device__ __forceinline__ uint32_t smem_u32(const void* p) {
    uint32_t a;
    asm("{ .reg .u64 t; cvta.to.shared.u64 t, %1; cvt.u32.u64 %0, t; }"
        : "=r"(a) : "l"(p));
    return a;
}
__device__ __forceinline__ void cp16(uint32_t dst, const void* src) {
    asm volatile("cp.async.cg.shared.global [%0], [%1], 16;"
                 :: "r"(dst), "l"(src) : "memory");
}
__device__ __forceinline__ void cp_commit() {
    asm volatile("cp.async.commit_group;" ::: "memory");
}
__device__ __forceinline__ void cp_wait0() {
    asm volatile("cp.async.wait_group 0;" ::: "memory");
}
__device__ __forceinline__ void ldsm4(uint32_t r[4], uint32_t addr) {
    asm volatile("ldmatrix.sync.aligned.m8n8.x4.shared.b16 {%0,%1,%2,%3}, [%4];"
                 : "=r"(r[0]), "=r"(r[1]), "=r"(r[2]), "=r"(r[3]) : "r"(addr));
}
__device__ __forceinline__ void ldsm4t(uint32_t r[4], uint32_t addr) {
    asm volatile("ldmatrix.sync.aligned.m8n8.x4.trans.shared.b16 {%0,%1,%2,%3}, [%4];"
                 : "=r"(r[0]), "=r"(r[1]), "=r"(r[2]), "=r"(r[3]) : "r"(addr));
}
__device__ __forceinline__ void mma_bf16(float c[4], const uint32_t a[4],
                                         const uint32_t b[2]) {
    asm volatile(
        "mma.sync.aligned.m16n8k16.row.col.f32.bf16.bf16.f32 "
        "{%0,%1,%2,%3}, {%4,%5,%6,%7}, {%8,%9}, {%0,%1,%2,%3};"
        : "+f"(c[0]), "+f"(c[1]), "+f"(c[2]), "+f"(c[3])
        : "r"(a[0]), "r"(a[1]), "r"(a[2]), "r"(a[3]), "r"(b[0]), "r"(b[1]));
}
__device__ __forceinline__ void mma_bf16s(float c[4], const uint32_t a[4],
                                          uint32_t b0, uint32_t b1) {
    asm volatile(
        "mma.sync.aligned.m16n8k16.row.col.f32.bf16.bf16.f32 "
        "{%0,%1,%2,%3}, {%4,%5,%6,%7}, {%8,%9}, {%0,%1,%2,%3};"
        : "+f"(c[0]), "+f"(c[1]), "+f"(c[2]), "+f"(c[3])
        : "r"(a[0]), "r"(a[1]), "r"(a[2]), "r"(a[3]), "r"(b0), "r"(b1));
}
__device__ __forceinline__ void packsplit(float c0, float c1,
                                          uint32_t& hi, uint32_t& lo) {
    __nv_bfloat16 h0 = __float2bfloat16(c0);
    __nv_bfloat16 h1 = __float2bfloat16(c1);
    __nv_bfloat16 l0 = __float2bfloat16(c0 - __bfloat162float(h0));
    __nv_bfloat16 l1 = __float2bfloat16(c1 - __bfloat162float(h1));
    hi = ((uint32_t)__bfloat16_as_ushort(h1) << 16) | __bfloat16_as_ushort(h0);
    lo = ((uint32_t)__bfloat16_as_ushort(l1) << 16) | __bfloat16_as_ushort(l0);
}

// ---------------------------------------------------------------------------
// Epilogue modes
// ---------------------------------------------------------------------------
#define EPI_F32   0
#define EPI_SPLIT 1
#define EPI_Q     2
#define EPI_CKV   3

template <int EPI>
__device__ __forceinline__ void epi_store(int row, int col, float v0, float v1,
    float* __restrict__ Cf,
    __nv_bfloat16* __restrict__ O1, __nv_bfloat16* __restrict__ O2,
    __nv_bfloat16* __restrict__ O3, __nv_bfloat16* __restrict__ O4, int ldc)
{
    if (EPI == EPI_F32) {
        *(float2*)&Cf[(size_t)row * ldc + col] = make_float2(v0, v1);
    } else if (EPI == EPI_SPLIT) {
        uint32_t h, l;
        packsplit(v0, v1, h, l);
        *(uint32_t*)&O1[(size_t)row * ldc + col] = h;
        *(uint32_t*)&O2[(size_t)row * ldc + col] = l;
    } else if (EPI == EPI_Q) {
        const int d = col & 127;
        if (d >= 64) {
            const float freq = g_freq[(d - 64) >> 1];
            float s, c;
            sincosf((float)(row & (T_ - 1)) * freq, &s, &c);
            const float t0 = v0 * c - v1 * s;
            const float t1 = v0 * s + v1 * c;
            v0 = t0; v1 = t1;
        }
        uint32_t h, l;
        packsplit(v0, v1, h, l);
        *(uint32_t*)&O1[(size_t)row * 2048 + col] = h;
        *(uint32_t*)&O2[(size_t)row * 2048 + col] = l;
    } else {  // EPI_CKV
        if (col < 512) {
            uint32_t h, l;
            packsplit(v0, v1, h, l);
            *(uint32_t*)&O1[(size_t)row * 512 + col] = h;
            *(uint32_t*)&O2[(size_t)row * 512 + col] = l;
        } else if (col < 576) {
            const float freq = g_freq[(col - 512) >> 1];
            float s, c;
            sincosf((float)(row & (T_ - 1)) * freq, &s, &c);
            uint32_t h, l;
            packsplit(v0 * c - v1 * s, v0 * s + v1 * c, h, l);
            *(uint32_t*)&O3[(size_t)row * 64 + (col - 512)] = h;
            *(uint32_t*)&O4[(size_t)row * 64 + (col - 512)] = l;
        }
    }
}

// ---------------------------------------------------------------------------
// HMMA split-precision GEMM, cp.async double-buffered, ONE barrier per K-iter.
// ---------------------------------------------------------------------------
#define ROWB   80
#define TILEB  (128 * ROWB)     // 10240
#define STAGEB (4 * TILEB)      // 40960
#define GEMM_SMEM (2 * STAGEB)  // 81920

template <int EPI>
__global__ __launch_bounds__(256)
void hmma_gemm(const __nv_bfloat16* __restrict__ Ahi, const __nv_bfloat16* __restrict__ Alo,
               const __nv_bfloat16* __restrict__ Bhi, const __nv_bfloat16* __restrict__ Blo,
               float* __restrict__ Cf,
               __nv_bfloat16* __restrict__ O1, __nv_bfloat16* __restrict__ O2,
               __nv_bfloat16* __restrict__ O3, __nv_bfloat16* __restrict__ O4,
               int K, int lda, int ldb, int ldc)
{
    extern __shared__ char smc[];
    const uint32_t sb = smem_u32(smc);
    const int tid = threadIdx.x;
    const int lane = tid & 31, warp = tid >> 5;
    const int wm = warp >> 2, wn = warp & 3;
    const int m0 = blockIdx.y * 128, n0 = blockIdx.x * 128;

    const int r_ld = tid >> 2;
    const int cc = tid & 3;
    const __nv_bfloat16* pAh0 = Ahi + (size_t)(m0 + r_ld) * lda + cc * 8;
    const __nv_bfloat16* pAh1 = Ahi + (size_t)(m0 + r_ld + 64) * lda + cc * 8;
    const __nv_bfloat16* pAl0 = Alo + (size_t)(m0 + r_ld) * lda + cc * 8;
    const __nv_bfloat16* pAl1 = Alo + (size_t)(m0 + r_ld + 64) * lda + cc * 8;
    const __nv_bfloat16* pBh0 = Bhi + (size_t)(n0 + r_ld) * ldb + cc * 8;
    const __nv_bfloat16* pBh1 = Bhi + (size_t)(n0 + r_ld + 64) * ldb + cc * 8;
    const __nv_bfloat16* pBl0 = Blo + (size_t)(n0 + r_ld) * ldb + cc * 8;
    const __nv_bfloat16* pBl1 = Blo + (size_t)(n0 + r_ld + 64) * ldb + cc * 8;
    const uint32_t d0 = r_ld * ROWB + cc * 16;
    const uint32_t d1 = (r_ld + 64) * ROWB + cc * 16;

    #define ISSUE(st, k0_) do {                                               \
        const uint32_t bb = sb + (uint32_t)(st) * STAGEB;                     \
        cp16(bb + 0 * TILEB + d0, pAh0 + (k0_));                              \
        cp16(bb + 0 * TILEB + d1, pAh1 + (k0_));                              \
        cp16(bb + 1 * TILEB + d0, pAl0 + (k0_));                              \
        cp16(bb + 1 * TILEB + d1, pAl1 + (k0_));                              \
        cp16(bb + 2 * TILEB + d0, pBh0 + (k0_));                              \
        cp16(bb + 2 * TILEB + d1, pBh1 + (k0_));                              \
        cp16(bb + 3 * TILEB + d0, pBl0 + (k0_));                              \
        cp16(bb + 3 * TILEB + d1, pBl1 + (k0_));                              \
        cp_commit();                                                          \
    } while (0)

    float c[4][4][4];
    #pragma unroll
    for (int i = 0; i < 4; i++)
        #pragma unroll
        for (int j = 0; j < 4; j++)
            #pragma unroll
            for (int l = 0; l < 4; l++) c[i][j][l] = 0.f;

    const uint32_t a_row = wm * 64 + (lane & 15);
    const uint32_t a_koff = (lane >> 4) * 16;
    const uint32_t b_row = wn * 32 + ((lane >> 4) << 3) + (lane & 7);
    const uint32_t b_koff = ((lane >> 3) & 1) * 16;

    const int niter = K >> 5;
    ISSUE(0, 0);

    for (int it = 0; it < niter; it++) {
        cp_wait0();
        __syncthreads();
        // Safe: the barrier above proves every thread finished compute(it-1),
        // so overwriting stage (it+1)&1 (used by iter it-1) is race-free.
        if (it + 1 < niter) ISSUE((it + 1) & 1, (it + 1) << 5);

        const uint32_t buf = sb + (uint32_t)(it & 1) * STAGEB;
        #pragma unroll
        for (int ks = 0; ks < 2; ks++) {
            const uint32_t kb = ks * 32;
            uint32_t afh[4][4], afl[4][4], bfh[4][2], bfl[4][2];
            #pragma unroll
            for (int mt = 0; mt < 4; mt++) {
                const uint32_t ad = buf + (a_row + mt * 16) * ROWB + kb + a_koff;
                ldsm4(afh[mt], ad + 0 * TILEB);
                ldsm4(afl[mt], ad + 1 * TILEB);
            }
            #pragma unroll
            for (int np = 0; np < 2; np++) {
                const uint32_t bd = buf + (b_row + np * 16) * ROWB + kb + b_koff;
                uint32_t t[4];
                ldsm4(t, bd + 2 * TILEB);
                bfh[np * 2][0] = t[0]; bfh[np * 2][1] = t[1];
                bfh[np * 2 + 1][0] = t[2]; bfh[np * 2 + 1][1] = t[3];
                ldsm4(t, bd + 3 * TILEB);
                bfl[np * 2][0] = t[0]; bfl[np * 2][1] = t[1];
                bfl[np * 2 + 1][0] = t[2]; bfl[np * 2 + 1][1] = t[3];
            }
            #pragma unroll
            for (int mt = 0; mt < 4; mt++)
                #pragma unroll
                for (int nt = 0; nt < 4; nt++) {
                    mma_bf16(c[mt][nt], afh[mt], bfh[nt]);
                    mma_bf16(c[mt][nt], afh[mt], bfl[nt]);
                    mma_bf16(c[mt][nt], afl[mt], bfh[nt]);
                }
        }
    }
    #undef ISSUE

    #pragma unroll
    for (int mt = 0; mt < 4; mt++) {
        const int row = m0 + wm * 64 + mt * 16 + (lane >> 2);
        #pragma unroll
        for (int nt = 0; nt < 4; nt++) {
            const int col = n0 + wn * 32 + nt * 8 + (lane & 3) * 2;
            epi_store<EPI>(row,     col, c[mt][nt][0], c[mt][nt][1],
                           Cf, O1, O2, O3, O4, ldc);
            epi_store<EPI>(row + 8, col, c[mt][nt][2], c[mt][nt][3],
                           Cf, O1, O2, O3, O4, ldc);
        }
    }
}

// ---------------------------------------------------------------------------
// HMMA flash attention (causal), split precision.
// K tiles double-buffered via cp.async in the (reused) Q-staging smem.
// ---------------------------------------------------------------------------
#define APITCH 272
#define KTILEB (64 * APITCH)                 // 17408  (one hi or lo tile)
#define KSTAGE (2 * KTILEB)                  // 34816  (hi+lo)
#define ATTN_SMEM (2 * KSTAGE)               // 69632  (= Q staging hi+lo)

__global__ __launch_bounds__(256)
void attn_hmma(const __nv_bfloat16* __restrict__ qhi, const __nv_bfloat16* __restrict__ qlo,
               const __nv_bfloat16* __restrict__ kvhi, const __nv_bfloat16* __restrict__ kvlo,
               const __nv_bfloat16* __restrict__ krhi, const __nv_bfloat16* __restrict__ krlo,
               __nv_bfloat16* __restrict__ yhi, __nv_bfloat16* __restrict__ ylo)
{
    extern __shared__ char sma[];
    const uint32_t sb = smem_u32(sma);
    const int tid = threadIdx.x;
    const int lane = tid & 31, warp = tid >> 5;
    const int qt = blockIdx.x, h = blockIdx.y, b = blockIdx.z;
    const int q0 = qt * 128;
    const int bq0 = b * T_ + q0;
    const float scale = 0.08838834764831845f;

    // ---- stage Q (hi, lo) and pull fragments into registers ----
    #pragma unroll
    for (int t = 0; t < 2; t++) {
        const __nv_bfloat16* src = t ? qlo : qhi;
        #pragma unroll
        for (int i = 0; i < 8; i++) {
            const int idx = i * 256 + tid;
            const int r = idx >> 4, gc = idx & 15;
            *(float4*)(sma + t * (128 * APITCH) + r * APITCH + gc * 16) =
                *(const float4*)(src + (size_t)(bq0 + r) * 2048 + h * 128 + gc * 8);
        }
    }
    __syncthreads();

    uint32_t qh[8][4], ql[8][4];
    {
        const uint32_t a_base = sb + (warp * 16 + (lane & 15)) * APITCH + (lane >> 4) * 16;
        #pragma unroll
        for (int kt = 0; kt < 8; kt++) {
            ldsm4(qh[kt], a_base + kt * 32);
            ldsm4(ql[kt], a_base + kt * 32 + 128 * APITCH);
        }
    }
    __syncthreads();    // smem now free for the K-tile ring

    // per-thread cp.async mapping for one K tile (s = key row, gc = 16B chunk)
    const int s_ld = tid >> 4;               // base key row (0..15), step 16
    const int gc_ld = tid & 15;              // 16B chunk in 256B row
    const int hoff = h * 64 + (gc_ld & 7) * 8;
    const int roff = (gc_ld - 8) * 8;

    #define KISSUE(st, bk0_) do {                                             \
        const uint32_t bb = sb + (uint32_t)(st) * KSTAGE;                     \
        _Pragma("unroll")                                                     \
        for (int t = 0; t < 2; t++) {                                         \
            const __nv_bfloat16* vsrc = t ? kvlo : kvhi;                      \
            const __nv_bfloat16* rsrc = t ? krlo : krhi;                      \
            _Pragma("unroll")                                                 \
            for (int i = 0; i < 4; i++) {                                     \
                const int s = s_ld + i * 16;                                  \
                const void* src = (gc_ld < 8)                                 \
                    ? (const void*)(vsrc + (size_t)((bk0_) + s) * 1024 + hoff)\
                    : (const void*)(rsrc + (size_t)((bk0_) + s) * 64 + roff); \
                cp16(bb + t * KTILEB + s * APITCH + gc_ld * 16, src);         \
            }                                                                 \
        }                                                                     \
        cp_commit();                                                          \
    } while (0)

    float m_i[2] = {-1e30f, -1e30f};
    float l_i[2] = {0.f, 0.f};
    float o[8][4];
    #pragma unroll
    for (int j = 0; j < 8; j++)
        #pragma unroll
        for (int e = 0; e < 4; e++) o[j][e] = 0.f;

    const int g = lane >> 2, cq = lane & 3;
    const int rbase = q0 + warp * 16 + g;

    const int nk = 2 * qt + 2;
    KISSUE(0, b * T_);

    for (int c = 0; c < nk; c++) {
        cp_wait0();
        __syncthreads();
        // Barrier proves compute(c-1) done -> stage (c+1)&1 reusable.
        if (c + 1 < nk) KISSUE((c + 1) & 1, b * T_ + (c + 1) * 64);

        const uint32_t kbuf = sb + (uint32_t)(c & 1) * KSTAGE;

        // ---- S = Q K^T ----
        float cS[8][4];
        #pragma unroll
        for (int j = 0; j < 8; j++)
            #pragma unroll
            for (int e = 0; e < 4; e++) cS[j][e] = 0.f;

        const uint32_t b_base = kbuf + (((lane >> 4) << 3) + (lane & 7)) * APITCH
                              + ((lane >> 3) & 1) * 16;
        #pragma unroll
        for (int kt = 0; kt < 8; kt++) {
            #pragma unroll
            for (int np = 0; np < 4; np++) {
                uint32_t th[4], tl[4];
                const uint32_t bd = b_base + np * 16 * APITCH + kt * 32;
                ldsm4(th, bd);
                ldsm4(tl, bd + KTILEB);
                const int j0 = 2 * np;
                mma_bf16s(cS[j0],     qh[kt], th[0], th[1]);
                mma_bf16s(cS[j0],     qh[kt], tl[0], tl[1]);
                mma_bf16s(cS[j0],     ql[kt], th[0], th[1]);
                mma_bf16s(cS[j0 + 1], qh[kt], th[2], th[3]);
                mma_bf16s(cS[j0 + 1], qh[kt], tl[2], tl[3]);
                mma_bf16s(cS[j0 + 1], ql[kt], th[2], th[3]);
            }
        }

        // ---- scale + causal mask ----
        const int cbase = c * 64 + cq * 2;
        #pragma unroll
        for (int j = 0; j < 8; j++) {
            const int col = cbase + j * 8;
            cS[j][0] = (col     <= rbase)     ? cS[j][0] * scale : -3e30f;
            cS[j][1] = (col + 1 <= rbase)     ? cS[j][1] * scale : -3e30f;
            cS[j][2] = (col     <= rbase + 8) ? cS[j][2] * scale : -3e30f;
            cS[j][3] = (col + 1 <= rbase + 8) ? cS[j][3] * scale : -3e30f;
        }

        // ---- online softmax ----
        float mx0 = -3e30f, mx1 = -3e30f;
        #pragma unroll
        for (int j = 0; j < 8; j++) {
            mx0 = fmaxf(mx0, fmaxf(cS[j][0], cS[j][1]));
            mx1 = fmaxf(mx1, fmaxf(cS[j][2], cS[j][3]));
        }
        mx0 = fmaxf(mx0, __shfl_xor_sync(0xffffffffu, mx0, 1));
        mx0 = fmaxf(mx0, __shfl_xor_sync(0xffffffffu, mx0, 2));
        mx1 = fmaxf(mx1, __shfl_xor_sync(0xffffffffu, mx1, 1));
        mx1 = fmaxf(mx1, __shfl_xor_sync(0xffffffffu, mx1, 2));
        const float nm0 = fmaxf(m_i[0], mx0);
        const float nm1 = fmaxf(m_i[1], mx1);
        const float f0 = __expf(m_i[0] - nm0);
        const float f1 = __expf(m_i[1] - nm1);
        float s0 = 0.f, s1 = 0.f;
        #pragma unroll
        for (int j = 0; j < 8; j++) {
            cS[j][0] = __expf(cS[j][0] - nm0);
            cS[j][1] = __expf(cS[j][1] - nm0);
            cS[j][2] = __expf(cS[j][2] - nm1);
            cS[j][3] = __expf(cS[j][3] - nm1);
            s0 += cS[j][0] + cS[j][1];
            s1 += cS[j][2] + cS[j][3];
        }
        s0 += __shfl_xor_sync(0xffffffffu, s0, 1);
        s0 += __shfl_xor_sync(0xffffffffu, s0, 2);
        s1 += __shfl_xor_sync(0xffffffffu, s1, 1);
        s1 += __shfl_xor_sync(0xffffffffu, s1, 2);
        l_i[0] = l_i[0] * f0 + s0;  m_i[0] = nm0;
        l_i[1] = l_i[1] * f1 + s1;  m_i[1] = nm1;
        #pragma unroll
        for (int j = 0; j < 8; j++) {
            o[j][0] *= f0; o[j][1] *= f0;
            o[j][2] *= f1; o[j][3] *= f1;
        }

        // ---- O += P @ V ----
        const uint32_t v_row = ((lane & 7) + 8 * ((lane >> 3) & 1)) * APITCH
                             + (lane >> 4) * 16;
        #pragma unroll
        for (int ks = 0; ks < 4; ks++) {
            uint32_t ah[4], al[4];
            packsplit(cS[2 * ks][0],     cS[2 * ks][1],     ah[0], al[0]);
            packsplit(cS[2 * ks][2],     cS[2 * ks][3],     ah[1], al[1]);
            packsplit(cS[2 * ks + 1][0], cS[2 * ks + 1][1], ah[2], al[2]);
            packsplit(cS[2 * ks + 1][2], cS[2 * ks + 1][3], ah[3], al[3]);
            #pragma unroll
            for (int np = 0; np < 4; np++) {
                uint32_t th[4], tl[4];
                const uint32_t vd = kbuf + v_row + ks * 16 * APITCH + np * 32;
                ldsm4t(th, vd);
                ldsm4t(tl, vd + KTILEB);
                const int jd = 2 * np;
                mma_bf16s(o[jd],     ah, th[0], th[1]);
                mma_bf16s(o[jd],     ah, tl[0], tl[1]);
                mma_bf16s(o[jd],     al, th[0], th[1]);
                mma_bf16s(o[jd + 1], ah, th[2], th[3]);
                mma_bf16s(o[jd + 1], ah, tl[2], tl[3]);
                mma_bf16s(o[jd + 1], al, th[2], th[3]);
            }
        }
    }
    #undef KISSUE

    const float inv0 = 1.f / l_i[0];
    const float inv1 = 1.f / l_i[1];
    const size_t row0 = (size_t)(bq0 + warp * 16 + g);
    const size_t row1 = row0 + 8;
    #pragma unroll
    for (int j = 0; j < 8; j++) {
        const int col = h * 64 + j * 8 + cq * 2;
        uint32_t hi, lo;
        packsplit(o[j][0] * inv0, o[j][1] * inv0, hi, lo);
        *(uint32_t*)&yhi[row0 * 1024 + col] = hi;
        *(uint32_t*)&ylo[row0 * 1024 + col] = lo;
        packsplit(o[j][2] * inv1, o[j][3] * inv1, hi, lo);
        *(uint32_t*)&yhi[row1 * 1024 + col] = hi;
        *(uint32_t*)&ylo[row1 * 1024 + col] = lo;
    }
}

// ---------------------------------------------------------------------------
// Launch
// ---------------------------------------------------------------------------
extern "C" void kernel_launch(void* const* d_in, const int* in_sizes, int n_in,
                              void* d_out, int out_size)
{
    const float* x    = (const float*)d_in[0];
    const float* Wq   = (const float*)d_in[1];
    const float* Wkva = (const float*)d_in[2];
    const float* Wkvb = (const float*)d_in[3];
    const float* Wo   = (const float*)d_in[4];
    float* out = (float*)d_out;

    __nv_bfloat16 *xhi, *xlo, *qhi, *qlo, *ckvhi, *ckvlo;
    __nv_bfloat16 *kvhi, *kvlo, *krhi, *krlo, *yhi, *ylo;
    __nv_bfloat16 *wqh, *wql, *wah, *wal, *wbh, *wbl, *woh, *wol;
    cudaGetSymbolAddress((void**)&xhi, g_xhi);     cudaGetSymbolAddress((void**)&xlo, g_xlo);
    cudaGetSymbolAddress((void**)&qhi, g_qhi);     cudaGetSymbolAddress((void**)&qlo, g_qlo);
    cudaGetSymbolAddress((void**)&ckvhi, g_ckvhi); cudaGetSymbolAddress((void**)&ckvlo, g_ckvlo);
    cudaGetSymbolAddress((void**)&kvhi, g_kvhi);   cudaGetSymbolAddress((void**)&kvlo, g_kvlo);
    cudaGetSymbolAddress((void**)&krhi, g_krhi);   cudaGetSymbolAddress((void**)&krlo, g_krlo);
    cudaGetSymbolAddress((void**)&yhi, g_yhi);     cudaGetSymbolAddress((void**)&ylo, g_ylo);
    cudaGetSymbolAddress((void**)&wqh, g_wqt_hi);  cudaGetSymbolAddress((void**)&wql, g_wqt_lo);
    cudaGetSymbolAddress((void**)&wah, g_wkvat_hi); cudaGetSymbolAddress((void**)&wal, g_wkvat_lo);
    cudaGetSymbolAddress((void**)&wbh, g_wkvbt_hi); cudaGetSymbolAddress((void**)&wbl, g_wkvbt_lo);
    cudaGetSymbolAddress((void**)&woh, g_wot_hi);  cudaGetSymbolAddress((void**)&wol, g_wot_lo);

    cudaFuncSetAttribute(hmma_gemm<EPI_F32>,
                         cudaFuncAttributeMaxDynamicSharedMemorySize, GEMM_SMEM);
    cudaFuncSetAttribute(hmma_gemm<EPI_SPLIT>,
                         cudaFuncAttributeMaxDynamicSharedMemorySize, GEMM_SMEM);
    cudaFuncSetAttribute(hmma_gemm<EPI_Q>,
                         cudaFuncAttributeMaxDynamicSharedMemorySize, GEMM_SMEM);
    cudaFuncSetAttribute(hmma_gemm<EPI_CKV>,
                         cudaFuncAttributeMaxDynamicSharedMemorySize, GEMM_SMEM);
    cudaFuncSetAttribute(attn_hmma,
                         cudaFuncAttributeMaxDynamicSharedMemorySize, ATTN_SMEM);

    freq_init_kernel<<<1, 32>>>();

    const dim3 tb(32, 8);
    splitT_kernel<false><<<dim3(64, 64), tb>>>(Wq,   2048, 2048, wqh, wql, 2048);
    splitT_kernel<false><<<dim3(64, 20), tb>>>(Wkva,  576,  576, wah, wal, 2048);
    splitT_kernel<false><<<dim3(16, 32), tb>>>(Wkvb, 1024, 1024, wbh, wbl,  512);
    splitT_kernel<true ><<<dim3(32, 64), tb>>>(Wo,   2048, 2048, woh, wol, 1024);
    split_kernel<<<8192, 256>>>(x, 2048, xhi, xlo, 4096, 2048);

    // q = rope(x @ Wq) -> qhi/qlo
    hmma_gemm<EPI_Q><<<dim3(16, 32), 256, GEMM_SMEM>>>(
        xhi, xlo, wqh, wql, nullptr, qhi, qlo, nullptr, nullptr,
        2048, 2048, 2048, 0);
    // ckv = x @ Wkva -> ckvhi/ckvlo + roped krhi/krlo
    hmma_gemm<EPI_CKV><<<dim3(5, 32), 256, GEMM_SMEM>>>(
        xhi, xlo, wah, wal, nullptr, ckvhi, ckvlo, krhi, krlo,
        2048, 2048, 2048, 0);
    // kv = latent @ Wkvb -> kvhi/kvlo
    hmma_gemm<EPI_SPLIT><<<dim3(8, 32), 256, GEMM_SMEM>>>(
        ckvhi, ckvlo, wbh, wbl, nullptr, kvhi, kvlo, nullptr, nullptr,
        512, 512, 512, 1024);
    // attention -> yhi/ylo
    attn_hmma<<<dim3(16, 16, 2), 256, ATTN_SMEM>>>(qhi, qlo, kvhi, kvlo,
                                                   krhi, krlo, yhi, ylo);
    // out = y @ gather(Wo)
    hmma_gemm<EPI_F32><<<dim3(16, 32), 256, GEMM_SMEM>>>(
        yhi, ylo, woh, wol, out, nullptr, nullptr, nullptr, nullptr,
        1024, 1024, 1024, 2048);
}

// round 9
// speedup vs baseline: 4.3930x; 1.4644x over previous
#include <cuda_runtime.h>
#include <cuda_fp16.h>
#include <math.h>
#include <stdint.h>

// Problem constants
#define B_    2
#define T_    2048
#define C_    2048
#define H_    16
#define HD_   128
#define LORA_ 512
#define RD_   64
#define ND_   64
#define BT_   (B_ * T_)   // 4096

// ---------------------------------------------------------------------------
// Scratch (static __device__ globals — allocation-free per harness rules)
// ---------------------------------------------------------------------------
__device__ float g_freq[32];

// activations: fp16 hi/lo split (A operands)
__device__ __align__(16) __half g_xhi[(size_t)BT_ * 2048],  g_xlo[(size_t)BT_ * 2048];
__device__ __align__(16) __half g_qhi[(size_t)BT_ * 2048],  g_qlo[(size_t)BT_ * 2048];
__device__ __align__(16) __half g_ckvhi[(size_t)BT_ * 512], g_ckvlo[(size_t)BT_ * 512];
__device__ __align__(16) __half g_yhi[(size_t)BT_ * 1024],  g_ylo[(size_t)BT_ * 1024];
// K/V and weights: single fp16 (B operands)
__device__ __align__(16) __half g_kvh[(size_t)BT_ * 1024];
__device__ __align__(16) __half g_krh[(size_t)BT_ * 64];
__device__ __align__(16) __half g_wqt[(size_t)2048 * 2048];
__device__ __align__(16) __half g_wkvat[(size_t)640 * 2048];
__device__ __align__(16) __half g_wkvbt[(size_t)1024 * 512];
__device__ __align__(16) __half g_wot[(size_t)2048 * 1024];

// ---------------------------------------------------------------------------
// RoPE frequency table (exact formula as reference)
// ---------------------------------------------------------------------------
__global__ void freq_init_kernel() {
    const int i = threadIdx.x;
    if (i < 32) g_freq[i] = (float)pow(100000.0, -(double)i / 32.0);
}

// ---------------------------------------------------------------------------
// fp32 -> fp16 hi/lo split (for x)
// ---------------------------------------------------------------------------
__global__ void split_kernel(const float* __restrict__ in,
                             __half* __restrict__ hi, __half* __restrict__ lo,
                             int total4)
{
    const int idx = blockIdx.x * blockDim.x + threadIdx.x;
    if (idx >= total4) return;
    const float4 v = *(const float4*)&in[(size_t)idx * 4];
    float f[4] = {v.x, v.y, v.z, v.w};
    ushort4 hv, lv;
    unsigned short* hp = &hv.x;
    unsigned short* lp = &lv.x;
    #pragma unroll
    for (int i = 0; i < 4; i++) {
        __half h = __float2half_rn(f[i]);
        __half l = __float2half_rn(f[i] - __half2float(h));
        hp[i] = __half_as_ushort(h);
        lp[i] = __half_as_ushort(l);
    }
    *(ushort4*)&hi[(size_t)idx * 4] = hv;
    *(ushort4*)&lo[(size_t)idx * 4] = lv;
}

// ---------------------------------------------------------------------------
// fp32 W[k][n] -> single fp16 out[n][k] (transpose + optional gather + pad)
// ---------------------------------------------------------------------------
template <bool GATHER>
__global__ void splitT_kernel(const float* __restrict__ W, int ldw, int nIn,
                              __half* __restrict__ out, int kDim)
{
    __shared__ float tile[32][33];
    const int k0 = blockIdx.x * 32, n0 = blockIdx.y * 32;
    #pragma unroll
    for (int i = threadIdx.y; i < 32; i += 8) {
        const int k = k0 + i;
        const int row = GATHER ? (((k >> 6) << 7) + (k & 63)) : k;
        const int n = n0 + threadIdx.x;
        tile[i][threadIdx.x] = (n < nIn) ? W[(size_t)row * ldw + n] : 0.f;
    }
    __syncthreads();
    #pragma unroll
    for (int i = threadIdx.y; i < 32; i += 8) {
        const int n = n0 + i, k = k0 + threadIdx.x;
        out[(size_t)n * kDim + k] = __float2half_rn(tile[threadIdx.x][i]);
    }
}

// ---------------------------------------------------------------------------
// Shared HMMA helpers (fp16)
// ---------------------------------------------------------------------------
__device__ __forceinline__ uint32_t smem_u32(const void* p) {
    uint32_t a;
    asm("{ .reg .u64 t; cvta.to.shared.u64 t, %1; cvt.u32.u64 %0, t; }"
        : "=r"(a) : "l"(p));
    return a;
}
__device__ __forceinline__ void cp16(uint32_t dst, const void* src) {
    asm volatile("cp.async.cg.shared.global [%0], [%1], 16;"
                 :: "r"(dst), "l"(src) : "memory");
}
__device__ __forceinline__ void cp_commit() {
    asm volatile("cp.async.commit_group;" ::: "memory");
}
__device__ __forceinline__ void cp_wait0() {
    asm volatile("cp.async.wait_group 0;" ::: "memory");
}
__device__ __forceinline__ void ldsm4(uint32_t r[4], uint32_t addr) {
    asm volatile("ldmatrix.sync.aligned.m8n8.x4.shared.b16 {%0,%1,%2,%3}, [%4];"
                 : "=r"(r[0]), "=r"(r[1]), "=r"(r[2]), "=r"(r[3]) : "r"(addr));
}
__device__ __forceinline__ void ldsm4t(uint32_t r[4], uint32_t addr) {
    asm volatile("ldmatrix.sync.aligned.m8n8.x4.trans.shared.b16 {%0,%1,%2,%3}, [%4];"
                 : "=r"(r[0]), "=r"(r[1]), "=r"(r[2]), "=r"(r[3]) : "r"(addr));
}
__device__ __forceinline__ void mma_f16(float c[4], const uint32_t a[4],
                                        const uint32_t b[2]) {
    asm volatile(
        "mma.sync.aligned.m16n8k16.row.col.f32.f16.f16.f32 "
        "{%0,%1,%2,%3}, {%4,%5,%6,%7}, {%8,%9}, {%0,%1,%2,%3};"
        : "+f"(c[0]), "+f"(c[1]), "+f"(c[2]), "+f"(c[3])
        : "r"(a[0]), "r"(a[1]), "r"(a[2]), "r"(a[3]), "r"(b[0]), "r"(b[1]));
}
__device__ __forceinline__ void mma_f16s(float c[4], const uint32_t a[4],
                                         uint32_t b0, uint32_t b1) {
    asm volatile(
        "mma.sync.aligned.m16n8k16.row.col.f32.f16.f16.f32 "
        "{%0,%1,%2,%3}, {%4,%5,%6,%7}, {%8,%9}, {%0,%1,%2,%3};"
        : "+f"(c[0]), "+f"(c[1]), "+f"(c[2]), "+f"(c[3])
        : "r"(a[0]), "r"(a[1]), "r"(a[2]), "r"(a[3]), "r"(b0), "r"(b1));
}
__device__ __forceinline__ void packsplit_h(float c0, float c1,
                                            uint32_t& hi, uint32_t& lo) {
    __half h0 = __float2half_rn(c0);
    __half h1 = __float2half_rn(c1);
    __half l0 = __float2half_rn(c0 - __half2float(h0));
    __half l1 = __float2half_rn(c1 - __half2float(h1));
    hi = ((uint32_t)__half_as_ushort(h1) << 16) | __half_as_ushort(h0);
    lo = ((uint32_t)__half_as_ushort(l1) << 16) | __half_as_ushort(l0);
}
__device__ __forceinline__ uint32_t packh(float c0, float c1) {
    return ((uint32_t)__half_as_ushort(__float2half_rn(c1)) << 16)
         | __half_as_ushort(__float2half_rn(c0));
}

// ---------------------------------------------------------------------------
// Epilogue modes
// ---------------------------------------------------------------------------
#define EPI_F32   0
#define EPI_KV    1
#define EPI_Q     2
#define EPI_CKV   3

template <int EPI>
__device__ __forceinline__ void epi_store(int row, int col, float v0, float v1,
    float* __restrict__ Cf,
    __half* __restrict__ O1, __half* __restrict__ O2,
    __half* __restrict__ O3, int ldc)
{
    if (EPI == EPI_F32) {
        *(float2*)&Cf[(size_t)row * ldc + col] = make_float2(v0, v1);
    } else if (EPI == EPI_KV) {
        *(uint32_t*)&O1[(size_t)row * ldc + col] = packh(v0, v1);
    } else if (EPI == EPI_Q) {
        const int d = col & 127;
        if (d >= 64) {
            const float freq = g_freq[(d - 64) >> 1];
            float s, c;
            sincosf((float)(row & (T_ - 1)) * freq, &s, &c);
            const float t0 = v0 * c - v1 * s;
            const float t1 = v0 * s + v1 * c;
            v0 = t0; v1 = t1;
        }
        uint32_t h, l;
        packsplit_h(v0, v1, h, l);
        *(uint32_t*)&O1[(size_t)row * 2048 + col] = h;
        *(uint32_t*)&O2[(size_t)row * 2048 + col] = l;
    } else {  // EPI_CKV
        if (col < 512) {
            uint32_t h, l;
            packsplit_h(v0, v1, h, l);
            *(uint32_t*)&O1[(size_t)row * 512 + col] = h;
            *(uint32_t*)&O2[(size_t)row * 512 + col] = l;
        } else if (col < 576) {
            const float freq = g_freq[(col - 512) >> 1];
            float s, c;
            sincosf((float)(row & (T_ - 1)) * freq, &s, &c);
            *(uint32_t*)&O3[(size_t)row * 64 + (col - 512)] =
                packh(v0 * c - v1 * s, v0 * s + v1 * c);
        }
    }
}

// ---------------------------------------------------------------------------
// HMMA fp16 asymmetric-split GEMM:
//   C[M,N] = (Ahi+Alo)[M,K] @ B[N,K]^T    (2 MMAs per product)
// CTA 128x128, 8 warps of 64x32, BK=32, cp.async double buffer.
// ---------------------------------------------------------------------------
#define ROWB   80
#define TILEB  (128 * ROWB)     // 10240
#define STAGEB (3 * TILEB)      // 30720 (Ahi, Alo, B)
#define GEMM_SMEM (2 * STAGEB)  // 61440

template <int EPI>
__global__ __launch_bounds__(256)
void hmma_gemm(const __half* __restrict__ Ahi, const __half* __restrict__ Alo,
               const __half* __restrict__ Bm,
               float* __restrict__ Cf,
               __half* __restrict__ O1, __half* __restrict__ O2,
               __half* __restrict__ O3,
               int K, int lda, int ldb, int ldc)
{
    extern __shared__ char smc[];
    const uint32_t sb = smem_u32(smc);
    const int tid = threadIdx.x;
    const int lane = tid & 31, warp = tid >> 5;
    const int wm = warp >> 2, wn = warp & 3;
    const int m0 = blockIdx.y * 128, n0 = blockIdx.x * 128;

    const int r_ld = tid >> 2;
    const int cc = tid & 3;
    const __half* pAh0 = Ahi + (size_t)(m0 + r_ld) * lda + cc * 8;
    const __half* pAh1 = Ahi + (size_t)(m0 + r_ld + 64) * lda + cc * 8;
    const __half* pAl0 = Alo + (size_t)(m0 + r_ld) * lda + cc * 8;
    const __half* pAl1 = Alo + (size_t)(m0 + r_ld + 64) * lda + cc * 8;
    const __half* pB0  = Bm  + (size_t)(n0 + r_ld) * ldb + cc * 8;
    const __half* pB1  = Bm  + (size_t)(n0 + r_ld + 64) * ldb + cc * 8;
    const uint32_t d0 = r_ld * ROWB + cc * 16;
    const uint32_t d1 = (r_ld + 64) * ROWB + cc * 16;

    #define ISSUE(st, k0_) do {                                               \
        const uint32_t bb = sb + (uint32_t)(st) * STAGEB;                     \
        cp16(bb + 0 * TILEB + d0, pAh0 + (k0_));                              \
        cp16(bb + 0 * TILEB + d1, pAh1 + (k0_));                              \
        cp16(bb + 1 * TILEB + d0, pAl0 + (k0_));                              \
        cp16(bb + 1 * TILEB + d1, pAl1 + (k0_));                              \
        cp16(bb + 2 * TILEB + d0, pB0 + (k0_));                               \
        cp16(bb + 2 * TILEB + d1, pB1 + (k0_));                               \
        cp_commit();                                                          \
    } while (0)

    float c[4][4][4];
    #pragma unroll
    for (int i = 0; i < 4; i++)
        #pragma unroll
        for (int j = 0; j < 4; j++)
            #pragma unroll
            for (int l = 0; l < 4; l++) c[i][j][l] = 0.f;

    const uint32_t a_row = wm * 64 + (lane & 15);
    const uint32_t a_koff = (lane >> 4) * 16;
    const uint32_t b_row = wn * 32 + ((lane >> 4) << 3) + (lane & 7);
    const uint32_t b_koff = ((lane >> 3) & 1) * 16;

    const int niter = K >> 5;
    ISSUE(0, 0);

    for (int it = 0; it < niter; it++) {
        cp_wait0();
        __syncthreads();
        if (it + 1 < niter) ISSUE((it + 1) & 1, (it + 1) << 5);

        const uint32_t buf = sb + (uint32_t)(it & 1) * STAGEB;
        #pragma unroll
        for (int ks = 0; ks < 2; ks++) {
            const uint32_t kb = ks * 32;
            uint32_t afh[4][4], afl[4][4], bf[4][2];
            #pragma unroll
            for (int mt = 0; mt < 4; mt++) {
                const uint32_t ad = buf + (a_row + mt * 16) * ROWB + kb + a_koff;
                ldsm4(afh[mt], ad + 0 * TILEB);
                ldsm4(afl[mt], ad + 1 * TILEB);
            }
            #pragma unroll
            for (int np = 0; np < 2; np++) {
                const uint32_t bd = buf + (b_row + np * 16) * ROWB + kb + b_koff;
                uint32_t t[4];
                ldsm4(t, bd + 2 * TILEB);
                bf[np * 2][0] = t[0]; bf[np * 2][1] = t[1];
                bf[np * 2 + 1][0] = t[2]; bf[np * 2 + 1][1] = t[3];
            }
            #pragma unroll
            for (int mt = 0; mt < 4; mt++)
                #pragma unroll
                for (int nt = 0; nt < 4; nt++) {
                    mma_f16(c[mt][nt], afh[mt], bf[nt]);
                    mma_f16(c[mt][nt], afl[mt], bf[nt]);
                }
        }
    }
    #undef ISSUE

    #pragma unroll
    for (int mt = 0; mt < 4; mt++) {
        const int row = m0 + wm * 64 + mt * 16 + (lane >> 2);
        #pragma unroll
        for (int nt = 0; nt < 4; nt++) {
            const int col = n0 + wn * 32 + nt * 8 + (lane & 3) * 2;
            epi_store<EPI>(row,     col, c[mt][nt][0], c[mt][nt][1],
                           Cf, O1, O2, O3, ldc);
            epi_store<EPI>(row + 8, col, c[mt][nt][2], c[mt][nt][3],
                           Cf, O1, O2, O3, ldc);
        }
    }
}

// ---------------------------------------------------------------------------
// HMMA flash attention (causal), fp16 asymmetric split.
// Q split in regs; K/V single fp16 tile (double-buffered cp.async ring).
// ---------------------------------------------------------------------------
#define APITCH 272
#define KTILEB (64 * APITCH)                 // 17408 (single K/V tile)
#define ATTN_SMEM (2 * 2 * 128 * 136)        // 69632 (Q staging hi+lo; >= 2*KTILEB)

__global__ __launch_bounds__(256)
void attn_hmma(const __half* __restrict__ qhi, const __half* __restrict__ qlo,
               const __half* __restrict__ kvh, const __half* __restrict__ krh,
               __half* __restrict__ yhi, __half* __restrict__ ylo)
{
    extern __shared__ char sma[];
    const uint32_t sb = smem_u32(sma);
    const int tid = threadIdx.x;
    const int lane = tid & 31, warp = tid >> 5;
    const int qt = blockIdx.x, h = blockIdx.y, b = blockIdx.z;
    const int q0 = qt * 128;
    const int bq0 = b * T_ + q0;
    const float scale = 0.08838834764831845f;

    // ---- stage Q (hi, lo) and pull fragments into registers ----
    #pragma unroll
    for (int t = 0; t < 2; t++) {
        const __half* src = t ? qlo : qhi;
        #pragma unroll
        for (int i = 0; i < 8; i++) {
            const int idx = i * 256 + tid;
            const int r = idx >> 4, gc = idx & 15;
            *(float4*)(sma + t * (128 * APITCH) + r * APITCH + gc * 16) =
                *(const float4*)(src + (size_t)(bq0 + r) * 2048 + h * 128 + gc * 8);
        }
    }
    __syncthreads();

    uint32_t qh[8][4], ql[8][4];
    {
        const uint32_t a_base = sb + (warp * 16 + (lane & 15)) * APITCH + (lane >> 4) * 16;
        #pragma unroll
        for (int kt = 0; kt < 8; kt++) {
            ldsm4(qh[kt], a_base + kt * 32);
            ldsm4(ql[kt], a_base + kt * 32 + 128 * APITCH);
        }
    }
    __syncthreads();    // smem now free for the K-tile ring

    const int s_ld = tid >> 4;
    const int gc_ld = tid & 15;
    const int hoff = h * 64 + (gc_ld & 7) * 8;
    const int roff = (gc_ld - 8) * 8;

    #define KISSUE(st, bk0_) do {                                             \
        const uint32_t bb = sb + (uint32_t)(st) * KTILEB;                     \
        _Pragma("unroll")                                                     \
        for (int i = 0; i < 4; i++) {                                         \
            const int s = s_ld + i * 16;                                      \
            const void* src = (gc_ld < 8)                                     \
                ? (const void*)(kvh + (size_t)((bk0_) + s) * 1024 + hoff)     \
                : (const void*)(krh + (size_t)((bk0_) + s) * 64 + roff);      \
            cp16(bb + s * APITCH + gc_ld * 16, src);                          \
        }                                                                     \
        cp_commit();                                                          \
    } while (0)

    float m_i[2] = {-1e30f, -1e30f};
    float l_i[2] = {0.f, 0.f};
    float o[8][4];
    #pragma unroll
    for (int j = 0; j < 8; j++)
        #pragma unroll
        for (int e = 0; e < 4; e++) o[j][e] = 0.f;

    const int g = lane >> 2, cq = lane & 3;
    const int rbase = q0 + warp * 16 + g;

    const int nk = 2 * qt + 2;
    KISSUE(0, b * T_);

    for (int c = 0; c < nk; c++) {
        cp_wait0();
        __syncthreads();
        if (c + 1 < nk) KISSUE((c + 1) & 1, b * T_ + (c + 1) * 64);

        const uint32_t kbuf = sb + (uint32_t)(c & 1) * KTILEB;

        // ---- S = Q K^T ----
        float cS[8][4];
        #pragma unroll
        for (int j = 0; j < 8; j++)
            #pragma unroll
            for (int e = 0; e < 4; e++) cS[j][e] = 0.f;

        const uint32_t b_base = kbuf + (((lane >> 4) << 3) + (lane & 7)) * APITCH
                              + ((lane >> 3) & 1) * 16;
        #pragma unroll
        for (int kt = 0; kt < 8; kt++) {
            #pragma unroll
            for (int np = 0; np < 4; np++) {
                uint32_t th[4];
                ldsm4(th, b_base + np * 16 * APITCH + kt * 32);
                const int j0 = 2 * np;
                mma_f16s(cS[j0],     qh[kt], th[0], th[1]);
                mma_f16s(cS[j0],     ql[kt], th[0], th[1]);
                mma_f16s(cS[j0 + 1], qh[kt], th[2], th[3]);
                mma_f16s(cS[j0 + 1], ql[kt], th[2], th[3]);
            }
        }

        // ---- scale + causal mask ----
        const int cbase = c * 64 + cq * 2;
        #pragma unroll
        for (int j = 0; j < 8; j++) {
            const int col = cbase + j * 8;
            cS[j][0] = (col     <= rbase)     ? cS[j][0] * scale : -3e30f;
            cS[j][1] = (col + 1 <= rbase)     ? cS[j][1] * scale : -3e30f;
            cS[j][2] = (col     <= rbase + 8) ? cS[j][2] * scale : -3e30f;
            cS[j][3] = (col + 1 <= rbase + 8) ? cS[j][3] * scale : -3e30f;
        }

        // ---- online softmax ----
        float mx0 = -3e30f, mx1 = -3e30f;
        #pragma unroll
        for (int j = 0; j < 8; j++) {
            mx0 = fmaxf(mx0, fmaxf(cS[j][0], cS[j][1]));
            mx1 = fmaxf(mx1, fmaxf(cS[j][2], cS[j][3]));
        }
        mx0 = fmaxf(mx0, __shfl_xor_sync(0xffffffffu, mx0, 1));
        mx0 = fmaxf(mx0, __shfl_xor_sync(0xffffffffu, mx0, 2));
        mx1 = fmaxf(mx1, __shfl_xor_sync(0xffffffffu, mx1, 1));
        mx1 = fmaxf(mx1, __shfl_xor_sync(0xffffffffu, mx1, 2));
        const float nm0 = fmaxf(m_i[0], mx0);
        const float nm1 = fmaxf(m_i[1], mx1);
        const float f0 = __expf(m_i[0] - nm0);
        const float f1 = __expf(m_i[1] - nm1);
        float s0 = 0.f, s1 = 0.f;
        #pragma unroll
        for (int j = 0; j < 8; j++) {
            cS[j][0] = __expf(cS[j][0] - nm0);
            cS[j][1] = __expf(cS[j][1] - nm0);
            cS[j][2] = __expf(cS[j][2] - nm1);
            cS[j][3] = __expf(cS[j][3] - nm1);
            s0 += cS[j][0] + cS[j][1];
            s1 += cS[j][2] + cS[j][3];
        }
        s0 += __shfl_xor_sync(0xffffffffu, s0, 1);
        s0 += __shfl_xor_sync(0xffffffffu, s0, 2);
        s1 += __shfl_xor_sync(0xffffffffu, s1, 1);
        s1 += __shfl_xor_sync(0xffffffffu, s1, 2);
        l_i[0] = l_i[0] * f0 + s0;  m_i[0] = nm0;
        l_i[1] = l_i[1] * f1 + s1;  m_i[1] = nm1;
        #pragma unroll
        for (int j = 0; j < 8; j++) {
            o[j][0] *= f0; o[j][1] *= f0;
            o[j][2] *= f1; o[j][3] *= f1;
        }

        // ---- O += P @ V (P split hi/lo, V single) ----
        const uint32_t v_row = ((lane & 7) + 8 * ((lane >> 3) & 1)) * APITCH
                             + (lane >> 4) * 16;
        #pragma unroll
        for (int ks = 0; ks < 4; ks++) {
            uint32_t ah[4], al[4];
            packsplit_h(cS[2 * ks][0],     cS[2 * ks][1],     ah[0], al[0]);
            packsplit_h(cS[2 * ks][2],     cS[2 * ks][3],     ah[1], al[1]);
            packsplit_h(cS[2 * ks + 1][0], cS[2 * ks + 1][1], ah[2], al[2]);
            packsplit_h(cS[2 * ks + 1][2], cS[2 * ks + 1][3], ah[3], al[3]);
            #pragma unroll
            for (int np = 0; np < 4; np++) {
                uint32_t th[4];
                ldsm4t(th, kbuf + v_row + ks * 16 * APITCH + np * 32);
                const int jd = 2 * np;
                mma_f16s(o[jd],     ah, th[0], th[1]);
                mma_f16s(o[jd],     al, th[0], th[1]);
                mma_f16s(o[jd + 1], ah, th[2], th[3]);
                mma_f16s(o[jd + 1], al, th[2], th[3]);
            }
        }
    }
    #undef KISSUE

    const float inv0 = 1.f / l_i[0];
    const float inv1 = 1.f / l_i[1];
    const size_t row0 = (size_t)(bq0 + warp * 16 + g);
    const size_t row1 = row0 + 8;
    #pragma unroll
    for (int j = 0; j < 8; j++) {
        const int col = h * 64 + j * 8 + cq * 2;
        uint32_t hi, lo;
        packsplit_h(o[j][0] * inv0, o[j][1] * inv0, hi, lo);
        *(uint32_t*)&yhi[row0 * 1024 + col] = hi;
        *(uint32_t*)&ylo[row0 * 1024 + col] = lo;
        packsplit_h(o[j][2] * inv1, o[j][3] * inv1, hi, lo);
        *(uint32_t*)&yhi[row1 * 1024 + col] = hi;
        *(uint32_t*)&ylo[row1 * 1024 + col] = lo;
    }
}

// ---------------------------------------------------------------------------
// Launch
// ---------------------------------------------------------------------------
extern "C" void kernel_launch(void* const* d_in, const int* in_sizes, int n_in,
                              void* d_out, int out_size)
{
    const float* x    = (const float*)d_in[0];
    const float* Wq   = (const float*)d_in[1];
    const float* Wkva = (const float*)d_in[2];
    const float* Wkvb = (const float*)d_in[3];
    const float* Wo   = (const float*)d_in[4];
    float* out = (float*)d_out;

    __half *xhi, *xlo, *qhi, *qlo, *ckvhi, *ckvlo, *yhi, *ylo;
    __half *kvh, *krh, *wq, *wa, *wb, *wo;
    cudaGetSymbolAddress((void**)&xhi, g_xhi);     cudaGetSymbolAddress((void**)&xlo, g_xlo);
    cudaGetSymbolAddress((void**)&qhi, g_qhi);     cudaGetSymbolAddress((void**)&qlo, g_qlo);
    cudaGetSymbolAddress((void**)&ckvhi, g_ckvhi); cudaGetSymbolAddress((void**)&ckvlo, g_ckvlo);
    cudaGetSymbolAddress((void**)&yhi, g_yhi);     cudaGetSymbolAddress((void**)&ylo, g_ylo);
    cudaGetSymbolAddress((void**)&kvh, g_kvh);     cudaGetSymbolAddress((void**)&krh, g_krh);
    cudaGetSymbolAddress((void**)&wq, g_wqt);      cudaGetSymbolAddress((void**)&wa, g_wkvat);
    cudaGetSymbolAddress((void**)&wb, g_wkvbt);    cudaGetSymbolAddress((void**)&wo, g_wot);

    cudaFuncSetAttribute(hmma_gemm<EPI_F32>,
                         cudaFuncAttributeMaxDynamicSharedMemorySize, GEMM_SMEM);
    cudaFuncSetAttribute(hmma_gemm<EPI_KV>,
                         cudaFuncAttributeMaxDynamicSharedMemorySize, GEMM_SMEM);
    cudaFuncSetAttribute(hmma_gemm<EPI_Q>,
                         cudaFuncAttributeMaxDynamicSharedMemorySize, GEMM_SMEM);
    cudaFuncSetAttribute(hmma_gemm<EPI_CKV>,
                         cudaFuncAttributeMaxDynamicSharedMemorySize, GEMM_SMEM);
    cudaFuncSetAttribute(attn_hmma,
                         cudaFuncAttributeMaxDynamicSharedMemorySize, ATTN_SMEM);

    freq_init_kernel<<<1, 32>>>();

    const dim3 tb(32, 8);
    splitT_kernel<false><<<dim3(64, 64), tb>>>(Wq,   2048, 2048, wq, 2048);
    splitT_kernel<false><<<dim3(64, 20), tb>>>(Wkva,  576,  576, wa, 2048);
    splitT_kernel<false><<<dim3(16, 32), tb>>>(Wkvb, 1024, 1024, wb,  512);
    splitT_kernel<true ><<<dim3(32, 64), tb>>>(Wo,   2048, 2048, wo, 1024);
    split_kernel<<<8192, 256>>>(x, xhi, xlo, 4096 * 512);

    // q = rope(x @ Wq) -> qhi/qlo
    hmma_gemm<EPI_Q><<<dim3(16, 32), 256, GEMM_SMEM>>>(
        xhi, xlo, wq, nullptr, qhi, qlo, nullptr,
        2048, 2048, 2048, 0);
    // ckv = x @ Wkva -> ckvhi/ckvlo + roped krh
    hmma_gemm<EPI_CKV><<<dim3(5, 32), 256, GEMM_SMEM>>>(
        xhi, xlo, wa, nullptr, ckvhi, ckvlo, krh,
        2048, 2048, 2048, 0);
    // kv = latent @ Wkvb -> kvh (single)
    hmma_gemm<EPI_KV><<<dim3(8, 32), 256, GEMM_SMEM>>>(
        ckvhi, ckvlo, wb, nullptr, kvh, nullptr, nullptr,
        512, 512, 512, 1024);
    // attention -> yhi/ylo
    attn_hmma<<<dim3(16, 16, 2), 256, ATTN_SMEM>>>(qhi, qlo, kvh, krh, yhi, ylo);
    // out = y @ gather(Wo)
    hmma_gemm<EPI_F32><<<dim3(16, 32), 256, GEMM_SMEM>>>(
        yhi, ylo, wo, out, nullptr, nullptr, nullptr,
        1024, 1024, 1024, 2048);
}

// round 12
// speedup vs baseline: 4.7186x; 1.0741x over previous
#include <cuda_runtime.h>
#include <cuda_fp16.h>
#include <math.h>
#include <stdint.h>

// Problem constants
#define B_    2
#define T_    2048
#define C_    2048
#define H_    16
#define HD_   128
#define LORA_ 512
#define RD_   64
#define ND_   64
#define BT_   (B_ * T_)   // 4096

// ---------------------------------------------------------------------------
// Scratch (static __device__ globals — allocation-free per harness rules)
// ---------------------------------------------------------------------------
__device__ float g_freq[32];

// activations: fp16 hi/lo split (A operands)
__device__ __align__(16) __half g_xhi[(size_t)BT_ * 2048],  g_xlo[(size_t)BT_ * 2048];
__device__ __align__(16) __half g_qhi[(size_t)BT_ * 2048],  g_qlo[(size_t)BT_ * 2048];
__device__ __align__(16) __half g_ckvhi[(size_t)BT_ * 512], g_ckvlo[(size_t)BT_ * 512];
__device__ __align__(16) __half g_yhi[(size_t)BT_ * 1024],  g_ylo[(size_t)BT_ * 1024];
// K/V and weights: single fp16 (B operands)
__device__ __align__(16) __half g_kvh[(size_t)BT_ * 1024];
__device__ __align__(16) __half g_krh[(size_t)BT_ * 64];
__device__ __align__(16) __half g_wqt[(size_t)2048 * 2048];
__device__ __align__(16) __half g_wkvat[(size_t)640 * 2048];
__device__ __align__(16) __half g_wkvbt[(size_t)1024 * 512];
__device__ __align__(16) __half g_wot[(size_t)2048 * 1024];

// ---------------------------------------------------------------------------
// RoPE frequency table (exact formula as reference)
// ---------------------------------------------------------------------------
__global__ void freq_init_kernel() {
    const int i = threadIdx.x;
    if (i < 32) g_freq[i] = (float)pow(100000.0, -(double)i / 32.0);
}

// ---------------------------------------------------------------------------
// fp32 -> fp16 hi/lo split (for x)
// ---------------------------------------------------------------------------
__global__ void split_kernel(const float* __restrict__ in,
                             __half* __restrict__ hi, __half* __restrict__ lo,
                             int total4)
{
    const int idx = blockIdx.x * blockDim.x + threadIdx.x;
    if (idx >= total4) return;
    const float4 v = *(const float4*)&in[(size_t)idx * 4];
    float f[4] = {v.x, v.y, v.z, v.w};
    ushort4 hv, lv;
    unsigned short* hp = &hv.x;
    unsigned short* lp = &lv.x;
    #pragma unroll
    for (int i = 0; i < 4; i++) {
        __half h = __float2half_rn(f[i]);
        __half l = __float2half_rn(f[i] - __half2float(h));
        hp[i] = __half_as_ushort(h);
        lp[i] = __half_as_ushort(l);
    }
    *(ushort4*)&hi[(size_t)idx * 4] = hv;
    *(ushort4*)&lo[(size_t)idx * 4] = lv;
}

// ---------------------------------------------------------------------------
// fp32 W[k][n] -> single fp16 out[n][k] (transpose + optional gather + pad)
// ---------------------------------------------------------------------------
template <bool GATHER>
__global__ void splitT_kernel(const float* __restrict__ W, int ldw, int nIn,
                              __half* __restrict__ out, int kDim)
{
    __shared__ float tile[32][33];
    const int k0 = blockIdx.x * 32, n0 = blockIdx.y * 32;
    #pragma unroll
    for (int i = threadIdx.y; i < 32; i += 8) {
        const int k = k0 + i;
        const int row = GATHER ? (((k >> 6) << 7) + (k & 63)) : k;
        const int n = n0 + threadIdx.x;
        tile[i][threadIdx.x] = (n < nIn) ? W[(size_t)row * ldw + n] : 0.f;
    }
    __syncthreads();
    #pragma unroll
    for (int i = threadIdx.y; i < 32; i += 8) {
        const int n = n0 + i, k = k0 + threadIdx.x;
        out[(size_t)n * kDim + k] = __float2half_rn(tile[threadIdx.x][i]);
    }
}

// ---------------------------------------------------------------------------
// Shared HMMA helpers (fp16)
// ---------------------------------------------------------------------------
__device__ __forceinline__ uint32_t smem_u32(const void* p) {
    uint32_t a;
    asm("{ .reg .u64 t; cvta.to.shared.u64 t, %1; cvt.u32.u64 %0, t; }"
        : "=r"(a) : "l"(p));
    return a;
}
__device__ __forceinline__ void cp16(uint32_t dst, const void* src) {
    asm volatile("cp.async.cg.shared.global [%0], [%1], 16;"
                 :: "r"(dst), "l"(src) : "memory");
}
__device__ __forceinline__ void cp_commit() {
    asm volatile("cp.async.commit_group;" ::: "memory");
}
__device__ __forceinline__ void cp_wait0() {
    asm volatile("cp.async.wait_group 0;" ::: "memory");
}
__device__ __forceinline__ void ldsm4(uint32_t r[4], uint32_t addr) {
    asm volatile("ldmatrix.sync.aligned.m8n8.x4.shared.b16 {%0,%1,%2,%3}, [%4];"
                 : "=r"(r[0]), "=r"(r[1]), "=r"(r[2]), "=r"(r[3]) : "r"(addr));
}
__device__ __forceinline__ void ldsm4t(uint32_t r[4], uint32_t addr) {
    asm volatile("ldmatrix.sync.aligned.m8n8.x4.trans.shared.b16 {%0,%1,%2,%3}, [%4];"
                 : "=r"(r[0]), "=r"(r[1]), "=r"(r[2]), "=r"(r[3]) : "r"(addr));
}
__device__ __forceinline__ void mma_f16(float c[4], const uint32_t a[4],
                                        const uint32_t b[2]) {
    asm volatile(
        "mma.sync.aligned.m16n8k16.row.col.f32.f16.f16.f32 "
        "{%0,%1,%2,%3}, {%4,%5,%6,%7}, {%8,%9}, {%0,%1,%2,%3};"
        : "+f"(c[0]), "+f"(c[1]), "+f"(c[2]), "+f"(c[3])
        : "r"(a[0]), "r"(a[1]), "r"(a[2]), "r"(a[3]), "r"(b[0]), "r"(b[1]));
}
__device__ __forceinline__ void mma_f16s(float c[4], const uint32_t a[4],
                                         uint32_t b0, uint32_t b1) {
    asm volatile(
        "mma.sync.aligned.m16n8k16.row.col.f32.f16.f16.f32 "
        "{%0,%1,%2,%3}, {%4,%5,%6,%7}, {%8,%9}, {%0,%1,%2,%3};"
        : "+f"(c[0]), "+f"(c[1]), "+f"(c[2]), "+f"(c[3])
        : "r"(a[0]), "r"(a[1]), "r"(a[2]), "r"(a[3]), "r"(b0), "r"(b1));
}
__device__ __forceinline__ void packsplit_h(float c0, float c1,
                                            uint32_t& hi, uint32_t& lo) {
    __half h0 = __float2half_rn(c0);
    __half h1 = __float2half_rn(c1);
    __half l0 = __float2half_rn(c0 - __half2float(h0));
    __half l1 = __float2half_rn(c1 - __half2float(h1));
    hi = ((uint32_t)__half_as_ushort(h1) << 16) | __half_as_ushort(h0);
    lo = ((uint32_t)__half_as_ushort(l1) << 16) | __half_as_ushort(l0);
}
__device__ __forceinline__ uint32_t packh(float c0, float c1) {
    return ((uint32_t)__half_as_ushort(__float2half_rn(c1)) << 16)
         | __half_as_ushort(__float2half_rn(c0));
}

// ---------------------------------------------------------------------------
// Epilogue modes
// ---------------------------------------------------------------------------
#define EPI_F32   0
#define EPI_KV    1
#define EPI_Q     2
#define EPI_CKV   3
#define EPI_QCKV  4

template <int EPI>
__device__ __forceinline__ void epi_store(int row, int col, float v0, float v1,
    float* __restrict__ Cf,
    __half* __restrict__ O1, __half* __restrict__ O2,
    __half* __restrict__ O3, int ldc)
{
    if (EPI == EPI_F32) {
        *(float2*)&Cf[(size_t)row * ldc + col] = make_float2(v0, v1);
    } else if (EPI == EPI_KV) {
        *(uint32_t*)&O1[(size_t)row * ldc + col] = packh(v0, v1);
    } else if (EPI == EPI_Q) {
        const int d = col & 127;
        if (d >= 64) {
            const float freq = g_freq[(d - 64) >> 1];
            float s, c;
            sincosf((float)(row & (T_ - 1)) * freq, &s, &c);
            const float t0 = v0 * c - v1 * s;
            const float t1 = v0 * s + v1 * c;
            v0 = t0; v1 = t1;
        }
        uint32_t h, l;
        packsplit_h(v0, v1, h, l);
        *(uint32_t*)&O1[(size_t)row * 2048 + col] = h;
        *(uint32_t*)&O2[(size_t)row * 2048 + col] = l;
    } else if (EPI == EPI_CKV) {
        if (col < 512) {
            uint32_t h, l;
            packsplit_h(v0, v1, h, l);
            *(uint32_t*)&O1[(size_t)row * 512 + col] = h;
            *(uint32_t*)&O2[(size_t)row * 512 + col] = l;
        } else if (col < 576) {
            const float freq = g_freq[(col - 512) >> 1];
            float s, c;
            sincosf((float)(row & (T_ - 1)) * freq, &s, &c);
            *(uint32_t*)&O3[(size_t)row * 64 + (col - 512)] =
                packh(v0 * c - v1 * s, v0 * s + v1 * c);
        }
    }
}

// ---------------------------------------------------------------------------
// HMMA fp16 asymmetric-split GEMM:
//   C[M,N] = (Ahi+Alo)[M,K] @ B[N,K]^T    (2 MMAs per product)
// CTA 128x128, 8 warps of 64x32, BK=32, cp.async double buffer.
// EPI_QCKV: merged q+ckv launch — grid.x=21; blocks 0-15 use Bm (Wq, EPI_Q),
//           blocks 16-20 use Balt (Wkva, EPI_CKV). Fills the wave tail.
// ---------------------------------------------------------------------------
#define ROWB   80
#define TILEB  (128 * ROWB)     // 10240
#define STAGEB (3 * TILEB)      // 30720 (Ahi, Alo, B)
#define GEMM_SMEM (2 * STAGEB)  // 61440

template <int EPI>
__global__ __launch_bounds__(256)
void hmma_gemm(const __half* __restrict__ Ahi, const __half* __restrict__ Alo,
               const __half* __restrict__ Bm, const __half* __restrict__ Balt,
               float* __restrict__ Cf,
               __half* __restrict__ O1, __half* __restrict__ O2,
               __half* __restrict__ O3, __half* __restrict__ O4,
               __half* __restrict__ O5,
               int K, int lda, int ldb, int ldc)
{
    extern __shared__ char smc[];
    const uint32_t sb = smem_u32(smc);
    const int tid = threadIdx.x;
    const int lane = tid & 31, warp = tid >> 5;
    const int wm = warp >> 2, wn = warp & 3;
    const int m0 = blockIdx.y * 128;

    bool isQ = true;
    const __half* Bu = Bm;
    int n0 = blockIdx.x * 128;
    if (EPI == EPI_QCKV && blockIdx.x >= 16) {
        isQ = false;
        Bu = Balt;
        n0 = (blockIdx.x - 16) * 128;
    }

    const int r_ld = tid >> 2;
    const int cc = tid & 3;
    const __half* pAh0 = Ahi + (size_t)(m0 + r_ld) * lda + cc * 8;
    const __half* pAh1 = Ahi + (size_t)(m0 + r_ld + 64) * lda + cc * 8;
    const __half* pAl0 = Alo + (size_t)(m0 + r_ld) * lda + cc * 8;
    const __half* pAl1 = Alo + (size_t)(m0 + r_ld + 64) * lda + cc * 8;
    const __half* pB0  = Bu  + (size_t)(n0 + r_ld) * ldb + cc * 8;
    const __half* pB1  = Bu  + (size_t)(n0 + r_ld + 64) * ldb + cc * 8;
    const uint32_t d0 = r_ld * ROWB + cc * 16;
    const uint32_t d1 = (r_ld + 64) * ROWB + cc * 16;

    #define ISSUE(st, k0_) do {                                               \
        const uint32_t bb = sb + (uint32_t)(st) * STAGEB;                     \
        cp16(bb + 0 * TILEB + d0, pAh0 + (k0_));                              \
        cp16(bb + 0 * TILEB + d1, pAh1 + (k0_));                              \
        cp16(bb + 1 * TILEB + d0, pAl0 + (k0_));                              \
        cp16(bb + 1 * TILEB + d1, pAl1 + (k0_));                              \
        cp16(bb + 2 * TILEB + d0, pB0 + (k0_));                               \
        cp16(bb + 2 * TILEB + d1, pB1 + (k0_));                               \
        cp_commit();                                                          \
    } while (0)

    float c[4][4][4];
    #pragma unroll
    for (int i = 0; i < 4; i++)
        #pragma unroll
        for (int j = 0; j < 4; j++)
            #pragma unroll
            for (int l = 0; l < 4; l++) c[i][j][l] = 0.f;

    const uint32_t a_row = wm * 64 + (lane & 15);
    const uint32_t a_koff = (lane >> 4) * 16;
    const uint32_t b_row = wn * 32 + ((lane >> 4) << 3) + (lane & 7);
    const uint32_t b_koff = ((lane >> 3) & 1) * 16;

    const int niter = K >> 5;
    ISSUE(0, 0);

    for (int it = 0; it < niter; it++) {
        cp_wait0();
        __syncthreads();
        if (it + 1 < niter) ISSUE((it + 1) & 1, (it + 1) << 5);

        const uint32_t buf = sb + (uint32_t)(it & 1) * STAGEB;
        #pragma unroll
        for (int ks = 0; ks < 2; ks++) {
            const uint32_t kb = ks * 32;
            uint32_t afh[4][4], afl[4][4], bf[4][2];
            #pragma unroll
            for (int mt = 0; mt < 4; mt++) {
                const uint32_t ad = buf + (a_row + mt * 16) * ROWB + kb + a_koff;
                ldsm4(afh[mt], ad + 0 * TILEB);
                ldsm4(afl[mt], ad + 1 * TILEB);
            }
            #pragma unroll
            for (int np = 0; np < 2; np++) {
                const uint32_t bd = buf + (b_row + np * 16) * ROWB + kb + b_koff;
                uint32_t t[4];
                ldsm4(t, bd + 2 * TILEB);
                bf[np * 2][0] = t[0]; bf[np * 2][1] = t[1];
                bf[np * 2 + 1][0] = t[2]; bf[np * 2 + 1][1] = t[3];
            }
            #pragma unroll
            for (int mt = 0; mt < 4; mt++)
                #pragma unroll
                for (int nt = 0; nt < 4; nt++) {
                    mma_f16(c[mt][nt], afh[mt], bf[nt]);
                    mma_f16(c[mt][nt], afl[mt], bf[nt]);
                }
        }
    }
    #undef ISSUE

    #pragma unroll
    for (int mt = 0; mt < 4; mt++) {
        const int row = m0 + wm * 64 + mt * 16 + (lane >> 2);
        #pragma unroll
        for (int nt = 0; nt < 4; nt++) {
            const int col = n0 + wn * 32 + nt * 8 + (lane & 3) * 2;
            if (EPI == EPI_QCKV) {
                if (isQ) {
                    epi_store<EPI_Q>(row,     col, c[mt][nt][0], c[mt][nt][1],
                                     nullptr, O1, O2, nullptr, 0);
                    epi_store<EPI_Q>(row + 8, col, c[mt][nt][2], c[mt][nt][3],
                                     nullptr, O1, O2, nullptr, 0);
                } else {
                    epi_store<EPI_CKV>(row,     col, c[mt][nt][0], c[mt][nt][1],
                                       nullptr, O3, O4, O5, 0);
                    epi_store<EPI_CKV>(row + 8, col, c[mt][nt][2], c[mt][nt][3],
                                       nullptr, O3, O4, O5, 0);
                }
            } else {
                epi_store<EPI>(row,     col, c[mt][nt][0], c[mt][nt][1],
                               Cf, O1, O2, O3, ldc);
                epi_store<EPI>(row + 8, col, c[mt][nt][2], c[mt][nt][3],
                               Cf, O1, O2, O3, ldc);
            }
        }
    }
}

// ---------------------------------------------------------------------------
// HMMA flash attention (causal), fp16 asymmetric split.
// qt mapped DESCENDING from blockIdx.x so the longest CTAs schedule first
// (LPT — removes the straggler tail).
// ---------------------------------------------------------------------------
#define APITCH 272
#define KTILEB (64 * APITCH)                 // 17408 (single K/V tile)
#define ATTN_SMEM (2 * 2 * 128 * 136)        // 69632 (Q staging hi+lo; >= 2*KTILEB)

__global__ __launch_bounds__(256)
void attn_hmma(const __half* __restrict__ qhi, const __half* __restrict__ qlo,
               const __half* __restrict__ kvh, const __half* __restrict__ krh,
               __half* __restrict__ yhi, __half* __restrict__ ylo)
{
    extern __shared__ char sma[];
    const uint32_t sb = smem_u32(sma);
    const int tid = threadIdx.x;
    const int lane = tid & 31, warp = tid >> 5;
    const int qt = (int)gridDim.x - 1 - (int)blockIdx.x;   // big work first
    const int h = blockIdx.y, b = blockIdx.z;
    const int q0 = qt * 128;
    const int bq0 = b * T_ + q0;
    const float scale = 0.08838834764831845f;

    // ---- stage Q (hi, lo) and pull fragments into registers ----
    #pragma unroll
    for (int t = 0; t < 2; t++) {
        const __half* src = t ? qlo : qhi;
        #pragma unroll
        for (int i = 0; i < 8; i++) {
            const int idx = i * 256 + tid;
            const int r = idx >> 4, gc = idx & 15;
            *(float4*)(sma + t * (128 * APITCH) + r * APITCH + gc * 16) =
                *(const float4*)(src + (size_t)(bq0 + r) * 2048 + h * 128 + gc * 8);
        }
    }
    __syncthreads();

    uint32_t qh[8][4], ql[8][4];
    {
        const uint32_t a_base = sb + (warp * 16 + (lane & 15)) * APITCH + (lane >> 4) * 16;
        #pragma unroll
        for (int kt = 0; kt < 8; kt++) {
            ldsm4(qh[kt], a_base + kt * 32);
            ldsm4(ql[kt], a_base + kt * 32 + 128 * APITCH);
        }
    }
    __syncthreads();    // smem now free for the K-tile ring

    const int s_ld = tid >> 4;
    const int gc_ld = tid & 15;
    const int hoff = h * 64 + (gc_ld & 7) * 8;
    const int roff = (gc_ld - 8) * 8;

    #define KISSUE(st, bk0_) do {                                             \
        const uint32_t bb = sb + (uint32_t)(st) * KTILEB;                     \
        _Pragma("unroll")                                                     \
        for (int i = 0; i < 4; i++) {                                         \
            const int s = s_ld + i * 16;                                      \
            const void* src = (gc_ld < 8)                                     \
                ? (const void*)(kvh + (size_t)((bk0_) + s) * 1024 + hoff)     \
                : (const void*)(krh + (size_t)((bk0_) + s) * 64 + roff);      \
            cp16(bb + s * APITCH + gc_ld * 16, src);                          \
        }                                                                     \
        cp_commit();                                                          \
    } while (0)

    float m_i[2] = {-1e30f, -1e30f};
    float l_i[2] = {0.f, 0.f};
    float o[8][4];
    #pragma unroll
    for (int j = 0; j < 8; j++)
        #pragma unroll
        for (int e = 0; e < 4; e++) o[j][e] = 0.f;

    const int g = lane >> 2, cq = lane & 3;
    const int rbase = q0 + warp * 16 + g;

    const int nk = 2 * qt + 2;
    KISSUE(0, b * T_);

    for (int c = 0; c < nk; c++) {
        cp_wait0();
        __syncthreads();
        if (c + 1 < nk) KISSUE((c + 1) & 1, b * T_ + (c + 1) * 64);

        const uint32_t kbuf = sb + (uint32_t)(c & 1) * KTILEB;

        // ---- S = Q K^T ----
        float cS[8][4];
        #pragma unroll
        for (int j = 0; j < 8; j++)
            #pragma unroll
            for (int e = 0; e < 4; e++) cS[j][e] = 0.f;

        const uint32_t b_base = kbuf + (((lane >> 4) << 3) + (lane & 7)) * APITCH
                              + ((lane >> 3) & 1) * 16;
        #pragma unroll
        for (int kt = 0; kt < 8; kt++) {
            #pragma unroll
            for (int np = 0; np < 4; np++) {
                uint32_t th[4];
                ldsm4(th, b_base + np * 16 * APITCH + kt * 32);
                const int j0 = 2 * np;
                mma_f16s(cS[j0],     qh[kt], th[0], th[1]);
                mma_f16s(cS[j0],     ql[kt], th[0], th[1]);
                mma_f16s(cS[j0 + 1], qh[kt], th[2], th[3]);
                mma_f16s(cS[j0 + 1], ql[kt], th[2], th[3]);
            }
        }

        // ---- scale + causal mask ----
        const int cbase = c * 64 + cq * 2;
        #pragma unroll
        for (int j = 0; j < 8; j++) {
            const int col = cbase + j * 8;
            cS[j][0] = (col     <= rbase)     ? cS[j][0] * scale : -3e30f;
            cS[j][1] = (col + 1 <= rbase)     ? cS[j][1] * scale : -3e30f;
            cS[j][2] = (col     <= rbase + 8) ? cS[j][2] * scale : -3e30f;
            cS[j][3] = (col + 1 <= rbase + 8) ? cS[j][3] * scale : -3e30f;
        }

        // ---- online softmax ----
        float mx0 = -3e30f, mx1 = -3e30f;
        #pragma unroll
        for (int j = 0; j < 8; j++) {
            mx0 = fmaxf(mx0, fmaxf(cS[j][0], cS[j][1]));
            mx1 = fmaxf(mx1, fmaxf(cS[j][2], cS[j][3]));
        }
        mx0 = fmaxf(mx0, __shfl_xor_sync(0xffffffffu, mx0, 1));
        mx0 = fmaxf(mx0, __shfl_xor_sync(0xffffffffu, mx0, 2));
        mx1 = fmaxf(mx1, __shfl_xor_sync(0xffffffffu, mx1, 1));
        mx1 = fmaxf(mx1, __shfl_xor_sync(0xffffffffu, mx1, 2));
        const float nm0 = fmaxf(m_i[0], mx0);
        const float nm1 = fmaxf(m_i[1], mx1);
        const float f0 = __expf(m_i[0] - nm0);
        const float f1 = __expf(m_i[1] - nm1);
        float s0 = 0.f, s1 = 0.f;
        #pragma unroll
        for (int j = 0; j < 8; j++) {
            cS[j][0] = __expf(cS[j][0] - nm0);
            cS[j][1] = __expf(cS[j][1] - nm0);
            cS[j][2] = __expf(cS[j][2] - nm1);
            cS[j][3] = __expf(cS[j][3] - nm1);
            s0 += cS[j][0] + cS[j][1];
            s1 += cS[j][2] + cS[j][3];
        }
        s0 += __shfl_xor_sync(0xffffffffu, s0, 1);
        s0 += __shfl_xor_sync(0xffffffffu, s0, 2);
        s1 += __shfl_xor_sync(0xffffffffu, s1, 1);
        s1 += __shfl_xor_sync(0xffffffffu, s1, 2);
        l_i[0] = l_i[0] * f0 + s0;  m_i[0] = nm0;
        l_i[1] = l_i[1] * f1 + s1;  m_i[1] = nm1;
        #pragma unroll
        for (int j = 0; j < 8; j++) {
            o[j][0] *= f0; o[j][1] *= f0;
            o[j][2] *= f1; o[j][3] *= f1;
        }

        // ---- O += P @ V (P split hi/lo, V single) ----
        const uint32_t v_row = ((lane & 7) + 8 * ((lane >> 3) & 1)) * APITCH
                             + (lane >> 4) * 16;
        #pragma unroll
        for (int ks = 0; ks < 4; ks++) {
            uint32_t ah[4], al[4];
            packsplit_h(cS[2 * ks][0],     cS[2 * ks][1],     ah[0], al[0]);
            packsplit_h(cS[2 * ks][2],     cS[2 * ks][3],     ah[1], al[1]);
            packsplit_h(cS[2 * ks + 1][0], cS[2 * ks + 1][1], ah[2], al[2]);
            packsplit_h(cS[2 * ks + 1][2], cS[2 * ks + 1][3], ah[3], al[3]);
            #pragma unroll
            for (int np = 0; np < 4; np++) {
                uint32_t th[4];
                ldsm4t(th, kbuf + v_row + ks * 16 * APITCH + np * 32);
                const int jd = 2 * np;
                mma_f16s(o[jd],     ah, th[0], th[1]);
                mma_f16s(o[jd],     al, th[0], th[1]);
                mma_f16s(o[jd + 1], ah, th[2], th[3]);
                mma_f16s(o[jd + 1], al, th[2], th[3]);
            }
        }
    }
    #undef KISSUE

    const float inv0 = 1.f / l_i[0];
    const float inv1 = 1.f / l_i[1];
    const size_t row0 = (size_t)(bq0 + warp * 16 + g);
    const size_t row1 = row0 + 8;
    #pragma unroll
    for (int j = 0; j < 8; j++) {
        const int col = h * 64 + j * 8 + cq * 2;
        uint32_t hi, lo;
        packsplit_h(o[j][0] * inv0, o[j][1] * inv0, hi, lo);
        *(uint32_t*)&yhi[row0 * 1024 + col] = hi;
        *(uint32_t*)&ylo[row0 * 1024 + col] = lo;
        packsplit_h(o[j][2] * inv1, o[j][3] * inv1, hi, lo);
        *(uint32_t*)&yhi[row1 * 1024 + col] = hi;
        *(uint32_t*)&ylo[row1 * 1024 + col] = lo;
    }
}

// ---------------------------------------------------------------------------
// Launch
// ---------------------------------------------------------------------------
extern "C" void kernel_launch(void* const* d_in, const int* in_sizes, int n_in,
                              void* d_out, int out_size)
{
    const float* x    = (const float*)d_in[0];
    const float* Wq   = (const float*)d_in[1];
    const float* Wkva = (const float*)d_in[2];
    const float* Wkvb = (const float*)d_in[3];
    const float* Wo   = (const float*)d_in[4];
    float* out = (float*)d_out;

    __half *xhi, *xlo, *qhi, *qlo, *ckvhi, *ckvlo, *yhi, *ylo;
    __half *kvh, *krh, *wq, *wa, *wb, *wo;
    cudaGetSymbolAddress((void**)&xhi, g_xhi);     cudaGetSymbolAddress((void**)&xlo, g_xlo);
    cudaGetSymbolAddress((void**)&qhi, g_qhi);     cudaGetSymbolAddress((void**)&qlo, g_qlo);
    cudaGetSymbolAddress((void**)&ckvhi, g_ckvhi); cudaGetSymbolAddress((void**)&ckvlo, g_ckvlo);
    cudaGetSymbolAddress((void**)&yhi, g_yhi);     cudaGetSymbolAddress((void**)&ylo, g_ylo);
    cudaGetSymbolAddress((void**)&kvh, g_kvh);     cudaGetSymbolAddress((void**)&krh, g_krh);
    cudaGetSymbolAddress((void**)&wq, g_wqt);      cudaGetSymbolAddress((void**)&wa, g_wkvat);
    cudaGetSymbolAddress((void**)&wb, g_wkvbt);    cudaGetSymbolAddress((void**)&wo, g_wot);

    cudaFuncSetAttribute(hmma_gemm<EPI_F32>,
                         cudaFuncAttributeMaxDynamicSharedMemorySize, GEMM_SMEM);
    cudaFuncSetAttribute(hmma_gemm<EPI_KV>,
                         cudaFuncAttributeMaxDynamicSharedMemorySize, GEMM_SMEM);
    cudaFuncSetAttribute(hmma_gemm<EPI_QCKV>,
                         cudaFuncAttributeMaxDynamicSharedMemorySize, GEMM_SMEM);
    cudaFuncSetAttribute(attn_hmma,
                         cudaFuncAttributeMaxDynamicSharedMemorySize, ATTN_SMEM);

    freq_init_kernel<<<1, 32>>>();

    const dim3 tb(32, 8);
    splitT_kernel<false><<<dim3(64, 64), tb>>>(Wq,   2048, 2048, wq, 2048);
    splitT_kernel<false><<<dim3(64, 20), tb>>>(Wkva,  576,  576, wa, 2048);
    splitT_kernel<false><<<dim3(16, 32), tb>>>(Wkvb, 1024, 1024, wb,  512);
    splitT_kernel<true ><<<dim3(32, 64), tb>>>(Wo,   2048, 2048, wo, 1024);
    split_kernel<<<8192, 256>>>(x, xhi, xlo, 4096 * 512);

    // merged: q = rope(x @ Wq) AND ckv = x @ Wkva (+ roped krh), one launch
    hmma_gemm<EPI_QCKV><<<dim3(21, 32), 256, GEMM_SMEM>>>(
        xhi, xlo, wq, wa, nullptr, qhi, qlo, ckvhi, ckvlo, krh,
        2048, 2048, 2048, 0);
    // kv = latent @ Wkvb -> kvh (single)
    hmma_gemm<EPI_KV><<<dim3(8, 32), 256, GEMM_SMEM>>>(
        ckvhi, ckvlo, wb, nullptr, nullptr, kvh, nullptr, nullptr, nullptr,
        nullptr, 512, 512, 512, 1024);
    // attention -> yhi/ylo
    attn_hmma<<<dim3(16, 16, 2), 256, ATTN_SMEM>>>(qhi, qlo, kvh, krh, yhi, ylo);
    // out = y @ gather(Wo)
    hmma_gemm<EPI_F32><<<dim3(16, 32), 256, GEMM_SMEM>>>(
        yhi, ylo, wo, nullptr, out, nullptr, nullptr, nullptr, nullptr,
        nullptr, 1024, 1024, 1024, 2048);
}

// round 13
// speedup vs baseline: 5.2085x; 1.1038x over previous
#include <cuda_runtime.h>
#include <cuda_fp16.h>
#include <math.h>
#include <stdint.h>

// Problem constants
#define B_    2
#define T_    2048
#define C_    2048
#define H_    16
#define HD_   128
#define LORA_ 512
#define RD_   64
#define ND_   64
#define BT_   (B_ * T_)   // 4096

// ---------------------------------------------------------------------------
// Scratch (static __device__ globals — allocation-free per harness rules)
// ---------------------------------------------------------------------------
__device__ float g_freq[32];

// activations
__device__ __align__(16) __half g_xhi[(size_t)BT_ * 2048],  g_xlo[(size_t)BT_ * 2048];
__device__ __align__(16) __half g_qh[(size_t)BT_ * 2048];                      // single fp16
__device__ __align__(16) __half g_ckvhi[(size_t)BT_ * 512], g_ckvlo[(size_t)BT_ * 512];
__device__ __align__(16) __half g_yhi[(size_t)BT_ * 1024],  g_ylo[(size_t)BT_ * 1024];
// K/V and weights: single fp16 (B operands)
__device__ __align__(16) __half g_kvh[(size_t)BT_ * 1024];
__device__ __align__(16) __half g_krh[(size_t)BT_ * 64];
__device__ __align__(16) __half g_wqt[(size_t)2048 * 2048];
__device__ __align__(16) __half g_wkvat[(size_t)640 * 2048];
__device__ __align__(16) __half g_wkvbt[(size_t)1024 * 512];
__device__ __align__(16) __half g_wot[(size_t)2048 * 1024];

// ---------------------------------------------------------------------------
// RoPE frequency table (exact formula as reference)
// ---------------------------------------------------------------------------
__global__ void freq_init_kernel() {
    const int i = threadIdx.x;
    if (i < 32) g_freq[i] = (float)pow(100000.0, -(double)i / 32.0);
}

// ---------------------------------------------------------------------------
// fp32 -> fp16 hi/lo split (for x)
// ---------------------------------------------------------------------------
__global__ void split_kernel(const float* __restrict__ in,
                             __half* __restrict__ hi, __half* __restrict__ lo,
                             int total4)
{
    const int idx = blockIdx.x * blockDim.x + threadIdx.x;
    if (idx >= total4) return;
    const float4 v = *(const float4*)&in[(size_t)idx * 4];
    float f[4] = {v.x, v.y, v.z, v.w};
    ushort4 hv, lv;
    unsigned short* hp = &hv.x;
    unsigned short* lp = &lv.x;
    #pragma unroll
    for (int i = 0; i < 4; i++) {
        __half h = __float2half_rn(f[i]);
        __half l = __float2half_rn(f[i] - __half2float(h));
        hp[i] = __half_as_ushort(h);
        lp[i] = __half_as_ushort(l);
    }
    *(ushort4*)&hi[(size_t)idx * 4] = hv;
    *(ushort4*)&lo[(size_t)idx * 4] = lv;
}

// ---------------------------------------------------------------------------
// fp32 W[k][n] -> single fp16 out[n][k] (transpose + optional gather + pad)
// ---------------------------------------------------------------------------
template <bool GATHER>
__global__ void splitT_kernel(const float* __restrict__ W, int ldw, int nIn,
                              __half* __restrict__ out, int kDim)
{
    __shared__ float tile[32][33];
    const int k0 = blockIdx.x * 32, n0 = blockIdx.y * 32;
    #pragma unroll
    for (int i = threadIdx.y; i < 32; i += 8) {
        const int k = k0 + i;
        const int row = GATHER ? (((k >> 6) << 7) + (k & 63)) : k;
        const int n = n0 + threadIdx.x;
        tile[i][threadIdx.x] = (n < nIn) ? W[(size_t)row * ldw + n] : 0.f;
    }
    __syncthreads();
    #pragma unroll
    for (int i = threadIdx.y; i < 32; i += 8) {
        const int n = n0 + i, k = k0 + threadIdx.x;
        out[(size_t)n * kDim + k] = __float2half_rn(tile[threadIdx.x][i]);
    }
}

// ---------------------------------------------------------------------------
// Shared HMMA helpers (fp16)
// ---------------------------------------------------------------------------
__device__ __forceinline__ uint32_t smem_u32(const void* p) {
    uint32_t a;
    asm("{ .reg .u64 t; cvta.to.shared.u64 t, %1; cvt.u32.u64 %0, t; }"
        : "=r"(a) : "l"(p));
    return a;
}
__device__ __forceinline__ void cp16(uint32_t dst, const void* src) {
    asm volatile("cp.async.cg.shared.global [%0], [%1], 16;"
                 :: "r"(dst), "l"(src) : "memory");
}
__device__ __forceinline__ void cp_commit() {
    asm volatile("cp.async.commit_group;" ::: "memory");
}
__device__ __forceinline__ void cp_wait0() {
    asm volatile("cp.async.wait_group 0;" ::: "memory");
}
__device__ __forceinline__ void ldsm4(uint32_t r[4], uint32_t addr) {
    asm volatile("ldmatrix.sync.aligned.m8n8.x4.shared.b16 {%0,%1,%2,%3}, [%4];"
                 : "=r"(r[0]), "=r"(r[1]), "=r"(r[2]), "=r"(r[3]) : "r"(addr));
}
__device__ __forceinline__ void ldsm4t(uint32_t r[4], uint32_t addr) {
    asm volatile("ldmatrix.sync.aligned.m8n8.x4.trans.shared.b16 {%0,%1,%2,%3}, [%4];"
                 : "=r"(r[0]), "=r"(r[1]), "=r"(r[2]), "=r"(r[3]) : "r"(addr));
}
__device__ __forceinline__ void mma_f16(float c[4], const uint32_t a[4],
                                        const uint32_t b[2]) {
    asm volatile(
        "mma.sync.aligned.m16n8k16.row.col.f32.f16.f16.f32 "
        "{%0,%1,%2,%3}, {%4,%5,%6,%7}, {%8,%9}, {%0,%1,%2,%3};"
        : "+f"(c[0]), "+f"(c[1]), "+f"(c[2]), "+f"(c[3])
        : "r"(a[0]), "r"(a[1]), "r"(a[2]), "r"(a[3]), "r"(b[0]), "r"(b[1]));
}
__device__ __forceinline__ void mma_f16s(float c[4], const uint32_t a[4],
                                         uint32_t b0, uint32_t b1) {
    asm volatile(
        "mma.sync.aligned.m16n8k16.row.col.f32.f16.f16.f32 "
        "{%0,%1,%2,%3}, {%4,%5,%6,%7}, {%8,%9}, {%0,%1,%2,%3};"
        : "+f"(c[0]), "+f"(c[1]), "+f"(c[2]), "+f"(c[3])
        : "r"(a[0]), "r"(a[1]), "r"(a[2]), "r"(a[3]), "r"(b0), "r"(b1));
}
__device__ __forceinline__ void packsplit_h(float c0, float c1,
                                            uint32_t& hi, uint32_t& lo) {
    __half h0 = __float2half_rn(c0);
    __half h1 = __float2half_rn(c1);
    __half l0 = __float2half_rn(c0 - __half2float(h0));
    __half l1 = __float2half_rn(c1 - __half2float(h1));
    hi = ((uint32_t)__half_as_ushort(h1) << 16) | __half_as_ushort(h0);
    lo = ((uint32_t)__half_as_ushort(l1) << 16) | __half_as_ushort(l0);
}
__device__ __forceinline__ uint32_t packh(float c0, float c1) {
    return ((uint32_t)__half_as_ushort(__float2half_rn(c1)) << 16)
         | __half_as_ushort(__float2half_rn(c0));
}

// ---------------------------------------------------------------------------
// Epilogue modes
// ---------------------------------------------------------------------------
#define EPI_F32   0
#define EPI_KV    1
#define EPI_Q     2
#define EPI_CKV   3
#define EPI_QCKV  4

template <int EPI>
__device__ __forceinline__ void epi_store(int row, int col, float v0, float v1,
    float* __restrict__ Cf,
    __half* __restrict__ O1, __half* __restrict__ O2,
    __half* __restrict__ O3, int ldc)
{
    if (EPI == EPI_F32) {
        *(float2*)&Cf[(size_t)row * ldc + col] = make_float2(v0, v1);
    } else if (EPI == EPI_KV) {
        *(uint32_t*)&O1[(size_t)row * ldc + col] = packh(v0, v1);
    } else if (EPI == EPI_Q) {
        const int d = col & 127;
        if (d >= 64) {
            const float freq = g_freq[(d - 64) >> 1];
            float s, c;
            sincosf((float)(row & (T_ - 1)) * freq, &s, &c);
            const float t0 = v0 * c - v1 * s;
            const float t1 = v0 * s + v1 * c;
            v0 = t0; v1 = t1;
        }
        *(uint32_t*)&O1[(size_t)row * 2048 + col] = packh(v0, v1);   // single fp16
    } else if (EPI == EPI_CKV) {
        if (col < 512) {
            uint32_t h, l;
            packsplit_h(v0, v1, h, l);
            *(uint32_t*)&O1[(size_t)row * 512 + col] = h;
            *(uint32_t*)&O2[(size_t)row * 512 + col] = l;
        } else if (col < 576) {
            const float freq = g_freq[(col - 512) >> 1];
            float s, c;
            sincosf((float)(row & (T_ - 1)) * freq, &s, &c);
            *(uint32_t*)&O3[(size_t)row * 64 + (col - 512)] =
                packh(v0 * c - v1 * s, v0 * s + v1 * c);
        }
    }
}

// ---------------------------------------------------------------------------
// HMMA fp16 asymmetric-split GEMM (unchanged from R12)
// ---------------------------------------------------------------------------
#define ROWB   80
#define TILEB  (128 * ROWB)     // 10240
#define STAGEB (3 * TILEB)      // 30720 (Ahi, Alo, B)
#define GEMM_SMEM (2 * STAGEB)  // 61440

template <int EPI>
__global__ __launch_bounds__(256)
void hmma_gemm(const __half* __restrict__ Ahi, const __half* __restrict__ Alo,
               const __half* __restrict__ Bm, const __half* __restrict__ Balt,
               float* __restrict__ Cf,
               __half* __restrict__ O1, __half* __restrict__ O2,
               __half* __restrict__ O3, __half* __restrict__ O4,
               __half* __restrict__ O5,
               int K, int lda, int ldb, int ldc)
{
    extern __shared__ char smc[];
    const uint32_t sb = smem_u32(smc);
    const int tid = threadIdx.x;
    const int lane = tid & 31, warp = tid >> 5;
    const int wm = warp >> 2, wn = warp & 3;
    const int m0 = blockIdx.y * 128;

    bool isQ = true;
    const __half* Bu = Bm;
    int n0 = blockIdx.x * 128;
    if (EPI == EPI_QCKV && blockIdx.x >= 16) {
        isQ = false;
        Bu = Balt;
        n0 = (blockIdx.x - 16) * 128;
    }

    const int r_ld = tid >> 2;
    const int cc = tid & 3;
    const __half* pAh0 = Ahi + (size_t)(m0 + r_ld) * lda + cc * 8;
    const __half* pAh1 = Ahi + (size_t)(m0 + r_ld + 64) * lda + cc * 8;
    const __half* pAl0 = Alo + (size_t)(m0 + r_ld) * lda + cc * 8;
    const __half* pAl1 = Alo + (size_t)(m0 + r_ld + 64) * lda + cc * 8;
    const __half* pB0  = Bu  + (size_t)(n0 + r_ld) * ldb + cc * 8;
    const __half* pB1  = Bu  + (size_t)(n0 + r_ld + 64) * ldb + cc * 8;
    const uint32_t d0 = r_ld * ROWB + cc * 16;
    const uint32_t d1 = (r_ld + 64) * ROWB + cc * 16;

    #define ISSUE(st, k0_) do {                                               \
        const uint32_t bb = sb + (uint32_t)(st) * STAGEB;                     \
        cp16(bb + 0 * TILEB + d0, pAh0 + (k0_));                              \
        cp16(bb + 0 * TILEB + d1, pAh1 + (k0_));                              \
        cp16(bb + 1 * TILEB + d0, pAl0 + (k0_));                              \
        cp16(bb + 1 * TILEB + d1, pAl1 + (k0_));                              \
        cp16(bb + 2 * TILEB + d0, pB0 + (k0_));                               \
        cp16(bb + 2 * TILEB + d1, pB1 + (k0_));                               \
        cp_commit();                                                          \
    } while (0)

    float c[4][4][4];
    #pragma unroll
    for (int i = 0; i < 4; i++)
        #pragma unroll
        for (int j = 0; j < 4; j++)
            #pragma unroll
            for (int l = 0; l < 4; l++) c[i][j][l] = 0.f;

    const uint32_t a_row = wm * 64 + (lane & 15);
    const uint32_t a_koff = (lane >> 4) * 16;
    const uint32_t b_row = wn * 32 + ((lane >> 4) << 3) + (lane & 7);
    const uint32_t b_koff = ((lane >> 3) & 1) * 16;

    const int niter = K >> 5;
    ISSUE(0, 0);

    for (int it = 0; it < niter; it++) {
        cp_wait0();
        __syncthreads();
        if (it + 1 < niter) ISSUE((it + 1) & 1, (it + 1) << 5);

        const uint32_t buf = sb + (uint32_t)(it & 1) * STAGEB;
        #pragma unroll
        for (int ks = 0; ks < 2; ks++) {
            const uint32_t kb = ks * 32;
            uint32_t afh[4][4], afl[4][4], bf[4][2];
            #pragma unroll
            for (int mt = 0; mt < 4; mt++) {
                const uint32_t ad = buf + (a_row + mt * 16) * ROWB + kb + a_koff;
                ldsm4(afh[mt], ad + 0 * TILEB);
                ldsm4(afl[mt], ad + 1 * TILEB);
            }
            #pragma unroll
            for (int np = 0; np < 2; np++) {
                const uint32_t bd = buf + (b_row + np * 16) * ROWB + kb + b_koff;
                uint32_t t[4];
                ldsm4(t, bd + 2 * TILEB);
                bf[np * 2][0] = t[0]; bf[np * 2][1] = t[1];
                bf[np * 2 + 1][0] = t[2]; bf[np * 2 + 1][1] = t[3];
            }
            #pragma unroll
            for (int mt = 0; mt < 4; mt++)
                #pragma unroll
                for (int nt = 0; nt < 4; nt++) {
                    mma_f16(c[mt][nt], afh[mt], bf[nt]);
                    mma_f16(c[mt][nt], afl[mt], bf[nt]);
                }
        }
    }
    #undef ISSUE

    #pragma unroll
    for (int mt = 0; mt < 4; mt++) {
        const int row = m0 + wm * 64 + mt * 16 + (lane >> 2);
        #pragma unroll
        for (int nt = 0; nt < 4; nt++) {
            const int col = n0 + wn * 32 + nt * 8 + (lane & 3) * 2;
            if (EPI == EPI_QCKV) {
                if (isQ) {
                    epi_store<EPI_Q>(row,     col, c[mt][nt][0], c[mt][nt][1],
                                     nullptr, O1, O2, nullptr, 0);
                    epi_store<EPI_Q>(row + 8, col, c[mt][nt][2], c[mt][nt][3],
                                     nullptr, O1, O2, nullptr, 0);
                } else {
                    epi_store<EPI_CKV>(row,     col, c[mt][nt][0], c[mt][nt][1],
                                       nullptr, O3, O4, O5, 0);
                    epi_store<EPI_CKV>(row + 8, col, c[mt][nt][2], c[mt][nt][3],
                                       nullptr, O3, O4, O5, 0);
                }
            } else {
                epi_store<EPI>(row,     col, c[mt][nt][0], c[mt][nt][1],
                               Cf, O1, O2, O3, ldc);
                epi_store<EPI>(row + 8, col, c[mt][nt][2], c[mt][nt][3],
                               Cf, O1, O2, O3, ldc);
            }
        }
    }
}

// ---------------------------------------------------------------------------
// HMMA flash attention (causal), single-fp16 Q and P (lo terms dropped).
// Q frags in registers; K/V single fp16 ring; LPT block order.
// ---------------------------------------------------------------------------
#define APITCH 272
#define KTILEB (64 * APITCH)                 // 17408 (single K/V tile)
#define ATTN_SMEM (2 * KTILEB)               // 34816 (= Q staging, reused as ring)

__global__ __launch_bounds__(256)
void attn_hmma(const __half* __restrict__ qhg,
               const __half* __restrict__ kvh, const __half* __restrict__ krh,
               __half* __restrict__ yhi, __half* __restrict__ ylo)
{
    extern __shared__ char sma[];
    const uint32_t sb = smem_u32(sma);
    const int tid = threadIdx.x;
    const int lane = tid & 31, warp = tid >> 5;
    const int qt = (int)gridDim.x - 1 - (int)blockIdx.x;   // big work first
    const int h = blockIdx.y, b = blockIdx.z;
    const int q0 = qt * 128;
    const int bq0 = b * T_ + q0;
    const float scale = 0.08838834764831845f;

    // ---- stage Q (single) and pull fragments into registers ----
    #pragma unroll
    for (int i = 0; i < 8; i++) {
        const int idx = i * 256 + tid;
        const int r = idx >> 4, gc = idx & 15;
        *(float4*)(sma + r * APITCH + gc * 16) =
            *(const float4*)(qhg + (size_t)(bq0 + r) * 2048 + h * 128 + gc * 8);
    }
    __syncthreads();

    uint32_t qh[8][4];
    {
        const uint32_t a_base = sb + (warp * 16 + (lane & 15)) * APITCH + (lane >> 4) * 16;
        #pragma unroll
        for (int kt = 0; kt < 8; kt++)
            ldsm4(qh[kt], a_base + kt * 32);
    }
    __syncthreads();    // smem now free for the K-tile ring

    const int s_ld = tid >> 4;
    const int gc_ld = tid & 15;
    const int hoff = h * 64 + (gc_ld & 7) * 8;
    const int roff = (gc_ld - 8) * 8;

    #define KISSUE(st, bk0_) do {                                             \
        const uint32_t bb = sb + (uint32_t)(st) * KTILEB;                     \
        _Pragma("unroll")                                                     \
        for (int i = 0; i < 4; i++) {                                         \
            const int s = s_ld + i * 16;                                      \
            const void* src = (gc_ld < 8)                                     \
                ? (const void*)(kvh + (size_t)((bk0_) + s) * 1024 + hoff)     \
                : (const void*)(krh + (size_t)((bk0_) + s) * 64 + roff);      \
            cp16(bb + s * APITCH + gc_ld * 16, src);                          \
        }                                                                     \
        cp_commit();                                                          \
    } while (0)

    float m_i[2] = {-1e30f, -1e30f};
    float l_i[2] = {0.f, 0.f};
    float o[8][4];
    #pragma unroll
    for (int j = 0; j < 8; j++)
        #pragma unroll
        for (int e = 0; e < 4; e++) o[j][e] = 0.f;

    const int g = lane >> 2, cq = lane & 3;
    const int rbase = q0 + warp * 16 + g;

    const int nk = 2 * qt + 2;
    KISSUE(0, b * T_);

    for (int c = 0; c < nk; c++) {
        cp_wait0();
        __syncthreads();
        if (c + 1 < nk) KISSUE((c + 1) & 1, b * T_ + (c + 1) * 64);

        const uint32_t kbuf = sb + (uint32_t)(c & 1) * KTILEB;

        // ---- S = Q K^T (single-precision Q) ----
        float cS[8][4];
        #pragma unroll
        for (int j = 0; j < 8; j++)
            #pragma unroll
            for (int e = 0; e < 4; e++) cS[j][e] = 0.f;

        const uint32_t b_base = kbuf + (((lane >> 4) << 3) + (lane & 7)) * APITCH
                              + ((lane >> 3) & 1) * 16;
        #pragma unroll
        for (int kt = 0; kt < 8; kt++) {
            #pragma unroll
            for (int np = 0; np < 4; np++) {
                uint32_t th[4];
                ldsm4(th, b_base + np * 16 * APITCH + kt * 32);
                const int j0 = 2 * np;
                mma_f16s(cS[j0],     qh[kt], th[0], th[1]);
                mma_f16s(cS[j0 + 1], qh[kt], th[2], th[3]);
            }
        }

        // ---- scale + causal mask ----
        const int cbase = c * 64 + cq * 2;
        #pragma unroll
        for (int j = 0; j < 8; j++) {
            const int col = cbase + j * 8;
            cS[j][0] = (col     <= rbase)     ? cS[j][0] * scale : -3e30f;
            cS[j][1] = (col + 1 <= rbase)     ? cS[j][1] * scale : -3e30f;
            cS[j][2] = (col     <= rbase + 8) ? cS[j][2] * scale : -3e30f;
            cS[j][3] = (col + 1 <= rbase + 8) ? cS[j][3] * scale : -3e30f;
        }

        // ---- online softmax ----
        float mx0 = -3e30f, mx1 = -3e30f;
        #pragma unroll
        for (int j = 0; j < 8; j++) {
            mx0 = fmaxf(mx0, fmaxf(cS[j][0], cS[j][1]));
            mx1 = fmaxf(mx1, fmaxf(cS[j][2], cS[j][3]));
        }
        mx0 = fmaxf(mx0, __shfl_xor_sync(0xffffffffu, mx0, 1));
        mx0 = fmaxf(mx0, __shfl_xor_sync(0xffffffffu, mx0, 2));
        mx1 = fmaxf(mx1, __shfl_xor_sync(0xffffffffu, mx1, 1));
        mx1 = fmaxf(mx1, __shfl_xor_sync(0xffffffffu, mx1, 2));
        const float nm0 = fmaxf(m_i[0], mx0);
        const float nm1 = fmaxf(m_i[1], mx1);
        const float f0 = __expf(m_i[0] - nm0);
        const float f1 = __expf(m_i[1] - nm1);
        float s0 = 0.f, s1 = 0.f;
        #pragma unroll
        for (int j = 0; j < 8; j++) {
            cS[j][0] = __expf(cS[j][0] - nm0);
            cS[j][1] = __expf(cS[j][1] - nm0);
            cS[j][2] = __expf(cS[j][2] - nm1);
            cS[j][3] = __expf(cS[j][3] - nm1);
            s0 += cS[j][0] + cS[j][1];
            s1 += cS[j][2] + cS[j][3];
        }
        s0 += __shfl_xor_sync(0xffffffffu, s0, 1);
        s0 += __shfl_xor_sync(0xffffffffu, s0, 2);
        s1 += __shfl_xor_sync(0xffffffffu, s1, 1);
        s1 += __shfl_xor_sync(0xffffffffu, s1, 2);
        l_i[0] = l_i[0] * f0 + s0;  m_i[0] = nm0;
        l_i[1] = l_i[1] * f1 + s1;  m_i[1] = nm1;
        #pragma unroll
        for (int j = 0; j < 8; j++) {
            o[j][0] *= f0; o[j][1] *= f0;
            o[j][2] *= f1; o[j][3] *= f1;
        }

        // ---- O += P @ V (single-precision P) ----
        const uint32_t v_row = ((lane & 7) + 8 * ((lane >> 3) & 1)) * APITCH
                             + (lane >> 4) * 16;
        #pragma unroll
        for (int ks = 0; ks < 4; ks++) {
            uint32_t ah[4];
            ah[0] = packh(cS[2 * ks][0],     cS[2 * ks][1]);
            ah[1] = packh(cS[2 * ks][2],     cS[2 * ks][3]);
            ah[2] = packh(cS[2 * ks + 1][0], cS[2 * ks + 1][1]);
            ah[3] = packh(cS[2 * ks + 1][2], cS[2 * ks + 1][3]);
            #pragma unroll
            for (int np = 0; np < 4; np++) {
                uint32_t th[4];
                ldsm4t(th, kbuf + v_row + ks * 16 * APITCH + np * 32);
                const int jd = 2 * np;
                mma_f16s(o[jd],     ah, th[0], th[1]);
                mma_f16s(o[jd + 1], ah, th[2], th[3]);
            }
        }
    }
    #undef KISSUE

    const float inv0 = 1.f / l_i[0];
    const float inv1 = 1.f / l_i[1];
    const size_t row0 = (size_t)(bq0 + warp * 16 + g);
    const size_t row1 = row0 + 8;
    #pragma unroll
    for (int j = 0; j < 8; j++) {
        const int col = h * 64 + j * 8 + cq * 2;
        uint32_t hi, lo;
        packsplit_h(o[j][0] * inv0, o[j][1] * inv0, hi, lo);
        *(uint32_t*)&yhi[row0 * 1024 + col] = hi;
        *(uint32_t*)&ylo[row0 * 1024 + col] = lo;
        packsplit_h(o[j][2] * inv1, o[j][3] * inv1, hi, lo);
        *(uint32_t*)&yhi[row1 * 1024 + col] = hi;
        *(uint32_t*)&ylo[row1 * 1024 + col] = lo;
    }
}

// ---------------------------------------------------------------------------
// Launch
// ---------------------------------------------------------------------------
extern "C" void kernel_launch(void* const* d_in, const int* in_sizes, int n_in,
                              void* d_out, int out_size)
{
    const float* x    = (const float*)d_in[0];
    const float* Wq   = (const float*)d_in[1];
    const float* Wkva = (const float*)d_in[2];
    const float* Wkvb = (const float*)d_in[3];
    const float* Wo   = (const float*)d_in[4];
    float* out = (float*)d_out;

    __half *xhi, *xlo, *qh, *ckvhi, *ckvlo, *yhi, *ylo;
    __half *kvh, *krh, *wq, *wa, *wb, *wo;
    cudaGetSymbolAddress((void**)&xhi, g_xhi);     cudaGetSymbolAddress((void**)&xlo, g_xlo);
    cudaGetSymbolAddress((void**)&qh, g_qh);
    cudaGetSymbolAddress((void**)&ckvhi, g_ckvhi); cudaGetSymbolAddress((void**)&ckvlo, g_ckvlo);
    cudaGetSymbolAddress((void**)&yhi, g_yhi);     cudaGetSymbolAddress((void**)&ylo, g_ylo);
    cudaGetSymbolAddress((void**)&kvh, g_kvh);     cudaGetSymbolAddress((void**)&krh, g_krh);
    cudaGetSymbolAddress((void**)&wq, g_wqt);      cudaGetSymbolAddress((void**)&wa, g_wkvat);
    cudaGetSymbolAddress((void**)&wb, g_wkvbt);    cudaGetSymbolAddress((void**)&wo, g_wot);

    cudaFuncSetAttribute(hmma_gemm<EPI_F32>,
                         cudaFuncAttributeMaxDynamicSharedMemorySize, GEMM_SMEM);
    cudaFuncSetAttribute(hmma_gemm<EPI_KV>,
                         cudaFuncAttributeMaxDynamicSharedMemorySize, GEMM_SMEM);
    cudaFuncSetAttribute(hmma_gemm<EPI_QCKV>,
                         cudaFuncAttributeMaxDynamicSharedMemorySize, GEMM_SMEM);
    cudaFuncSetAttribute(attn_hmma,
                         cudaFuncAttributeMaxDynamicSharedMemorySize, ATTN_SMEM);

    freq_init_kernel<<<1, 32>>>();

    const dim3 tb(32, 8);
    splitT_kernel<false><<<dim3(64, 64), tb>>>(Wq,   2048, 2048, wq, 2048);
    splitT_kernel<false><<<dim3(64, 20), tb>>>(Wkva,  576,  576, wa, 2048);
    splitT_kernel<false><<<dim3(16, 32), tb>>>(Wkvb, 1024, 1024, wb,  512);
    splitT_kernel<true ><<<dim3(32, 64), tb>>>(Wo,   2048, 2048, wo, 1024);
    split_kernel<<<8192, 256>>>(x, xhi, xlo, 4096 * 512);

    // merged: q = rope(x @ Wq) (single fp16) AND ckv = x @ Wkva (+ roped krh)
    hmma_gemm<EPI_QCKV><<<dim3(21, 32), 256, GEMM_SMEM>>>(
        xhi, xlo, wq, wa, nullptr, qh, nullptr, ckvhi, ckvlo, krh,
        2048, 2048, 2048, 0);
    // kv = latent @ Wkvb -> kvh (single)
    hmma_gemm<EPI_KV><<<dim3(8, 32), 256, GEMM_SMEM>>>(
        ckvhi, ckvlo, wb, nullptr, nullptr, kvh, nullptr, nullptr, nullptr,
        nullptr, 512, 512, 512, 1024);
    // attention -> yhi/ylo
    attn_hmma<<<dim3(16, 16, 2), 256, ATTN_SMEM>>>(qh, kvh, krh, yhi, ylo);
    // out = y @ gather(Wo)
    hmma_gemm<EPI_F32><<<dim3(16, 32), 256, GEMM_SMEM>>>(
        yhi, ylo, wo, nullptr, out, nullptr, nullptr, nullptr, nullptr,
        nullptr, 1024, 1024, 1024, 2048);
}

// round 14
// speedup vs baseline: 7.4436x; 1.4291x over previous
#include <cuda_runtime.h>
#include <cuda_fp16.h>
#include <math.h>
#include <stdint.h>

// Problem constants
#define B_    2
#define T_    2048
#define C_    2048
#define H_    16
#define HD_   128
#define LORA_ 512
#define RD_   64
#define ND_   64
#define BT_   (B_ * T_)   // 4096

// ---------------------------------------------------------------------------
// Scratch (static __device__ globals — allocation-free per harness rules)
// ---------------------------------------------------------------------------
__device__ float g_freq[32];

// all operands single fp16 (fp32 accumulate in MMA)
__device__ __align__(16) __half g_xh[(size_t)BT_ * 2048];
__device__ __align__(16) __half g_qh[(size_t)BT_ * 2048];
__device__ __align__(16) __half g_ckvh[(size_t)BT_ * 512];
__device__ __align__(16) __half g_yh[(size_t)BT_ * 1024];
__device__ __align__(16) __half g_kvh[(size_t)BT_ * 1024];
__device__ __align__(16) __half g_krh[(size_t)BT_ * 64];
__device__ __align__(16) __half g_wqt[(size_t)2048 * 2048];
__device__ __align__(16) __half g_wkvat[(size_t)640 * 2048];
__device__ __align__(16) __half g_wkvbt[(size_t)1024 * 512];
__device__ __align__(16) __half g_wot[(size_t)2048 * 1024];

// ---------------------------------------------------------------------------
// RoPE frequency table (exact formula as reference)
// ---------------------------------------------------------------------------
__global__ void freq_init_kernel() {
    const int i = threadIdx.x;
    if (i < 32) g_freq[i] = (float)pow(100000.0, -(double)i / 32.0);
}

// ---------------------------------------------------------------------------
// fp32 -> fp16 convert (for x)
// ---------------------------------------------------------------------------
__global__ void convert_kernel(const float* __restrict__ in,
                               __half* __restrict__ out, int total4)
{
    const int idx = blockIdx.x * blockDim.x + threadIdx.x;
    if (idx >= total4) return;
    const float4 v = *(const float4*)&in[(size_t)idx * 4];
    ushort4 hv;
    hv.x = __half_as_ushort(__float2half_rn(v.x));
    hv.y = __half_as_ushort(__float2half_rn(v.y));
    hv.z = __half_as_ushort(__float2half_rn(v.z));
    hv.w = __half_as_ushort(__float2half_rn(v.w));
    *(ushort4*)&out[(size_t)idx * 4] = hv;
}

// ---------------------------------------------------------------------------
// fp32 W[k][n] -> fp16 out[n][k] (transpose + optional gather + pad)
// ---------------------------------------------------------------------------
template <bool GATHER>
__global__ void splitT_kernel(const float* __restrict__ W, int ldw, int nIn,
                              __half* __restrict__ out, int kDim)
{
    __shared__ float tile[32][33];
    const int k0 = blockIdx.x * 32, n0 = blockIdx.y * 32;
    #pragma unroll
    for (int i = threadIdx.y; i < 32; i += 8) {
        const int k = k0 + i;
        const int row = GATHER ? (((k >> 6) << 7) + (k & 63)) : k;
        const int n = n0 + threadIdx.x;
        tile[i][threadIdx.x] = (n < nIn) ? W[(size_t)row * ldw + n] : 0.f;
    }
    __syncthreads();
    #pragma unroll
    for (int i = threadIdx.y; i < 32; i += 8) {
        const int n = n0 + i, k = k0 + threadIdx.x;
        out[(size_t)n * kDim + k] = __float2half_rn(tile[threadIdx.x][i]);
    }
}

// ---------------------------------------------------------------------------
// Shared HMMA helpers (fp16)
// ---------------------------------------------------------------------------
__device__ __forceinline__ uint32_t smem_u32(const void* p) {
    uint32_t a;
    asm("{ .reg .u64 t; cvta.to.shared.u64 t, %1; cvt.u32.u64 %0, t; }"
        : "=r"(a) : "l"(p));
    return a;
}
__device__ __forceinline__ void cp16(uint32_t dst, const void* src) {
    asm volatile("cp.async.cg.shared.global [%0], [%1], 16;"
                 :: "r"(dst), "l"(src) : "memory");
}
__device__ __forceinline__ void cp_commit() {
    asm volatile("cp.async.commit_group;" ::: "memory");
}
__device__ __forceinline__ void cp_wait0() {
    asm volatile("cp.async.wait_group 0;" ::: "memory");
}
__device__ __forceinline__ void ldsm4(uint32_t r[4], uint32_t addr) {
    asm volatile("ldmatrix.sync.aligned.m8n8.x4.shared.b16 {%0,%1,%2,%3}, [%4];"
                 : "=r"(r[0]), "=r"(r[1]), "=r"(r[2]), "=r"(r[3]) : "r"(addr));
}
__device__ __forceinline__ void ldsm4t(uint32_t r[4], uint32_t addr) {
    asm volatile("ldmatrix.sync.aligned.m8n8.x4.trans.shared.b16 {%0,%1,%2,%3}, [%4];"
                 : "=r"(r[0]), "=r"(r[1]), "=r"(r[2]), "=r"(r[3]) : "r"(addr));
}
__device__ __forceinline__ void mma_f16(float c[4], const uint32_t a[4],
                                        const uint32_t b[2]) {
    asm volatile(
        "mma.sync.aligned.m16n8k16.row.col.f32.f16.f16.f32 "
        "{%0,%1,%2,%3}, {%4,%5,%6,%7}, {%8,%9}, {%0,%1,%2,%3};"
        : "+f"(c[0]), "+f"(c[1]), "+f"(c[2]), "+f"(c[3])
        : "r"(a[0]), "r"(a[1]), "r"(a[2]), "r"(a[3]), "r"(b[0]), "r"(b[1]));
}
__device__ __forceinline__ void mma_f16s(float c[4], const uint32_t a[4],
                                         uint32_t b0, uint32_t b1) {
    asm volatile(
        "mma.sync.aligned.m16n8k16.row.col.f32.f16.f16.f32 "
        "{%0,%1,%2,%3}, {%4,%5,%6,%7}, {%8,%9}, {%0,%1,%2,%3};"
        : "+f"(c[0]), "+f"(c[1]), "+f"(c[2]), "+f"(c[3])
        : "r"(a[0]), "r"(a[1]), "r"(a[2]), "r"(a[3]), "r"(b0), "r"(b1));
}
__device__ __forceinline__ uint32_t packh(float c0, float c1) {
    return ((uint32_t)__half_as_ushort(__float2half_rn(c1)) << 16)
         | __half_as_ushort(__float2half_rn(c0));
}

// ---------------------------------------------------------------------------
// Epilogue modes
// ---------------------------------------------------------------------------
#define EPI_F32   0
#define EPI_KV    1
#define EPI_Q     2
#define EPI_CKV   3
#define EPI_QCKV  4

template <int EPI>
__device__ __forceinline__ void epi_store(int row, int col, float v0, float v1,
    float* __restrict__ Cf,
    __half* __restrict__ O1, __half* __restrict__ O2, int ldc)
{
    if (EPI == EPI_F32) {
        *(float2*)&Cf[(size_t)row * ldc + col] = make_float2(v0, v1);
    } else if (EPI == EPI_KV) {
        *(uint32_t*)&O1[(size_t)row * ldc + col] = packh(v0, v1);
    } else if (EPI == EPI_Q) {
        const int d = col & 127;
        if (d >= 64) {
            const float freq = g_freq[(d - 64) >> 1];
            float s, c;
            sincosf((float)(row & (T_ - 1)) * freq, &s, &c);
            const float t0 = v0 * c - v1 * s;
            const float t1 = v0 * s + v1 * c;
            v0 = t0; v1 = t1;
        }
        *(uint32_t*)&O1[(size_t)row * 2048 + col] = packh(v0, v1);
    } else if (EPI == EPI_CKV) {
        if (col < 512) {
            *(uint32_t*)&O1[(size_t)row * 512 + col] = packh(v0, v1);
        } else if (col < 576) {
            const float freq = g_freq[(col - 512) >> 1];
            float s, c;
            sincosf((float)(row & (T_ - 1)) * freq, &s, &c);
            *(uint32_t*)&O2[(size_t)row * 64 + (col - 512)] =
                packh(v0 * c - v1 * s, v0 * s + v1 * c);
        }
    }
}

// ---------------------------------------------------------------------------
// HMMA fp16 GEMM (single precision operands, fp32 accumulate):
//   C[M,N] = A[M,K] @ B[N,K]^T
// CTA 128x128, 8 warps of 64x32, BK=32, cp.async double buffer.
// EPI_QCKV: merged q+ckv launch — grid.x=21; blocks 0-15 use Bm (Wq, EPI_Q),
//           blocks 16-20 use Balt (Wkva, EPI_CKV).
// ---------------------------------------------------------------------------
#define ROWB   80
#define TILEB  (128 * ROWB)     // 10240
#define STAGEB (2 * TILEB)      // 20480 (A, B)
#define GEMM_SMEM (2 * STAGEB)  // 40960

template <int EPI>
__global__ __launch_bounds__(256)
void hmma_gemm(const __half* __restrict__ Am,
               const __half* __restrict__ Bm, const __half* __restrict__ Balt,
               float* __restrict__ Cf,
               __half* __restrict__ O1, __half* __restrict__ O2,
               __half* __restrict__ O3,
               int K, int lda, int ldb, int ldc)
{
    extern __shared__ char smc[];
    const uint32_t sb = smem_u32(smc);
    const int tid = threadIdx.x;
    const int lane = tid & 31, warp = tid >> 5;
    const int wm = warp >> 2, wn = warp & 3;
    const int m0 = blockIdx.y * 128;

    bool isQ = true;
    const __half* Bu = Bm;
    int n0 = blockIdx.x * 128;
    if (EPI == EPI_QCKV && blockIdx.x >= 16) {
        isQ = false;
        Bu = Balt;
        n0 = (blockIdx.x - 16) * 128;
    }

    const int r_ld = tid >> 2;
    const int cc = tid & 3;
    const __half* pA0 = Am + (size_t)(m0 + r_ld) * lda + cc * 8;
    const __half* pA1 = Am + (size_t)(m0 + r_ld + 64) * lda + cc * 8;
    const __half* pB0 = Bu + (size_t)(n0 + r_ld) * ldb + cc * 8;
    const __half* pB1 = Bu + (size_t)(n0 + r_ld + 64) * ldb + cc * 8;
    const uint32_t d0 = r_ld * ROWB + cc * 16;
    const uint32_t d1 = (r_ld + 64) * ROWB + cc * 16;

    #define ISSUE(st, k0_) do {                                               \
        const uint32_t bb = sb + (uint32_t)(st) * STAGEB;                     \
        cp16(bb + 0 * TILEB + d0, pA0 + (k0_));                               \
        cp16(bb + 0 * TILEB + d1, pA1 + (k0_));                               \
        cp16(bb + 1 * TILEB + d0, pB0 + (k0_));                               \
        cp16(bb + 1 * TILEB + d1, pB1 + (k0_));                               \
        cp_commit();                                                          \
    } while (0)

    float c[4][4][4];
    #pragma unroll
    for (int i = 0; i < 4; i++)
        #pragma unroll
        for (int j = 0; j < 4; j++)
            #pragma unroll
            for (int l = 0; l < 4; l++) c[i][j][l] = 0.f;

    const uint32_t a_row = wm * 64 + (lane & 15);
    const uint32_t a_koff = (lane >> 4) * 16;
    const uint32_t b_row = wn * 32 + ((lane >> 4) << 3) + (lane & 7);
    const uint32_t b_koff = ((lane >> 3) & 1) * 16;

    const int niter = K >> 5;
    ISSUE(0, 0);

    for (int it = 0; it < niter; it++) {
        cp_wait0();
        __syncthreads();
        if (it + 1 < niter) ISSUE((it + 1) & 1, (it + 1) << 5);

        const uint32_t buf = sb + (uint32_t)(it & 1) * STAGEB;
        #pragma unroll
        for (int ks = 0; ks < 2; ks++) {
            const uint32_t kb = ks * 32;
            uint32_t af[4][4], bf[4][2];
            #pragma unroll
            for (int mt = 0; mt < 4; mt++) {
                const uint32_t ad = buf + (a_row + mt * 16) * ROWB + kb + a_koff;
                ldsm4(af[mt], ad);
            }
            #pragma unroll
            for (int np = 0; np < 2; np++) {
                const uint32_t bd = buf + (b_row + np * 16) * ROWB + kb + b_koff;
                uint32_t t[4];
                ldsm4(t, bd + 1 * TILEB);
                bf[np * 2][0] = t[0]; bf[np * 2][1] = t[1];
                bf[np * 2 + 1][0] = t[2]; bf[np * 2 + 1][1] = t[3];
            }
            #pragma unroll
            for (int mt = 0; mt < 4; mt++)
                #pragma unroll
                for (int nt = 0; nt < 4; nt++)
                    mma_f16(c[mt][nt], af[mt], bf[nt]);
        }
    }
    #undef ISSUE

    #pragma unroll
    for (int mt = 0; mt < 4; mt++) {
        const int row = m0 + wm * 64 + mt * 16 + (lane >> 2);
        #pragma unroll
        for (int nt = 0; nt < 4; nt++) {
            const int col = n0 + wn * 32 + nt * 8 + (lane & 3) * 2;
            if (EPI == EPI_QCKV) {
                if (isQ) {
                    epi_store<EPI_Q>(row,     col, c[mt][nt][0], c[mt][nt][1],
                                     nullptr, O1, nullptr, 0);
                    epi_store<EPI_Q>(row + 8, col, c[mt][nt][2], c[mt][nt][3],
                                     nullptr, O1, nullptr, 0);
                } else {
                    epi_store<EPI_CKV>(row,     col, c[mt][nt][0], c[mt][nt][1],
                                       nullptr, O2, O3, 0);
                    epi_store<EPI_CKV>(row + 8, col, c[mt][nt][2], c[mt][nt][3],
                                       nullptr, O2, O3, 0);
                }
            } else {
                epi_store<EPI>(row,     col, c[mt][nt][0], c[mt][nt][1],
                               Cf, O1, O2, ldc);
                epi_store<EPI>(row + 8, col, c[mt][nt][2], c[mt][nt][3],
                               Cf, O1, O2, ldc);
            }
        }
    }
}

// ---------------------------------------------------------------------------
// HMMA flash attention (causal), pure fp16 operands, fp32 accumulate.
// Q frags in registers; K/V single fp16 ring; LPT block order.
// ---------------------------------------------------------------------------
#define APITCH 272
#define KTILEB (64 * APITCH)                 // 17408 (single K/V tile)
#define ATTN_SMEM (2 * KTILEB)               // 34816 (= Q staging, reused as ring)

__global__ __launch_bounds__(256)
void attn_hmma(const __half* __restrict__ qhg,
               const __half* __restrict__ kvh, const __half* __restrict__ krh,
               __half* __restrict__ yh)
{
    extern __shared__ char sma[];
    const uint32_t sb = smem_u32(sma);
    const int tid = threadIdx.x;
    const int lane = tid & 31, warp = tid >> 5;
    const int qt = (int)gridDim.x - 1 - (int)blockIdx.x;   // big work first
    const int h = blockIdx.y, b = blockIdx.z;
    const int q0 = qt * 128;
    const int bq0 = b * T_ + q0;
    const float scale = 0.08838834764831845f;

    // ---- stage Q and pull fragments into registers ----
    #pragma unroll
    for (int i = 0; i < 8; i++) {
        const int idx = i * 256 + tid;
        const int r = idx >> 4, gc = idx & 15;
        *(float4*)(sma + r * APITCH + gc * 16) =
            *(const float4*)(qhg + (size_t)(bq0 + r) * 2048 + h * 128 + gc * 8);
    }
    __syncthreads();

    uint32_t qh[8][4];
    {
        const uint32_t a_base = sb + (warp * 16 + (lane & 15)) * APITCH + (lane >> 4) * 16;
        #pragma unroll
        for (int kt = 0; kt < 8; kt++)
            ldsm4(qh[kt], a_base + kt * 32);
    }
    __syncthreads();    // smem now free for the K-tile ring

    const int s_ld = tid >> 4;
    const int gc_ld = tid & 15;
    const int hoff = h * 64 + (gc_ld & 7) * 8;
    const int roff = (gc_ld - 8) * 8;

    #define KISSUE(st, bk0_) do {                                             \
        const uint32_t bb = sb + (uint32_t)(st) * KTILEB;                     \
        _Pragma("unroll")                                                     \
        for (int i = 0; i < 4; i++) {                                         \
            const int s = s_ld + i * 16;                                      \
            const void* src = (gc_ld < 8)                                     \
                ? (const void*)(kvh + (size_t)((bk0_) + s) * 1024 + hoff)     \
                : (const void*)(krh + (size_t)((bk0_) + s) * 64 + roff);      \
            cp16(bb + s * APITCH + gc_ld * 16, src);                          \
        }                                                                     \
        cp_commit();                                                          \
    } while (0)

    float m_i[2] = {-1e30f, -1e30f};
    float l_i[2] = {0.f, 0.f};
    float o[8][4];
    #pragma unroll
    for (int j = 0; j < 8; j++)
        #pragma unroll
        for (int e = 0; e < 4; e++) o[j][e] = 0.f;

    const int g = lane >> 2, cq = lane & 3;
    const int rbase = q0 + warp * 16 + g;

    const int nk = 2 * qt + 2;
    KISSUE(0, b * T_);

    for (int c = 0; c < nk; c++) {
        cp_wait0();
        __syncthreads();
        if (c + 1 < nk) KISSUE((c + 1) & 1, b * T_ + (c + 1) * 64);

        const uint32_t kbuf = sb + (uint32_t)(c & 1) * KTILEB;

        // ---- S = Q K^T ----
        float cS[8][4];
        #pragma unroll
        for (int j = 0; j < 8; j++)
            #pragma unroll
            for (int e = 0; e < 4; e++) cS[j][e] = 0.f;

        const uint32_t b_base = kbuf + (((lane >> 4) << 3) + (lane & 7)) * APITCH
                              + ((lane >> 3) & 1) * 16;
        #pragma unroll
        for (int kt = 0; kt < 8; kt++) {
            #pragma unroll
            for (int np = 0; np < 4; np++) {
                uint32_t th[4];
                ldsm4(th, b_base + np * 16 * APITCH + kt * 32);
                const int j0 = 2 * np;
                mma_f16s(cS[j0],     qh[kt], th[0], th[1]);
                mma_f16s(cS[j0 + 1], qh[kt], th[2], th[3]);
            }
        }

        // ---- scale + causal mask ----
        const int cbase = c * 64 + cq * 2;
        #pragma unroll
        for (int j = 0; j < 8; j++) {
            const int col = cbase + j * 8;
            cS[j][0] = (col     <= rbase)     ? cS[j][0] * scale : -3e30f;
            cS[j][1] = (col + 1 <= rbase)     ? cS[j][1] * scale : -3e30f;
            cS[j][2] = (col     <= rbase + 8) ? cS[j][2] * scale : -3e30f;
            cS[j][3] = (col + 1 <= rbase + 8) ? cS[j][3] * scale : -3e30f;
        }

        // ---- online softmax ----
        float mx0 = -3e30f, mx1 = -3e30f;
        #pragma unroll
        for (int j = 0; j < 8; j++) {
            mx0 = fmaxf(mx0, fmaxf(cS[j][0], cS[j][1]));
            mx1 = fmaxf(mx1, fmaxf(cS[j][2], cS[j][3]));
        }
        mx0 = fmaxf(mx0, __shfl_xor_sync(0xffffffffu, mx0, 1));
        mx0 = fmaxf(mx0, __shfl_xor_sync(0xffffffffu, mx0, 2));
        mx1 = fmaxf(mx1, __shfl_xor_sync(0xffffffffu, mx1, 1));
        mx1 = fmaxf(mx1, __shfl_xor_sync(0xffffffffu, mx1, 2));
        const float nm0 = fmaxf(m_i[0], mx0);
        const float nm1 = fmaxf(m_i[1], mx1);
        const float f0 = __expf(m_i[0] - nm0);
        const float f1 = __expf(m_i[1] - nm1);
        float s0 = 0.f, s1 = 0.f;
        #pragma unroll
        for (int j = 0; j < 8; j++) {
            cS[j][0] = __expf(cS[j][0] - nm0);
            cS[j][1] = __expf(cS[j][1] - nm0);
            cS[j][2] = __expf(cS[j][2] - nm1);
            cS[j][3] = __expf(cS[j][3] - nm1);
            s0 += cS[j][0] + cS[j][1];
            s1 += cS[j][2] + cS[j][3];
        }
        s0 += __shfl_xor_sync(0xffffffffu, s0, 1);
        s0 += __shfl_xor_sync(0xffffffffu, s0, 2);
        s1 += __shfl_xor_sync(0xffffffffu, s1, 1);
        s1 += __shfl_xor_sync(0xffffffffu, s1, 2);
        l_i[0] = l_i[0] * f0 + s0;  m_i[0] = nm0;
        l_i[1] = l_i[1] * f1 + s1;  m_i[1] = nm1;
        #pragma unroll
        for (int j = 0; j < 8; j++) {
            o[j][0] *= f0; o[j][1] *= f0;
            o[j][2] *= f1; o[j][3] *= f1;
        }

        // ---- O += P @ V ----
        const uint32_t v_row = ((lane & 7) + 8 * ((lane >> 3) & 1)) * APITCH
                             + (lane >> 4) * 16;
        #pragma unroll
        for (int ks = 0; ks < 4; ks++) {
            uint32_t ah[4];
            ah[0] = packh(cS[2 * ks][0],     cS[2 * ks][1]);
            ah[1] = packh(cS[2 * ks][2],     cS[2 * ks][3]);
            ah[2] = packh(cS[2 * ks + 1][0], cS[2 * ks + 1][1]);
            ah[3] = packh(cS[2 * ks + 1][2], cS[2 * ks + 1][3]);
            #pragma unroll
            for (int np = 0; np < 4; np++) {
                uint32_t th[4];
                ldsm4t(th, kbuf + v_row + ks * 16 * APITCH + np * 32);
                const int jd = 2 * np;
                mma_f16s(o[jd],     ah, th[0], th[1]);
                mma_f16s(o[jd + 1], ah, th[2], th[3]);
            }
        }
    }
    #undef KISSUE

    const float inv0 = 1.f / l_i[0];
    const float inv1 = 1.f / l_i[1];
    const size_t row0 = (size_t)(bq0 + warp * 16 + g);
    const size_t row1 = row0 + 8;
    #pragma unroll
    for (int j = 0; j < 8; j++) {
        const int col = h * 64 + j * 8 + cq * 2;
        *(uint32_t*)&yh[row0 * 1024 + col] = packh(o[j][0] * inv0, o[j][1] * inv0);
        *(uint32_t*)&yh[row1 * 1024 + col] = packh(o[j][2] * inv1, o[j][3] * inv1);
    }
}

// ---------------------------------------------------------------------------
// Launch
// ---------------------------------------------------------------------------
extern "C" void kernel_launch(void* const* d_in, const int* in_sizes, int n_in,
                              void* d_out, int out_size)
{
    const float* x    = (const float*)d_in[0];
    const float* Wq   = (const float*)d_in[1];
    const float* Wkva = (const float*)d_in[2];
    const float* Wkvb = (const float*)d_in[3];
    const float* Wo   = (const float*)d_in[4];
    float* out = (float*)d_out;

    __half *xh, *qh, *ckvh, *yh, *kvh, *krh, *wq, *wa, *wb, *wo;
    cudaGetSymbolAddress((void**)&xh, g_xh);
    cudaGetSymbolAddress((void**)&qh, g_qh);
    cudaGetSymbolAddress((void**)&ckvh, g_ckvh);
    cudaGetSymbolAddress((void**)&yh, g_yh);
    cudaGetSymbolAddress((void**)&kvh, g_kvh);
    cudaGetSymbolAddress((void**)&krh, g_krh);
    cudaGetSymbolAddress((void**)&wq, g_wqt);
    cudaGetSymbolAddress((void**)&wa, g_wkvat);
    cudaGetSymbolAddress((void**)&wb, g_wkvbt);
    cudaGetSymbolAddress((void**)&wo, g_wot);

    cudaFuncSetAttribute(hmma_gemm<EPI_F32>,
                         cudaFuncAttributeMaxDynamicSharedMemorySize, GEMM_SMEM);
    cudaFuncSetAttribute(hmma_gemm<EPI_KV>,
                         cudaFuncAttributeMaxDynamicSharedMemorySize, GEMM_SMEM);
    cudaFuncSetAttribute(hmma_gemm<EPI_QCKV>,
                         cudaFuncAttributeMaxDynamicSharedMemorySize, GEMM_SMEM);
    cudaFuncSetAttribute(attn_hmma,
                         cudaFuncAttributeMaxDynamicSharedMemorySize, ATTN_SMEM);

    freq_init_kernel<<<1, 32>>>();

    const dim3 tb(32, 8);
    splitT_kernel<false><<<dim3(64, 64), tb>>>(Wq,   2048, 2048, wq, 2048);
    splitT_kernel<false><<<dim3(64, 20), tb>>>(Wkva,  576,  576, wa, 2048);
    splitT_kernel<false><<<dim3(16, 32), tb>>>(Wkvb, 1024, 1024, wb,  512);
    splitT_kernel<true ><<<dim3(32, 64), tb>>>(Wo,   2048, 2048, wo, 1024);
    convert_kernel<<<8192, 256>>>(x, xh, 4096 * 512);

    // merged: q = rope(x @ Wq) AND ckv = x @ Wkva (+ roped krh)
    hmma_gemm<EPI_QCKV><<<dim3(21, 32), 256, GEMM_SMEM>>>(
        xh, wq, wa, nullptr, qh, ckvh, krh,
        2048, 2048, 2048, 0);
    // kv = latent @ Wkvb -> kvh
    hmma_gemm<EPI_KV><<<dim3(8, 32), 256, GEMM_SMEM>>>(
        ckvh, wb, nullptr, nullptr, kvh, nullptr, nullptr,
        512, 512, 512, 1024);
    // attention -> yh
    attn_hmma<<<dim3(16, 16, 2), 256, ATTN_SMEM>>>(qh, kvh, krh, yh);
    // out = y @ gather(Wo)
    hmma_gemm<EPI_F32><<<dim3(16, 32), 256, GEMM_SMEM>>>(
        yh, wo, nullptr, out, nullptr, nullptr, nullptr,
        1024, 1024, 1024, 2048);
}

// round 16
// speedup vs baseline: 7.6266x; 1.0246x over previous
#include <cuda_runtime.h>
#include <cuda_fp16.h>
#include <math.h>
#include <stdint.h>

// Problem constants
#define B_    2
#define T_    2048
#define C_    2048
#define H_    16
#define HD_   128
#define LORA_ 512
#define RD_   64
#define ND_   64
#define BT_   (B_ * T_)   // 4096

// ---------------------------------------------------------------------------
// Scratch (static __device__ globals — allocation-free per harness rules)
// ---------------------------------------------------------------------------
__device__ float g_freq[32];

__device__ __align__(16) __half g_xh[(size_t)BT_ * 2048];
__device__ __align__(16) __half g_qh[(size_t)BT_ * 2048];
__device__ __align__(16) __half g_ckvh[(size_t)BT_ * 512];
__device__ __align__(16) __half g_yh[(size_t)BT_ * 1024];
__device__ __align__(16) __half g_kvh[(size_t)BT_ * 1024];
__device__ __align__(16) __half g_krh[(size_t)BT_ * 64];
__device__ __align__(16) __half g_wqt[(size_t)2048 * 2048];
__device__ __align__(16) __half g_wkvat[(size_t)640 * 2048];
__device__ __align__(16) __half g_wkvbt[(size_t)1024 * 512];
__device__ __align__(16) __half g_wot[(size_t)2048 * 1024];

// ---------------------------------------------------------------------------
// Merged prep kernel: all weight transposes + x convert + freq table.
// block dims (32,8). Block ranges:
//   [0,4096)      Wq   transpose (64 x 64 tiles)
//   [4096,5376)   Wkva transpose (64 x 20)
//   [5376,5888)   Wkvb transpose (16 x 32)
//   [5888,7936)   Wo   transpose+gather (32 x 64)
//   [7936,16128)  x fp32->fp16 convert (8192 blocks)
// ---------------------------------------------------------------------------
__device__ __forceinline__ void splitT_body(
    const float* __restrict__ W, int ldw, int nIn,
    __half* __restrict__ out, int kDim, bool gather, int bx, int by,
    float (*tile)[33])
{
    const int tx = threadIdx.x, ty = threadIdx.y;
    const int k0 = bx * 32, n0 = by * 32;
    #pragma unroll
    for (int i = ty; i < 32; i += 8) {
        const int k = k0 + i;
        const int row = gather ? (((k >> 6) << 7) + (k & 63)) : k;
        const int n = n0 + tx;
        tile[i][tx] = (n < nIn) ? W[(size_t)row * ldw + n] : 0.f;
    }
    __syncthreads();
    #pragma unroll
    for (int i = ty; i < 32; i += 8) {
        const int n = n0 + i, k = k0 + tx;
        out[(size_t)n * kDim + k] = __float2half_rn(tile[tx][i]);
    }
}

__global__ __launch_bounds__(256)
void prep_kernel(const float* __restrict__ x,
                 const float* __restrict__ Wq, const float* __restrict__ Wkva,
                 const float* __restrict__ Wkvb, const float* __restrict__ Wo)
{
    __shared__ float tile[32][33];
    const int bid = blockIdx.x;
    const int tid = threadIdx.y * 32 + threadIdx.x;

    if (bid == 0 && threadIdx.y == 0 && threadIdx.x < 32)
        g_freq[threadIdx.x] = (float)pow(100000.0, -(double)threadIdx.x / 32.0);

    if (bid < 4096) {
        splitT_body(Wq, 2048, 2048, g_wqt, 2048, false,
                    bid & 63, bid >> 6, tile);
    } else if (bid < 5376) {
        const int idx = bid - 4096;
        splitT_body(Wkva, 576, 576, g_wkvat, 2048, false,
                    idx & 63, idx >> 6, tile);
    } else if (bid < 5888) {
        const int idx = bid - 5376;
        splitT_body(Wkvb, 1024, 1024, g_wkvbt, 512, false,
                    idx & 15, idx >> 4, tile);
    } else if (bid < 7936) {
        const int idx = bid - 5888;
        splitT_body(Wo, 2048, 2048, g_wot, 1024, true,
                    idx & 31, idx >> 5, tile);
    } else {
        const int idx = (bid - 7936) * 256 + tid;     // float4 index
        const float4 v = *(const float4*)&x[(size_t)idx * 4];
        ushort4 hv;
        hv.x = __half_as_ushort(__float2half_rn(v.x));
        hv.y = __half_as_ushort(__float2half_rn(v.y));
        hv.z = __half_as_ushort(__float2half_rn(v.z));
        hv.w = __half_as_ushort(__float2half_rn(v.w));
        *(ushort4*)&g_xh[(size_t)idx * 4] = hv;
    }
}

// ---------------------------------------------------------------------------
// Shared HMMA helpers (fp16)
// ---------------------------------------------------------------------------
__device__ __forceinline__ uint32_t smem_u32(const void* p) {
    uint32_t a;
    asm("{ .reg .u64 t; cvta.to.shared.u64 t, %1; cvt.u32.u64 %0, t; }"
        : "=r"(a) : "l"(p));
    return a;
}
__device__ __forceinline__ void cp16(uint32_t dst, const void* src) {
    asm volatile("cp.async.cg.shared.global [%0], [%1], 16;"
                 :: "r"(dst), "l"(src) : "memory");
}
__device__ __forceinline__ void cp_commit() {
    asm volatile("cp.async.commit_group;" ::: "memory");
}
__device__ __forceinline__ void cp_wait0() {
    asm volatile("cp.async.wait_group 0;" ::: "memory");
}
__device__ __forceinline__ void cp_wait1() {
    asm volatile("cp.async.wait_group 1;" ::: "memory");
}
__device__ __forceinline__ void ldsm4(uint32_t r[4], uint32_t addr) {
    asm volatile("ldmatrix.sync.aligned.m8n8.x4.shared.b16 {%0,%1,%2,%3}, [%4];"
                 : "=r"(r[0]), "=r"(r[1]), "=r"(r[2]), "=r"(r[3]) : "r"(addr));
}
__device__ __forceinline__ void ldsm4t(uint32_t r[4], uint32_t addr) {
    asm volatile("ldmatrix.sync.aligned.m8n8.x4.trans.shared.b16 {%0,%1,%2,%3}, [%4];"
                 : "=r"(r[0]), "=r"(r[1]), "=r"(r[2]), "=r"(r[3]) : "r"(addr));
}
__device__ __forceinline__ void mma_f16(float c[4], const uint32_t a[4],
                                        const uint32_t b[2]) {
    asm volatile(
        "mma.sync.aligned.m16n8k16.row.col.f32.f16.f16.f32 "
        "{%0,%1,%2,%3}, {%4,%5,%6,%7}, {%8,%9}, {%0,%1,%2,%3};"
        : "+f"(c[0]), "+f"(c[1]), "+f"(c[2]), "+f"(c[3])
        : "r"(a[0]), "r"(a[1]), "r"(a[2]), "r"(a[3]), "r"(b[0]), "r"(b[1]));
}
__device__ __forceinline__ void mma_f16s(float c[4], const uint32_t a[4],
                                         uint32_t b0, uint32_t b1) {
    asm volatile(
        "mma.sync.aligned.m16n8k16.row.col.f32.f16.f16.f32 "
        "{%0,%1,%2,%3}, {%4,%5,%6,%7}, {%8,%9}, {%0,%1,%2,%3};"
        : "+f"(c[0]), "+f"(c[1]), "+f"(c[2]), "+f"(c[3])
        : "r"(a[0]), "r"(a[1]), "r"(a[2]), "r"(a[3]), "r"(b0), "r"(b1));
}
__device__ __forceinline__ uint32_t packh(float c0, float c1) {
    return ((uint32_t)__half_as_ushort(__float2half_rn(c1)) << 16)
         | __half_as_ushort(__float2half_rn(c0));
}

// ---------------------------------------------------------------------------
// Epilogue modes
// ---------------------------------------------------------------------------
#define EPI_F32   0
#define EPI_KV    1
#define EPI_Q     2
#define EPI_CKV   3
#define EPI_QCKV  4

template <int EPI>
__device__ __forceinline__ void epi_store(int row, int col, float v0, float v1,
    float* __restrict__ Cf,
    __half* __restrict__ O1, __half* __restrict__ O2, int ldc)
{
    if (EPI == EPI_F32) {
        *(float2*)&Cf[(size_t)row * ldc + col] = make_float2(v0, v1);
    } else if (EPI == EPI_KV) {
        *(uint32_t*)&O1[(size_t)row * ldc + col] = packh(v0, v1);
    } else if (EPI == EPI_Q) {
        const int d = col & 127;
        if (d >= 64) {
            const float freq = g_freq[(d - 64) >> 1];
            float s, c;
            sincosf((float)(row & (T_ - 1)) * freq, &s, &c);
            const float t0 = v0 * c - v1 * s;
            const float t1 = v0 * s + v1 * c;
            v0 = t0; v1 = t1;
        }
        *(uint32_t*)&O1[(size_t)row * 2048 + col] = packh(v0, v1);
    } else if (EPI == EPI_CKV) {
        if (col < 512) {
            *(uint32_t*)&O1[(size_t)row * 512 + col] = packh(v0, v1);
        } else if (col < 576) {
            const float freq = g_freq[(col - 512) >> 1];
            float s, c;
            sincosf((float)(row & (T_ - 1)) * freq, &s, &c);
            *(uint32_t*)&O2[(size_t)row * 64 + (col - 512)] =
                packh(v0 * c - v1 * s, v0 * s + v1 * c);
        }
    }
}

// ---------------------------------------------------------------------------
// HMMA fp16 GEMM, 3-stage cp.async pipeline (wait_group 1 => 2 loads in flight)
//   C[M,N] = A[M,K] @ B[N,K]^T
// CTA 128x128, 8 warps of 64x32, BK=32.
// ---------------------------------------------------------------------------
#define ROWB   80
#define TILEB  (128 * ROWB)     // 10240
#define STAGEB (2 * TILEB)      // 20480 (A, B)
#define NSTAGE 3
#define GEMM_SMEM (NSTAGE * STAGEB)  // 61440

template <int EPI>
__global__ __launch_bounds__(256)
void hmma_gemm(const __half* __restrict__ Am,
               const __half* __restrict__ Bm, const __half* __restrict__ Balt,
               float* __restrict__ Cf,
               __half* __restrict__ O1, __half* __restrict__ O2,
               __half* __restrict__ O3,
               int K, int lda, int ldb, int ldc)
{
    extern __shared__ char smc[];
    const uint32_t sb = smem_u32(smc);
    const int tid = threadIdx.x;
    const int lane = tid & 31, warp = tid >> 5;
    const int wm = warp >> 2, wn = warp & 3;
    const int m0 = blockIdx.y * 128;

    bool isQ = true;
    const __half* Bu = Bm;
    int n0 = blockIdx.x * 128;
    if (EPI == EPI_QCKV && blockIdx.x >= 16) {
        isQ = false;
        Bu = Balt;
        n0 = (blockIdx.x - 16) * 128;
    }

    const int r_ld = tid >> 2;
    const int cc = tid & 3;
    const __half* pA0 = Am + (size_t)(m0 + r_ld) * lda + cc * 8;
    const __half* pA1 = Am + (size_t)(m0 + r_ld + 64) * lda + cc * 8;
    const __half* pB0 = Bu + (size_t)(n0 + r_ld) * ldb + cc * 8;
    const __half* pB1 = Bu + (size_t)(n0 + r_ld + 64) * ldb + cc * 8;
    const uint32_t d0 = r_ld * ROWB + cc * 16;
    const uint32_t d1 = (r_ld + 64) * ROWB + cc * 16;

    #define ISSUE(st, k0_) do {                                               \
        const uint32_t bb = sb + (uint32_t)(st) * STAGEB;                     \
        cp16(bb + 0 * TILEB + d0, pA0 + (k0_));                               \
        cp16(bb + 0 * TILEB + d1, pA1 + (k0_));                               \
        cp16(bb + 1 * TILEB + d0, pB0 + (k0_));                               \
        cp16(bb + 1 * TILEB + d1, pB1 + (k0_));                               \
        cp_commit();                                                          \
    } while (0)

    float c[4][4][4];
    #pragma unroll
    for (int i = 0; i < 4; i++)
        #pragma unroll
        for (int j = 0; j < 4; j++)
            #pragma unroll
            for (int l = 0; l < 4; l++) c[i][j][l] = 0.f;

    const uint32_t a_row = wm * 64 + (lane & 15);
    const uint32_t a_koff = (lane >> 4) * 16;
    const uint32_t b_row = wn * 32 + ((lane >> 4) << 3) + (lane & 7);
    const uint32_t b_koff = ((lane >> 3) & 1) * 16;

    const int niter = K >> 5;     // >= 16 for all our shapes
    ISSUE(0, 0);
    ISSUE(1, 32);

    int st0 = 0, st2 = 2;         // compute stage / next fill stage
    for (int it = 0; it < niter; it++) {
        cp_wait1();               // stage st0's load (group it) complete
        __syncthreads();          // everyone done computing stage st2 (iter it-1)
        if (it + 2 < niter) ISSUE(st2, (it + 2) << 5);
        else cp_commit();         // keep group accounting aligned

        const uint32_t buf = sb + (uint32_t)st0 * STAGEB;
        #pragma unroll
        for (int ks = 0; ks < 2; ks++) {
            const uint32_t kb = ks * 32;
            uint32_t af[4][4], bf[4][2];
            #pragma unroll
            for (int mt = 0; mt < 4; mt++) {
                const uint32_t ad = buf + (a_row + mt * 16) * ROWB + kb + a_koff;
                ldsm4(af[mt], ad);
            }
            #pragma unroll
            for (int np = 0; np < 2; np++) {
                const uint32_t bd = buf + (b_row + np * 16) * ROWB + kb + b_koff;
                uint32_t t[4];
                ldsm4(t, bd + 1 * TILEB);
                bf[np * 2][0] = t[0]; bf[np * 2][1] = t[1];
                bf[np * 2 + 1][0] = t[2]; bf[np * 2 + 1][1] = t[3];
            }
            #pragma unroll
            for (int mt = 0; mt < 4; mt++)
                #pragma unroll
                for (int nt = 0; nt < 4; nt++)
                    mma_f16(c[mt][nt], af[mt], bf[nt]);
        }
        st0 = (st0 == NSTAGE - 1) ? 0 : st0 + 1;
        st2 = (st2 == NSTAGE - 1) ? 0 : st2 + 1;
    }
    #undef ISSUE

    #pragma unroll
    for (int mt = 0; mt < 4; mt++) {
        const int row = m0 + wm * 64 + mt * 16 + (lane >> 2);
        #pragma unroll
        for (int nt = 0; nt < 4; nt++) {
            const int col = n0 + wn * 32 + nt * 8 + (lane & 3) * 2;
            if (EPI == EPI_QCKV) {
                if (isQ) {
                    epi_store<EPI_Q>(row,     col, c[mt][nt][0], c[mt][nt][1],
                                     nullptr, O1, nullptr, 0);
                    epi_store<EPI_Q>(row + 8, col, c[mt][nt][2], c[mt][nt][3],
                                     nullptr, O1, nullptr, 0);
                } else {
                    epi_store<EPI_CKV>(row,     col, c[mt][nt][0], c[mt][nt][1],
                                       nullptr, O2, O3, 0);
                    epi_store<EPI_CKV>(row + 8, col, c[mt][nt][2], c[mt][nt][3],
                                       nullptr, O2, O3, 0);
                }
            } else {
                epi_store<EPI>(row,     col, c[mt][nt][0], c[mt][nt][1],
                               Cf, O1, O2, ldc);
                epi_store<EPI>(row + 8, col, c[mt][nt][2], c[mt][nt][3],
                               Cf, O1, O2, ldc);
            }
        }
    }
}

// ---------------------------------------------------------------------------
// HMMA flash attention (causal), pure fp16 operands, fp32 accumulate.
// Q frags in registers; K/V fp16 ring (2-stage, loads already latency-hidden);
// LPT block order.
// ---------------------------------------------------------------------------
#define APITCH 272
#define KTILEB (64 * APITCH)                 // 17408
#define ATTN_SMEM (2 * KTILEB)               // 34816

__global__ __launch_bounds__(256)
void attn_hmma(const __half* __restrict__ qhg,
               const __half* __restrict__ kvh, const __half* __restrict__ krh,
               __half* __restrict__ yh)
{
    extern __shared__ char sma[];
    const uint32_t sb = smem_u32(sma);
    const int tid = threadIdx.x;
    const int lane = tid & 31, warp = tid >> 5;
    const int qt = (int)gridDim.x - 1 - (int)blockIdx.x;   // big work first
    const int h = blockIdx.y, b = blockIdx.z;
    const int q0 = qt * 128;
    const int bq0 = b * T_ + q0;
    const float scale = 0.08838834764831845f;

    // ---- stage Q and pull fragments into registers ----
    #pragma unroll
    for (int i = 0; i < 8; i++) {
        const int idx = i * 256 + tid;
        const int r = idx >> 4, gc = idx & 15;
        *(float4*)(sma + r * APITCH + gc * 16) =
            *(const float4*)(qhg + (size_t)(bq0 + r) * 2048 + h * 128 + gc * 8);
    }
    __syncthreads();

    uint32_t qh[8][4];
    {
        const uint32_t a_base = sb + (warp * 16 + (lane & 15)) * APITCH + (lane >> 4) * 16;
        #pragma unroll
        for (int kt = 0; kt < 8; kt++)
            ldsm4(qh[kt], a_base + kt * 32);
    }
    __syncthreads();    // smem now free for the K-tile ring

    const int s_ld = tid >> 4;
    const int gc_ld = tid & 15;
    const int hoff = h * 64 + (gc_ld & 7) * 8;
    const int roff = (gc_ld - 8) * 8;

    #define KISSUE(st, bk0_) do {                                             \
        const uint32_t bb = sb + (uint32_t)(st) * KTILEB;                     \
        _Pragma("unroll")                                                     \
        for (int i = 0; i < 4; i++) {                                         \
            const int s = s_ld + i * 16;                                      \
            const void* src = (gc_ld < 8)                                     \
                ? (const void*)(kvh + (size_t)((bk0_) + s) * 1024 + hoff)     \
                : (const void*)(krh + (size_t)((bk0_) + s) * 64 + roff);      \
            cp16(bb + s * APITCH + gc_ld * 16, src);                          \
        }                                                                     \
        cp_commit();                                                          \
    } while (0)

    float m_i[2] = {-1e30f, -1e30f};
    float l_i[2] = {0.f, 0.f};
    float o[8][4];
    #pragma unroll
    for (int j = 0; j < 8; j++)
        #pragma unroll
        for (int e = 0; e < 4; e++) o[j][e] = 0.f;

    const int g = lane >> 2, cq = lane & 3;
    const int rbase = q0 + warp * 16 + g;

    const int nk = 2 * qt + 2;
    KISSUE(0, b * T_);

    for (int c = 0; c < nk; c++) {
        cp_wait0();
        __syncthreads();
        if (c + 1 < nk) KISSUE((c + 1) & 1, b * T_ + (c + 1) * 64);

        const uint32_t kbuf = sb + (uint32_t)(c & 1) * KTILEB;

        // ---- S = Q K^T ----
        float cS[8][4];
        #pragma unroll
        for (int j = 0; j < 8; j++)
            #pragma unroll
            for (int e = 0; e < 4; e++) cS[j][e] = 0.f;

        const uint32_t b_base = kbuf + (((lane >> 4) << 3) + (lane & 7)) * APITCH
                              + ((lane >> 3) & 1) * 16;
        #pragma unroll
        for (int kt = 0; kt < 8; kt++) {
            #pragma unroll
            for (int np = 0; np < 4; np++) {
                uint32_t th[4];
                ldsm4(th, b_base + np * 16 * APITCH + kt * 32);
                const int j0 = 2 * np;
                mma_f16s(cS[j0],     qh[kt], th[0], th[1]);
                mma_f16s(cS[j0 + 1], qh[kt], th[2], th[3]);
            }
        }

        // ---- scale + causal mask ----
        const int cbase = c * 64 + cq * 2;
        #pragma unroll
        for (int j = 0; j < 8; j++) {
            const int col = cbase + j * 8;
            cS[j][0] = (col     <= rbase)     ? cS[j][0] * scale : -3e30f;
            cS[j][1] = (col + 1 <= rbase)     ? cS[j][1] * scale : -3e30f;
            cS[j][2] = (col     <= rbase + 8) ? cS[j][2] * scale : -3e30f;
            cS[j][3] = (col + 1 <= rbase + 8) ? cS[j][3] * scale : -3e30f;
        }

        // ---- online softmax ----
        float mx0 = -3e30f, mx1 = -3e30f;
        #pragma unroll
        for (int j = 0; j < 8; j++) {
            mx0 = fmaxf(mx0, fmaxf(cS[j][0], cS[j][1]));
            mx1 = fmaxf(mx1, fmaxf(cS[j][2], cS[j][3]));
        }
        mx0 = fmaxf(mx0, __shfl_xor_sync(0xffffffffu, mx0, 1));
        mx0 = fmaxf(mx0, __shfl_xor_sync(0xffffffffu, mx0, 2));
        mx1 = fmaxf(mx1, __shfl_xor_sync(0xffffffffu, mx1, 1));
        mx1 = fmaxf(mx1, __shfl_xor_sync(0xffffffffu, mx1, 2));
        const float nm0 = fmaxf(m_i[0], mx0);
        const float nm1 = fmaxf(m_i[1], mx1);
        const float f0 = __expf(m_i[0] - nm0);
        const float f1 = __expf(m_i[1] - nm1);
        float s0 = 0.f, s1 = 0.f;
        #pragma unroll
        for (int j = 0; j < 8; j++) {
            cS[j][0] = __expf(cS[j][0] - nm0);
            cS[j][1] = __expf(cS[j][1] - nm0);
            cS[j][2] = __expf(cS[j][2] - nm1);
            cS[j][3] = __expf(cS[j][3] - nm1);
            s0 += cS[j][0] + cS[j][1];
            s1 += cS[j][2] + cS[j][3];
        }
        s0 += __shfl_xor_sync(0xffffffffu, s0, 1);
        s0 += __shfl_xor_sync(0xffffffffu, s0, 2);
        s1 += __shfl_xor_sync(0xffffffffu, s1, 1);
        s1 += __shfl_xor_sync(0xffffffffu, s1, 2);
        l_i[0] = l_i[0] * f0 + s0;  m_i[0] = nm0;
        l_i[1] = l_i[1] * f1 + s1;  m_i[1] = nm1;
        #pragma unroll
        for (int j = 0; j < 8; j++) {
            o[j][0] *= f0; o[j][1] *= f0;
            o[j][2] *= f1; o[j][3] *= f1;
        }

        // ---- O += P @ V ----
        const uint32_t v_row = ((lane & 7) + 8 * ((lane >> 3) & 1)) * APITCH
                             + (lane >> 4) * 16;
        #pragma unroll
        for (int ks = 0; ks < 4; ks++) {
            uint32_t ah[4];
            ah[0] = packh(cS[2 * ks][0],     cS[2 * ks][1]);
            ah[1] = packh(cS[2 * ks][2],     cS[2 * ks][3]);
            ah[2] = packh(cS[2 * ks + 1][0], cS[2 * ks + 1][1]);
            ah[3] = packh(cS[2 * ks + 1][2], cS[2 * ks + 1][3]);
            #pragma unroll
            for (int np = 0; np < 4; np++) {
                uint32_t th[4];
                ldsm4t(th, kbuf + v_row + ks * 16 * APITCH + np * 32);
                const int jd = 2 * np;
                mma_f16s(o[jd],     ah, th[0], th[1]);
                mma_f16s(o[jd + 1], ah, th[2], th[3]);
            }
        }
    }
    #undef KISSUE

    const float inv0 = 1.f / l_i[0];
    const float inv1 = 1.f / l_i[1];
    const size_t row0 = (size_t)(bq0 + warp * 16 + g);
    const size_t row1 = row0 + 8;
    #pragma unroll
    for (int j = 0; j < 8; j++) {
        const int col = h * 64 + j * 8 + cq * 2;
        *(uint32_t*)&yh[row0 * 1024 + col] = packh(o[j][0] * inv0, o[j][1] * inv0);
        *(uint32_t*)&yh[row1 * 1024 + col] = packh(o[j][2] * inv1, o[j][3] * inv1);
    }
}

// ---------------------------------------------------------------------------
// Launch
// ---------------------------------------------------------------------------
extern "C" void kernel_launch(void* const* d_in, const int* in_sizes, int n_in,
                              void* d_out, int out_size)
{
    const float* x    = (const float*)d_in[0];
    const float* Wq   = (const float*)d_in[1];
    const float* Wkva = (const float*)d_in[2];
    const float* Wkvb = (const float*)d_in[3];
    const float* Wo   = (const float*)d_in[4];
    float* out = (float*)d_out;

    __half *xh, *qh, *ckvh, *yh, *kvh, *krh, *wq, *wa, *wb, *wo;
    cudaGetSymbolAddress((void**)&xh, g_xh);
    cudaGetSymbolAddress((void**)&qh, g_qh);
    cudaGetSymbolAddress((void**)&ckvh, g_ckvh);
    cudaGetSymbolAddress((void**)&yh, g_yh);
    cudaGetSymbolAddress((void**)&kvh, g_kvh);
    cudaGetSymbolAddress((void**)&krh, g_krh);
    cudaGetSymbolAddress((void**)&wq, g_wqt);
    cudaGetSymbolAddress((void**)&wa, g_wkvat);
    cudaGetSymbolAddress((void**)&wb, g_wkvbt);
    cudaGetSymbolAddress((void**)&wo, g_wot);

    cudaFuncSetAttribute(hmma_gemm<EPI_F32>,
                         cudaFuncAttributeMaxDynamicSharedMemorySize, GEMM_SMEM);
    cudaFuncSetAttribute(hmma_gemm<EPI_KV>,
                         cudaFuncAttributeMaxDynamicSharedMemorySize, GEMM_SMEM);
    cudaFuncSetAttribute(hmma_gemm<EPI_QCKV>,
                         cudaFuncAttributeMaxDynamicSharedMemorySize, GEMM_SMEM);
    cudaFuncSetAttribute(attn_hmma,
                         cudaFuncAttributeMaxDynamicSharedMemorySize, ATTN_SMEM);

    // all conversions + freq table, one launch
    prep_kernel<<<16128, dim3(32, 8)>>>(x, Wq, Wkva, Wkvb, Wo);

    // merged: q = rope(x @ Wq) AND ckv = x @ Wkva (+ roped krh)
    hmma_gemm<EPI_QCKV><<<dim3(21, 32), 256, GEMM_SMEM>>>(
        xh, wq, wa, nullptr, qh, ckvh, krh,
        2048, 2048, 2048, 0);
    // kv = latent @ Wkvb -> kvh
    hmma_gemm<EPI_KV><<<dim3(8, 32), 256, GEMM_SMEM>>>(
        ckvh, wb, nullptr, nullptr, kvh, nullptr, nullptr,
        512, 512, 512, 1024);
    // attention -> yh
    attn_hmma<<<dim3(16, 16, 2), 256, ATTN_SMEM>>>(qh, kvh, krh, yh);
    // out = y @ gather(Wo)
    hmma_gemm<EPI_F32><<<dim3(16, 32), 256, GEMM_SMEM>>>(
        yh, wo, nullptr, out, nullptr, nullptr, nullptr,
        1024, 1024, 1024, 2048);
}